// round 1
// baseline (speedup 1.0000x reference)
#include <cuda_runtime.h>
#include <cstdint>

#define NX   8192
#define NN   8192
#define DIN  512
#define DH   32
#define DOUT 256

// ---------------- scratch (static __device__: allocation-free) ----------------
__device__ float g_hid [NX * DH];           // reused for x and neigh hidden
__device__ float g_xatt[NX * DH];
__device__ float g_natt[NN * DH];
__device__ float g_value[NN * DOUT];        // 8 MB
__device__ float g_E[(size_t)NX * NN];      // 256 MB: masked exp'd scores
__device__ float g_rowsum[NX];

// ---------------- f32x2 packed helpers (sm_10x) ----------------
__device__ __forceinline__ unsigned long long pack2(float a, float b) {
    unsigned long long r;
    asm("mov.b64 %0, {%1, %2};" : "=l"(r) : "f"(a), "f"(b));
    return r;
}
__device__ __forceinline__ void fma2(unsigned long long &d, unsigned long long a,
                                     unsigned long long b) {
    asm("fma.rn.f32x2 %0, %1, %2, %0;" : "+l"(d) : "l"(a), "l"(b));
}
__device__ __forceinline__ float2 unpack2(unsigned long long v) {
    float2 r;
    asm("mov.b64 {%0, %1}, %2;" : "=f"(r.x), "=f"(r.y) : "l"(v));
    return r;
}

// =====================================================================
// K1: hid = tanh(A @ W1 + b1)   A:(8192,512) W:(512,32)
// BM=128 rows/block, 256 threads, thread tile 4x4, BK=32
// =====================================================================
__global__ __launch_bounds__(256)
void k_hidden_tanh(const float* __restrict__ A, const float* __restrict__ W,
                   const float* __restrict__ b) {
    __shared__ float As[32][132];
    __shared__ float Ws[32][32];
    const int tid  = threadIdx.x;
    const int row0 = blockIdx.x * 128;
    const int ty = tid / 8, tx = tid % 8;      // rows ty*4.. , cols tx*4..
    float acc[4][4] = {};

    for (int k0 = 0; k0 < DIN; k0 += 32) {
        #pragma unroll
        for (int p = 0; p < 4; p++) {
            int r  = p * 32 + tid / 8;
            int kq = (tid % 8) * 4;
            float4 v = *(const float4*)&A[(size_t)(row0 + r) * DIN + k0 + kq];
            As[kq + 0][r] = v.x; As[kq + 1][r] = v.y;
            As[kq + 2][r] = v.z; As[kq + 3][r] = v.w;
        }
        {
            int k = tid / 8, c4 = (tid % 8) * 4;
            *(float4*)&Ws[k][c4] = *(const float4*)&W[(size_t)(k0 + k) * DH + c4];
        }
        __syncthreads();
        #pragma unroll
        for (int k = 0; k < 32; k++) {
            float4 a = *(const float4*)&As[k][ty * 4];
            float4 w = *(const float4*)&Ws[k][tx * 4];
            float av[4] = {a.x, a.y, a.z, a.w};
            float wv[4] = {w.x, w.y, w.z, w.w};
            #pragma unroll
            for (int r = 0; r < 4; r++)
                #pragma unroll
                for (int c = 0; c < 4; c++)
                    acc[r][c] += av[r] * wv[c];
        }
        __syncthreads();
    }
    #pragma unroll
    for (int r = 0; r < 4; r++) {
        int row = row0 + ty * 4 + r;
        #pragma unroll
        for (int c = 0; c < 4; c++)
            g_hid[row * DH + tx * 4 + c] = tanhf(acc[r][c] + b[tx * 4 + c]);
    }
}

// =====================================================================
// K2: att = hid @ W2 + b2   (8192x32 @ 32x32). One thread per output.
// which=0 -> g_natt, which=1 -> g_xatt
// =====================================================================
__global__ __launch_bounds__(256)
void k_att32(const float* __restrict__ W2, const float* __restrict__ b2, int which) {
    int gid = blockIdx.x * 256 + threadIdx.x;
    int n = gid / DH, c = gid % DH;
    const float* h = &g_hid[n * DH];
    float s = b2[c];
    #pragma unroll
    for (int k = 0; k < DH; k++) s += h[k] * W2[k * DH + c];
    float* dst = which ? g_xatt : g_natt;
    dst[n * DH + c] = s;
}

// =====================================================================
// K3: C = A @ W + b   A:(8192,512) W:(512,256)
// BM=64, 256 threads, thread tile 8x8 (ty=tid/32 rows, tx=tid%32 cols), BK=32
// use_value_buf: 1 -> write g_value (ldc ignored=256), 0 -> write Cout with ldc
// =====================================================================
__global__ __launch_bounds__(256)
void k_gemm512x256(const float* __restrict__ A, const float* __restrict__ W,
                   const float* __restrict__ b, float* Cout, int ldc,
                   int use_value_buf) {
    __shared__ float As[32][68];
    __shared__ float Ws[32][256];
    const int tid  = threadIdx.x;
    const int row0 = blockIdx.x * 64;
    const int ty = tid / 32, tx = tid % 32;
    unsigned long long acc[8][4];
    #pragma unroll
    for (int r = 0; r < 8; r++)
        #pragma unroll
        for (int c = 0; c < 4; c++) acc[r][c] = 0ULL;

    for (int k0 = 0; k0 < DIN; k0 += 32) {
        #pragma unroll
        for (int p = 0; p < 2; p++) {
            int r  = p * 32 + tid / 8;
            int kq = (tid % 8) * 4;
            float4 v = *(const float4*)&A[(size_t)(row0 + r) * DIN + k0 + kq];
            As[kq + 0][r] = v.x; As[kq + 1][r] = v.y;
            As[kq + 2][r] = v.z; As[kq + 3][r] = v.w;
        }
        #pragma unroll
        for (int p = 0; p < 8; p++) {
            int i = p * 256 + tid;
            int k = i / 64, c4 = (i % 64) * 4;
            *(float4*)&Ws[k][c4] = *(const float4*)&W[(size_t)(k0 + k) * DOUT + c4];
        }
        __syncthreads();
        #pragma unroll 8
        for (int k = 0; k < 32; k++) {
            float4 a0 = *(const float4*)&As[k][ty * 8];
            float4 a1 = *(const float4*)&As[k][ty * 8 + 4];
            ulonglong2 vA = *(const ulonglong2*)&Ws[k][tx * 8];
            ulonglong2 vB = *(const ulonglong2*)&Ws[k][tx * 8 + 4];
            float av[8] = {a0.x, a0.y, a0.z, a0.w, a1.x, a1.y, a1.z, a1.w};
            unsigned long long vv[4] = {vA.x, vA.y, vB.x, vB.y};
            #pragma unroll
            for (int r = 0; r < 8; r++) {
                unsigned long long ar = pack2(av[r], av[r]);
                #pragma unroll
                for (int c = 0; c < 4; c++) fma2(acc[r][c], ar, vv[c]);
            }
        }
        __syncthreads();
    }
    float* C = use_value_buf ? g_value : Cout;
    int ld   = use_value_buf ? DOUT : ldc;
    #pragma unroll
    for (int r = 0; r < 8; r++) {
        int row = row0 + ty * 8 + r;
        float o[8];
        #pragma unroll
        for (int c = 0; c < 4; c++) {
            float2 u = unpack2(acc[r][c]);
            o[2 * c]     = u.x + b[tx * 8 + 2 * c];
            o[2 * c + 1] = u.y + b[tx * 8 + 2 * c + 1];
        }
        float4 s0 = {o[0], o[1], o[2], o[3]};
        float4 s1 = {o[4], o[5], o[6], o[7]};
        size_t off = (size_t)row * ld + tx * 8;
        *(float4*)&C[off]     = s0;
        *(float4*)&C[off + 4] = s1;
    }
}

// =====================================================================
// K4: E[n,m] = adj ? exp(leaky_relu(xatt[n].natt[m])) : 0 ; rowsum[n]=sum_m E
// One block owns 64 full rows (no atomics, no max pass needed: scores tiny,
// masked -> exactly 0, matching reference's exp(-9e15-max) underflow).
// 256 threads, thread tile 4 rows x 8 m, m-tiles of 128.
// =====================================================================
__global__ __launch_bounds__(256)
void k_score_exp(const int* __restrict__ adj) {
    __shared__ float Qs[32][68];
    __shared__ float Ks[32][132];
    __shared__ float Red[64][16];
    const int tid  = threadIdx.x;
    const int row0 = blockIdx.x * 64;
    const int ty = tid / 16, tx = tid % 16;   // rows ty*4.., m offset tx*8

    #pragma unroll
    for (int p = 0; p < 2; p++) {
        int r  = p * 32 + tid / 8;
        int kq = (tid % 8) * 4;
        float4 v = *(const float4*)&g_xatt[(row0 + r) * DH + kq];
        Qs[kq + 0][r] = v.x; Qs[kq + 1][r] = v.y;
        Qs[kq + 2][r] = v.z; Qs[kq + 3][r] = v.w;
    }
    float rowacc[4] = {0.f, 0.f, 0.f, 0.f};

    for (int mt = 0; mt < NN / 128; mt++) {
        const int m0 = mt * 128;
        __syncthreads();
        #pragma unroll
        for (int p = 0; p < 4; p++) {
            int m  = p * 32 + tid / 8;
            int kq = (tid % 8) * 4;
            float4 v = *(const float4*)&g_natt[(m0 + m) * DH + kq];
            Ks[kq + 0][m] = v.x; Ks[kq + 1][m] = v.y;
            Ks[kq + 2][m] = v.z; Ks[kq + 3][m] = v.w;
        }
        __syncthreads();

        float s[4][8] = {};
        #pragma unroll 8
        for (int k = 0; k < 32; k++) {
            float4 q  = *(const float4*)&Qs[k][ty * 4];
            float4 b0 = *(const float4*)&Ks[k][tx * 8];
            float4 b1 = *(const float4*)&Ks[k][tx * 8 + 4];
            float qa[4] = {q.x, q.y, q.z, q.w};
            float kb[8] = {b0.x, b0.y, b0.z, b0.w, b1.x, b1.y, b1.z, b1.w};
            #pragma unroll
            for (int r = 0; r < 4; r++)
                #pragma unroll
                for (int j = 0; j < 8; j++)
                    s[r][j] += qa[r] * kb[j];
        }
        #pragma unroll
        for (int r = 0; r < 4; r++) {
            int row = row0 + ty * 4 + r;
            size_t off = (size_t)row * NN + m0 + tx * 8;
            const int4* ap = (const int4*)&adj[off];
            int4 a0 = ap[0], a1 = ap[1];
            int am[8] = {a0.x, a0.y, a0.z, a0.w, a1.x, a1.y, a1.z, a1.w};
            float e[8];
            float sum = 0.f;
            #pragma unroll
            for (int j = 0; j < 8; j++) {
                float sv = s[r][j];
                float w  = sv > 0.f ? sv : 0.01f * sv;   // leaky_relu(0.01)
                e[j] = (am[j] > 0) ? __expf(w) : 0.0f;
                sum += e[j];
            }
            rowacc[r] += sum;
            float4 e0 = {e[0], e[1], e[2], e[3]};
            float4 e1 = {e[4], e[5], e[6], e[7]};
            *(float4*)&g_E[off]     = e0;
            *(float4*)&g_E[off + 4] = e1;
        }
    }
    #pragma unroll
    for (int r = 0; r < 4; r++) Red[ty * 4 + r][tx] = rowacc[r];
    __syncthreads();
    if (tid < 64) {
        float t = 0.f;
        #pragma unroll
        for (int j = 0; j < 16; j++) t += Red[tid][j];
        g_rowsum[row0 + tid] = t;
    }
}

// =====================================================================
// K5: out[n, 256+d] = (E @ value)[n,d] / rowsum[n]
// BM=64 rows/block, 256 threads, 8x8 thread tile, K=8192 in BK=32 tiles.
// Inner loop uses packed fma.rn.f32x2 (2 fp32 FMA / inst).
// =====================================================================
__global__ __launch_bounds__(256)
void k_pv(float* __restrict__ out) {
    __shared__ float Es[32][68];
    __shared__ float Vs[32][256];
    const int tid  = threadIdx.x;
    const int row0 = blockIdx.x * 64;
    const int ty = tid / 32, tx = tid % 32;
    unsigned long long acc[8][4];
    #pragma unroll
    for (int r = 0; r < 8; r++)
        #pragma unroll
        for (int c = 0; c < 4; c++) acc[r][c] = 0ULL;

    for (int kt = 0; kt < NN / 32; kt++) {
        const int k0 = kt * 32;
        __syncthreads();
        #pragma unroll
        for (int p = 0; p < 2; p++) {
            int r  = p * 32 + tid / 8;
            int kq = (tid % 8) * 4;
            float4 v = *(const float4*)&g_E[(size_t)(row0 + r) * NN + k0 + kq];
            Es[kq + 0][r] = v.x; Es[kq + 1][r] = v.y;
            Es[kq + 2][r] = v.z; Es[kq + 3][r] = v.w;
        }
        #pragma unroll
        for (int p = 0; p < 8; p++) {
            int i = p * 256 + tid;
            int k = i / 64, c4 = (i % 64) * 4;
            *(float4*)&Vs[k][c4] = *(const float4*)&g_value[(size_t)(k0 + k) * DOUT + c4];
        }
        __syncthreads();
        #pragma unroll 8
        for (int k = 0; k < 32; k++) {
            float4 a0 = *(const float4*)&Es[k][ty * 8];
            float4 a1 = *(const float4*)&Es[k][ty * 8 + 4];
            ulonglong2 vA = *(const ulonglong2*)&Vs[k][tx * 8];
            ulonglong2 vB = *(const ulonglong2*)&Vs[k][tx * 8 + 4];
            float av[8] = {a0.x, a0.y, a0.z, a0.w, a1.x, a1.y, a1.z, a1.w};
            unsigned long long vv[4] = {vA.x, vA.y, vB.x, vB.y};
            #pragma unroll
            for (int r = 0; r < 8; r++) {
                unsigned long long ar = pack2(av[r], av[r]);
                #pragma unroll
                for (int c = 0; c < 4; c++) fma2(acc[r][c], ar, vv[c]);
            }
        }
    }
    #pragma unroll
    for (int r = 0; r < 8; r++) {
        int row = row0 + ty * 8 + r;
        float inv = 1.0f / g_rowsum[row];
        float o[8];
        #pragma unroll
        for (int c = 0; c < 4; c++) {
            float2 u = unpack2(acc[r][c]);
            o[2 * c]     = u.x * inv;
            o[2 * c + 1] = u.y * inv;
        }
        float4 s0 = {o[0], o[1], o[2], o[3]};
        float4 s1 = {o[4], o[5], o[6], o[7]};
        size_t off = (size_t)row * (2 * DOUT) + DOUT + tx * 8;
        *(float4*)&out[off]     = s0;
        *(float4*)&out[off + 4] = s1;
    }
}

// =====================================================================
// launch
// =====================================================================
extern "C" void kernel_launch(void* const* d_in, const int* in_sizes, int n_in,
                              void* d_out, int out_size) {
    const float* x    = (const float*)d_in[0];
    const float* neigh= (const float*)d_in[1];
    const int*   adj  = (const int*)  d_in[2];
    const float* Wx1  = (const float*)d_in[3];
    const float* bx1  = (const float*)d_in[4];
    const float* Wx2  = (const float*)d_in[5];
    const float* bx2  = (const float*)d_in[6];
    const float* Wn1  = (const float*)d_in[7];
    const float* bn1  = (const float*)d_in[8];
    const float* Wn2  = (const float*)d_in[9];
    const float* bn2  = (const float*)d_in[10];
    const float* Wv   = (const float*)d_in[11];
    const float* bv   = (const float*)d_in[12];
    const float* Wfx  = (const float*)d_in[13];
    const float* bfx  = (const float*)d_in[14];
    float* out = (float*)d_out;

    // neighbor branch: hidden -> att
    k_hidden_tanh<<<NX / 128, 256>>>(neigh, Wn1, bn1);
    k_att32<<<NX * DH / 256, 256>>>(Wn2, bn2, /*which=*/0);
    // x branch: hidden -> att
    k_hidden_tanh<<<NX / 128, 256>>>(x, Wx1, bx1);
    k_att32<<<NX * DH / 256, 256>>>(Wx2, bx2, /*which=*/1);
    // value and fc_x
    k_gemm512x256<<<NX / 64, 256>>>(neigh, Wv, bv, nullptr, 0, /*value buf*/1);
    k_gemm512x256<<<NX / 64, 256>>>(x, Wfx, bfx, out, 2 * DOUT, /*direct*/0);
    // masked exp scores + row sums
    k_score_exp<<<NX / 64, 256>>>(adj);
    // softmax-normalized aggregation
    k_pv<<<NX / 64, 256>>>(out);
}

// round 3
// speedup vs baseline: 2.5161x; 2.5161x over previous
#include <cuda_runtime.h>
#include <cuda_bf16.h>
#include <cstdint>

#define NX   8192
#define NN   8192
#define DIN  512
#define DH   32
#define DOUT 256

// ---------------- scratch (static __device__: allocation-free) ----------------
__device__ float g_hid [NX * DH];
__device__ float g_xatt[NX * DH];
__device__ float g_natt[NN * DH];
__device__ __nv_bfloat16 g_valueT[(size_t)DOUT * NN];   // 4 MB, [d][n] (transposed, bf16)
__device__ __nv_bfloat16 g_E[(size_t)NX * NN];          // 128 MB: masked exp'd scores (bf16)
__device__ float g_rowsum[NX];

// ---------------- f32x2 packed helpers ----------------
__device__ __forceinline__ unsigned long long pack2(float a, float b) {
    unsigned long long r;
    asm("mov.b64 %0, {%1, %2};" : "=l"(r) : "f"(a), "f"(b));
    return r;
}
__device__ __forceinline__ void fma2(unsigned long long &d, unsigned long long a,
                                     unsigned long long b) {
    asm("fma.rn.f32x2 %0, %1, %2, %0;" : "+l"(d) : "l"(a), "l"(b));
}
__device__ __forceinline__ float2 unpack2(unsigned long long v) {
    float2 r;
    asm("mov.b64 {%0, %1}, %2;" : "=f"(r.x), "=f"(r.y) : "l"(v));
    return r;
}

// ---------------- portable async-copy / mma helpers ----------------
__device__ __forceinline__ uint32_t smem_u32(const void* p) {
    uint32_t a;
    asm("{ .reg .u64 t; cvta.to.shared.u64 t, %1; cvt.u32.u64 %0, t; }" : "=r"(a) : "l"(p));
    return a;
}
#define CP16(dst, src) \
    asm volatile("cp.async.cg.shared.global [%0], [%1], 16;" :: "r"(dst), "l"(src))
#define CP_COMMIT() asm volatile("cp.async.commit_group;" ::: "memory")
#define CP_WAIT2()  asm volatile("cp.async.wait_group 2;" ::: "memory")

#define SW128(off) ((off) ^ (((off) >> 3) & 0x70))

#define LDMX4(r0, r1, r2, r3, addr) \
    asm volatile("ldmatrix.sync.aligned.m8n8.x4.shared.b16 {%0,%1,%2,%3}, [%4];" \
                 : "=r"(r0), "=r"(r1), "=r"(r2), "=r"(r3) : "r"(addr))

#define MMA16816(c, a, b) \
    asm volatile("mma.sync.aligned.m16n8k16.row.col.f32.bf16.bf16.f32 " \
                 "{%0,%1,%2,%3}, {%4,%5,%6,%7}, {%8,%9}, {%0,%1,%2,%3};" \
                 : "+f"((c)[0]), "+f"((c)[1]), "+f"((c)[2]), "+f"((c)[3]) \
                 : "r"((a)[0]), "r"((a)[1]), "r"((a)[2]), "r"((a)[3]), \
                   "r"((b)[0]), "r"((b)[1]))

// =====================================================================
// K1: hid = tanh(A @ W1 + b1)   A:(8192,512) W:(512,32)
// =====================================================================
__global__ __launch_bounds__(256)
void k_hidden_tanh(const float* __restrict__ A, const float* __restrict__ W,
                   const float* __restrict__ b) {
    __shared__ float As[32][132];
    __shared__ float Ws[32][32];
    const int tid  = threadIdx.x;
    const int row0 = blockIdx.x * 128;
    const int ty = tid / 8, tx = tid % 8;
    float acc[4][4] = {};

    for (int k0 = 0; k0 < DIN; k0 += 32) {
        #pragma unroll
        for (int p = 0; p < 4; p++) {
            int r  = p * 32 + tid / 8;
            int kq = (tid % 8) * 4;
            float4 v = *(const float4*)&A[(size_t)(row0 + r) * DIN + k0 + kq];
            As[kq + 0][r] = v.x; As[kq + 1][r] = v.y;
            As[kq + 2][r] = v.z; As[kq + 3][r] = v.w;
        }
        {
            int k = tid / 8, c4 = (tid % 8) * 4;
            *(float4*)&Ws[k][c4] = *(const float4*)&W[(size_t)(k0 + k) * DH + c4];
        }
        __syncthreads();
        #pragma unroll
        for (int k = 0; k < 32; k++) {
            float4 a = *(const float4*)&As[k][ty * 4];
            float4 w = *(const float4*)&Ws[k][tx * 4];
            float av[4] = {a.x, a.y, a.z, a.w};
            float wv[4] = {w.x, w.y, w.z, w.w};
            #pragma unroll
            for (int r = 0; r < 4; r++)
                #pragma unroll
                for (int c = 0; c < 4; c++)
                    acc[r][c] += av[r] * wv[c];
        }
        __syncthreads();
    }
    #pragma unroll
    for (int r = 0; r < 4; r++) {
        int row = row0 + ty * 4 + r;
        #pragma unroll
        for (int c = 0; c < 4; c++)
            g_hid[row * DH + tx * 4 + c] = tanhf(acc[r][c] + b[tx * 4 + c]);
    }
}

// =====================================================================
// K2: att = hid @ W2 + b2   (8192x32 @ 32x32)
// =====================================================================
__global__ __launch_bounds__(256)
void k_att32(const float* __restrict__ W2, const float* __restrict__ b2, int which) {
    int gid = blockIdx.x * 256 + threadIdx.x;
    int n = gid / DH, c = gid % DH;
    const float* h = &g_hid[n * DH];
    float s = b2[c];
    #pragma unroll
    for (int k = 0; k < DH; k++) s += h[k] * W2[k * DH + c];
    float* dst = which ? g_xatt : g_natt;
    dst[n * DH + c] = s;
}

// =====================================================================
// K3: C = A @ W + b   A:(8192,512) W:(512,256)
// use_value_buf=1 -> write g_valueT (bf16, transposed); 0 -> Cout fp32 (ldc)
// =====================================================================
__global__ __launch_bounds__(256)
void k_gemm512x256(const float* __restrict__ A, const float* __restrict__ W,
                   const float* __restrict__ b, float* Cout, int ldc,
                   int use_value_buf) {
    __shared__ float As[32][68];
    __shared__ float Ws[32][256];
    const int tid  = threadIdx.x;
    const int row0 = blockIdx.x * 64;
    const int ty = tid / 32, tx = tid % 32;
    unsigned long long acc[8][4];
    #pragma unroll
    for (int r = 0; r < 8; r++)
        #pragma unroll
        for (int c = 0; c < 4; c++) acc[r][c] = 0ULL;

    for (int k0 = 0; k0 < DIN; k0 += 32) {
        #pragma unroll
        for (int p = 0; p < 2; p++) {
            int r  = p * 32 + tid / 8;
            int kq = (tid % 8) * 4;
            float4 v = *(const float4*)&A[(size_t)(row0 + r) * DIN + k0 + kq];
            As[kq + 0][r] = v.x; As[kq + 1][r] = v.y;
            As[kq + 2][r] = v.z; As[kq + 3][r] = v.w;
        }
        #pragma unroll
        for (int p = 0; p < 8; p++) {
            int i = p * 256 + tid;
            int k = i / 64, c4 = (i % 64) * 4;
            *(float4*)&Ws[k][c4] = *(const float4*)&W[(size_t)(k0 + k) * DOUT + c4];
        }
        __syncthreads();
        #pragma unroll 8
        for (int k = 0; k < 32; k++) {
            float4 a0 = *(const float4*)&As[k][ty * 8];
            float4 a1 = *(const float4*)&As[k][ty * 8 + 4];
            ulonglong2 vA = *(const ulonglong2*)&Ws[k][tx * 8];
            ulonglong2 vB = *(const ulonglong2*)&Ws[k][tx * 8 + 4];
            float av[8] = {a0.x, a0.y, a0.z, a0.w, a1.x, a1.y, a1.z, a1.w};
            unsigned long long vv[4] = {vA.x, vA.y, vB.x, vB.y};
            #pragma unroll
            for (int r = 0; r < 8; r++) {
                unsigned long long ar = pack2(av[r], av[r]);
                #pragma unroll
                for (int c = 0; c < 4; c++) fma2(acc[r][c], ar, vv[c]);
            }
        }
        __syncthreads();
    }
    float ov[8][8];
    #pragma unroll
    for (int r = 0; r < 8; r++)
        #pragma unroll
        for (int c4 = 0; c4 < 4; c4++) {
            float2 u = unpack2(acc[r][c4]);
            ov[r][2 * c4]     = u.x + b[tx * 8 + 2 * c4];
            ov[r][2 * c4 + 1] = u.y + b[tx * 8 + 2 * c4 + 1];
        }
    if (use_value_buf) {
        const int rowb = row0 + ty * 8;
        #pragma unroll
        for (int c = 0; c < 8; c++) {
            int d = tx * 8 + c;
            __nv_bfloat162 p0 = __floats2bfloat162_rn(ov[0][c], ov[1][c]);
            __nv_bfloat162 p1 = __floats2bfloat162_rn(ov[2][c], ov[3][c]);
            __nv_bfloat162 p2 = __floats2bfloat162_rn(ov[4][c], ov[5][c]);
            __nv_bfloat162 p3 = __floats2bfloat162_rn(ov[6][c], ov[7][c]);
            uint4 u;
            u.x = reinterpret_cast<uint32_t&>(p0);
            u.y = reinterpret_cast<uint32_t&>(p1);
            u.z = reinterpret_cast<uint32_t&>(p2);
            u.w = reinterpret_cast<uint32_t&>(p3);
            *reinterpret_cast<uint4*>(&g_valueT[(size_t)d * NN + rowb]) = u;
        }
    } else {
        #pragma unroll
        for (int r = 0; r < 8; r++) {
            int row = row0 + ty * 8 + r;
            float4 s0 = {ov[r][0], ov[r][1], ov[r][2], ov[r][3]};
            float4 s1 = {ov[r][4], ov[r][5], ov[r][6], ov[r][7]};
            size_t off = (size_t)row * ldc + tx * 8;
            *(float4*)&Cout[off]     = s0;
            *(float4*)&Cout[off + 4] = s1;
        }
    }
}

// =====================================================================
// K4: E[n,m] = adj ? exp(leaky_relu(xatt[n].natt[m])) : 0  (bf16)
// rowsum computed from bf16-rounded values. f32x2 in the QK inner loop.
// =====================================================================
__global__ __launch_bounds__(256)
void k_score_exp(const int* __restrict__ adj) {
    __shared__ float Qs[32][68];
    __shared__ float Ks[32][132];
    __shared__ float Red[64][16];
    const int tid  = threadIdx.x;
    const int row0 = blockIdx.x * 64;
    const int ty = tid / 16, tx = tid % 16;

    #pragma unroll
    for (int p = 0; p < 2; p++) {
        int r  = p * 32 + tid / 8;
        int kq = (tid % 8) * 4;
        float4 v = *(const float4*)&g_xatt[(row0 + r) * DH + kq];
        Qs[kq + 0][r] = v.x; Qs[kq + 1][r] = v.y;
        Qs[kq + 2][r] = v.z; Qs[kq + 3][r] = v.w;
    }
    float rowacc[4] = {0.f, 0.f, 0.f, 0.f};

    for (int mt = 0; mt < NN / 128; mt++) {
        const int m0 = mt * 128;
        __syncthreads();
        #pragma unroll
        for (int p = 0; p < 4; p++) {
            int m  = p * 32 + tid / 8;
            int kq = (tid % 8) * 4;
            float4 v = *(const float4*)&g_natt[(m0 + m) * DH + kq];
            Ks[kq + 0][m] = v.x; Ks[kq + 1][m] = v.y;
            Ks[kq + 2][m] = v.z; Ks[kq + 3][m] = v.w;
        }
        __syncthreads();

        unsigned long long sacc[4][4];
        #pragma unroll
        for (int r = 0; r < 4; r++)
            #pragma unroll
            for (int c = 0; c < 4; c++) sacc[r][c] = 0ULL;
        #pragma unroll 8
        for (int k = 0; k < 32; k++) {
            float4 q  = *(const float4*)&Qs[k][ty * 4];
            ulonglong2 kA = *(const ulonglong2*)&Ks[k][tx * 8];
            ulonglong2 kB = *(const ulonglong2*)&Ks[k][tx * 8 + 4];
            float qa[4] = {q.x, q.y, q.z, q.w};
            unsigned long long kv[4] = {kA.x, kA.y, kB.x, kB.y};
            #pragma unroll
            for (int r = 0; r < 4; r++) {
                unsigned long long qr = pack2(qa[r], qa[r]);
                #pragma unroll
                for (int c = 0; c < 4; c++) fma2(sacc[r][c], qr, kv[c]);
            }
        }
        #pragma unroll
        for (int r = 0; r < 4; r++) {
            int row = row0 + ty * 4 + r;
            size_t off = (size_t)row * NN + m0 + tx * 8;
            const int4* ap = (const int4*)&adj[off];
            int4 a0 = ap[0], a1 = ap[1];
            int am[8] = {a0.x, a0.y, a0.z, a0.w, a1.x, a1.y, a1.z, a1.w};
            float sv[8];
            #pragma unroll
            for (int c = 0; c < 4; c++) {
                float2 u = unpack2(sacc[r][c]);
                sv[2 * c] = u.x; sv[2 * c + 1] = u.y;
            }
            __nv_bfloat162 pk[4];
            float sum = 0.f;
            #pragma unroll
            for (int j2 = 0; j2 < 4; j2++) {
                float s0 = sv[2 * j2],     s1 = sv[2 * j2 + 1];
                float w0 = s0 > 0.f ? s0 : 0.01f * s0;
                float w1 = s1 > 0.f ? s1 : 0.01f * s1;
                float e0 = (am[2 * j2] > 0)     ? __expf(w0) : 0.0f;
                float e1 = (am[2 * j2 + 1] > 0) ? __expf(w1) : 0.0f;
                __nv_bfloat162 p = __floats2bfloat162_rn(e0, e1);
                pk[j2] = p;
                sum += __low2float(p) + __high2float(p);
            }
            rowacc[r] += sum;
            uint4 u;
            u.x = reinterpret_cast<uint32_t&>(pk[0]);
            u.y = reinterpret_cast<uint32_t&>(pk[1]);
            u.z = reinterpret_cast<uint32_t&>(pk[2]);
            u.w = reinterpret_cast<uint32_t&>(pk[3]);
            *reinterpret_cast<uint4*>(&g_E[off]) = u;
        }
    }
    #pragma unroll
    for (int r = 0; r < 4; r++) Red[ty * 4 + r][tx] = rowacc[r];
    __syncthreads();
    if (tid < 64) {
        float t = 0.f;
        #pragma unroll
        for (int j = 0; j < 16; j++) t += Red[tid][j];
        g_rowsum[row0 + tid] = t;
    }
}

// =====================================================================
// K5: HMMA PV GEMM: agg = softmax_norm(E @ V)
// CTA M=128, N=128; 8 warps (4x2), warp tile 32x64, m16n8k16 bf16.
// BK=64, 4-stage cp.async pipeline (4 x 32KB SMEM), grid=128 (one wave).
// =====================================================================
#define PV_BK     64
#define PV_NCH    (NN / PV_BK)      // 128
#define PV_STAGEB 32768             // 16KB E + 16KB V per stage
#define PV_SMEM   (4 * PV_STAGEB + 1024)

__device__ __forceinline__ void pv_load(uint32_t tile, int tid, int row0, int n0, int c) {
    const size_t kb = (size_t)c * (PV_BK * 2);          // byte offset along K
    const uint32_t eb = tile + (uint32_t)(c & 3) * PV_STAGEB;
    const uint32_t vb = eb + 16384u;
    #pragma unroll
    for (int p = 0; p < 4; p++) {
        int u = p * 256 + tid;          // 0..1023
        int row = u >> 3, j = u & 7;
        uint32_t soff = SW128((uint32_t)(row * 128 + j * 16));
        const char* gE = (const char*)g_E +
            ((size_t)(row0 + row) * NN) * 2 + kb + (size_t)(j * 16);
        CP16(eb + soff, gE);
        const char* gV = (const char*)g_valueT +
            ((size_t)(n0 + row) * NN) * 2 + kb + (size_t)(j * 16);
        CP16(vb + soff, gV);
    }
}

__global__ __launch_bounds__(256)
void k_pv_mma(float* __restrict__ out) {
    extern __shared__ __align__(16) char dynsmem[];
    const int tid = threadIdx.x;
    const int wid = tid >> 5;
    const int l   = tid & 31;
    const int row0 = (int)(blockIdx.x >> 1) * 128;
    const int n0   = (int)(blockIdx.x & 1) * 128;
    const int wm0  = (wid >> 1) * 32;   // warp M offset in tile
    const int wn0  = (wid & 1) * 64;    // warp N offset in tile

    const uint32_t dynb = smem_u32(dynsmem);
    const uint32_t tile = (dynb + 1023u) & ~1023u;

    float acc[2][8][4];
    #pragma unroll
    for (int t = 0; t < 2; t++)
        #pragma unroll
        for (int u = 0; u < 8; u++)
            #pragma unroll
            for (int c = 0; c < 4; c++) acc[t][u][c] = 0.f;

    // prologue: 3 chunks in flight
    pv_load(tile, tid, row0, n0, 0); CP_COMMIT();
    pv_load(tile, tid, row0, n0, 1); CP_COMMIT();
    pv_load(tile, tid, row0, n0, 2); CP_COMMIT();

    // lane-invariant address pieces
    const int lm16 = l & 15;                       // A: row within m16 tile
    const int lhi  = (l >> 4) * 16;                // A: k-half byte offset
    const int bn   = (l & 7) + ((l >> 4) << 3);    // B: n-row within n16 pair
    const int bk16 = ((l >> 3) & 1) * 16;          // B: k8 byte offset

    for (int i = 0; i < PV_NCH; i++) {
        CP_WAIT2();                 // chunk i resident
        __syncthreads();
        const uint32_t eb = tile + (uint32_t)(i & 3) * PV_STAGEB;
        const uint32_t vb = eb + 16384u;
        #pragma unroll
        for (int kk = 0; kk < 4; kk++) {
            uint32_t a[2][4];
            #pragma unroll
            for (int t = 0; t < 2; t++) {
                uint32_t off = (uint32_t)((wm0 + t * 16 + lm16) * 128 + kk * 32 + lhi);
                LDMX4(a[t][0], a[t][1], a[t][2], a[t][3], eb + SW128(off));
            }
            uint32_t b[8][2];
            #pragma unroll
            for (int u2 = 0; u2 < 4; u2++) {
                uint32_t off = (uint32_t)((wn0 + u2 * 16 + bn) * 128 + kk * 32 + bk16);
                uint32_t r0, r1, r2, r3;
                LDMX4(r0, r1, r2, r3, vb + SW128(off));
                b[2 * u2][0] = r0;     b[2 * u2][1] = r1;
                b[2 * u2 + 1][0] = r2; b[2 * u2 + 1][1] = r3;
            }
            #pragma unroll
            for (int t = 0; t < 2; t++)
                #pragma unroll
                for (int u = 0; u < 8; u++)
                    MMA16816(acc[t][u], a[t], b[u]);
        }
        const int j = i + 3;
        if (j < PV_NCH) pv_load(tile, tid, row0, n0, j);
        CP_COMMIT();
    }

    // epilogue: divide by rowsum, direct stores
    #pragma unroll
    for (int t = 0; t < 2; t++) {
        int ra = row0 + wm0 + t * 16 + (l >> 2);
        int rb = ra + 8;
        float inva = 1.0f / g_rowsum[ra];
        float invb = 1.0f / g_rowsum[rb];
        #pragma unroll
        for (int u = 0; u < 8; u++) {
            int col = DOUT + n0 + wn0 + u * 8 + (l & 3) * 2;
            float2 v0 = {acc[t][u][0] * inva, acc[t][u][1] * inva};
            float2 v1 = {acc[t][u][2] * invb, acc[t][u][3] * invb};
            *(float2*)&out[(size_t)ra * (2 * DOUT) + col] = v0;
            *(float2*)&out[(size_t)rb * (2 * DOUT) + col] = v1;
        }
    }
}

// =====================================================================
// launch
// =====================================================================
extern "C" void kernel_launch(void* const* d_in, const int* in_sizes, int n_in,
                              void* d_out, int out_size) {
    const float* x    = (const float*)d_in[0];
    const float* neigh= (const float*)d_in[1];
    const int*   adj  = (const int*)  d_in[2];
    const float* Wx1  = (const float*)d_in[3];
    const float* bx1  = (const float*)d_in[4];
    const float* Wx2  = (const float*)d_in[5];
    const float* bx2  = (const float*)d_in[6];
    const float* Wn1  = (const float*)d_in[7];
    const float* bn1  = (const float*)d_in[8];
    const float* Wn2  = (const float*)d_in[9];
    const float* bn2  = (const float*)d_in[10];
    const float* Wv   = (const float*)d_in[11];
    const float* bv   = (const float*)d_in[12];
    const float* Wfx  = (const float*)d_in[13];
    const float* bfx  = (const float*)d_in[14];
    float* out = (float*)d_out;

    cudaFuncSetAttribute(k_pv_mma, cudaFuncAttributeMaxDynamicSharedMemorySize, PV_SMEM);

    // neighbor branch: hidden -> att
    k_hidden_tanh<<<NX / 128, 256>>>(neigh, Wn1, bn1);
    k_att32<<<NX * DH / 256, 256>>>(Wn2, bn2, /*which=*/0);
    // x branch: hidden -> att
    k_hidden_tanh<<<NX / 128, 256>>>(x, Wx1, bx1);
    k_att32<<<NX * DH / 256, 256>>>(Wx2, bx2, /*which=*/1);
    // value (-> transposed bf16) and fc_x (direct to out)
    k_gemm512x256<<<NX / 64, 256>>>(neigh, Wv, bv, nullptr, 0, /*value*/1);
    k_gemm512x256<<<NX / 64, 256>>>(x, Wfx, bfx, out, 2 * DOUT, /*direct*/0);
    // masked exp scores (bf16) + row sums
    k_score_exp<<<NX / 64, 256>>>(adj);
    // HMMA PV with softmax normalization
    k_pv_mma<<<(NX / 128) * 2, 256, PV_SMEM>>>(out);
}

// round 5
// speedup vs baseline: 3.0035x; 1.1937x over previous
#include <cuda_runtime.h>
#include <cuda_bf16.h>
#include <cstdint>

#define NX   8192
#define NN   8192
#define DIN  512
#define DH   32
#define DOUT 256

// ---------------- scratch (static __device__: allocation-free) ----------------
__device__ __nv_bfloat16 g_xattb[NX * DH];              // bf16 att (x)
__device__ __nv_bfloat16 g_nattb[NN * DH];              // bf16 att (neigh)
__device__ __nv_bfloat16 g_valueT[(size_t)DOUT * NN];   // 4 MB, [d][n] bf16
__device__ __nv_bfloat16 g_E[(size_t)NX * NN];          // 128 MB masked exp'd scores
__device__ float g_rowsum[NX];

// ---------------- f32x2 packed helpers ----------------
__device__ __forceinline__ unsigned long long pack2(float a, float b) {
    unsigned long long r;
    asm("mov.b64 %0, {%1, %2};" : "=l"(r) : "f"(a), "f"(b));
    return r;
}
__device__ __forceinline__ void fma2(unsigned long long &d, unsigned long long a,
                                     unsigned long long b) {
    asm("fma.rn.f32x2 %0, %1, %2, %0;" : "+l"(d) : "l"(a), "l"(b));
}
__device__ __forceinline__ float2 unpack2(unsigned long long v) {
    float2 r;
    asm("mov.b64 {%0, %1}, %2;" : "=f"(r.x), "=f"(r.y) : "l"(v));
    return r;
}

// ---------------- portable helpers ----------------
__device__ __forceinline__ uint32_t smem_u32(const void* p) {
    uint32_t a;
    asm("{ .reg .u64 t; cvta.to.shared.u64 t, %1; cvt.u32.u64 %0, t; }" : "=r"(a) : "l"(p));
    return a;
}
#define CP16(dst, src) \
    asm volatile("cp.async.cg.shared.global [%0], [%1], 16;" :: "r"(dst), "l"(src))
#define CP_COMMIT() asm volatile("cp.async.commit_group;" ::: "memory")
#define CP_WAIT1()  asm volatile("cp.async.wait_group 1;" ::: "memory")
#define CP_WAIT2()  asm volatile("cp.async.wait_group 2;" ::: "memory")

#define SW128(off) ((off) ^ (((off) >> 3) & 0x70))

#define LDMX4(r0, r1, r2, r3, addr) \
    asm volatile("ldmatrix.sync.aligned.m8n8.x4.shared.b16 {%0,%1,%2,%3}, [%4];" \
                 : "=r"(r0), "=r"(r1), "=r"(r2), "=r"(r3) : "r"(addr))

#define MMA16816(c, a, b) \
    asm volatile("mma.sync.aligned.m16n8k16.row.col.f32.bf16.bf16.f32 " \
                 "{%0,%1,%2,%3}, {%4,%5,%6,%7}, {%8,%9}, {%0,%1,%2,%3};" \
                 : "+f"((c)[0]), "+f"((c)[1]), "+f"((c)[2]), "+f"((c)[3]) \
                 : "r"((a)[0]), "r"((a)[1]), "r"((a)[2]), "r"((a)[3]), \
                   "r"((b)[0]), "r"((b)[1]))

// =====================================================================
// K1: fused MLP: att = tanh(A @ W1 + b1) @ W2 + b2 -> bf16
// =====================================================================
__global__ __launch_bounds__(256)
void k_mlp(const float* __restrict__ A, const float* __restrict__ W1,
           const float* __restrict__ b1, const float* __restrict__ W2,
           const float* __restrict__ b2, __nv_bfloat16* __restrict__ att) {
    __shared__ float As[32][132];
    __shared__ float Ws[32][32];
    __shared__ float W2s[32][33];
    __shared__ float Hs[128][36];
    const int tid  = threadIdx.x;
    const int row0 = blockIdx.x * 128;
    const int ty = tid / 8, tx = tid % 8;
    float acc[4][4] = {};

    #pragma unroll
    for (int p = 0; p < 4; p++) {
        int i = p * 256 + tid;
        W2s[i >> 5][i & 31] = W2[i];
    }

    for (int k0 = 0; k0 < DIN; k0 += 32) {
        #pragma unroll
        for (int p = 0; p < 4; p++) {
            int r  = p * 32 + tid / 8;
            int kq = (tid % 8) * 4;
            float4 v = *(const float4*)&A[(size_t)(row0 + r) * DIN + k0 + kq];
            As[kq + 0][r] = v.x; As[kq + 1][r] = v.y;
            As[kq + 2][r] = v.z; As[kq + 3][r] = v.w;
        }
        {
            int k = tid / 8, c4 = (tid % 8) * 4;
            *(float4*)&Ws[k][c4] = *(const float4*)&W1[(size_t)(k0 + k) * DH + c4];
        }
        __syncthreads();
        #pragma unroll
        for (int k = 0; k < 32; k++) {
            float4 a = *(const float4*)&As[k][ty * 4];
            float4 w = *(const float4*)&Ws[k][tx * 4];
            float av[4] = {a.x, a.y, a.z, a.w};
            float wv[4] = {w.x, w.y, w.z, w.w};
            #pragma unroll
            for (int r = 0; r < 4; r++)
                #pragma unroll
                for (int c = 0; c < 4; c++)
                    acc[r][c] += av[r] * wv[c];
        }
        __syncthreads();
    }
    #pragma unroll
    for (int r = 0; r < 4; r++)
        #pragma unroll
        for (int c = 0; c < 4; c++)
            Hs[ty * 4 + r][tx * 4 + c] = tanhf(acc[r][c] + b1[tx * 4 + c]);
    __syncthreads();

    {
        const int row = tid >> 1;
        const int cb  = (tid & 1) * 16;
        float s[16];
        #pragma unroll
        for (int j = 0; j < 16; j++) s[j] = b2[cb + j];
        #pragma unroll
        for (int k = 0; k < 32; k++) {
            float hv = Hs[row][k];
            #pragma unroll
            for (int j = 0; j < 16; j++) s[j] += hv * W2s[k][cb + j];
        }
        uint32_t ob[8];
        #pragma unroll
        for (int j2 = 0; j2 < 8; j2++) {
            __nv_bfloat162 p = __floats2bfloat162_rn(s[2 * j2], s[2 * j2 + 1]);
            ob[j2] = reinterpret_cast<uint32_t&>(p);
        }
        uint4 u0 = {ob[0], ob[1], ob[2], ob[3]};
        uint4 u1 = {ob[4], ob[5], ob[6], ob[7]};
        *(uint4*)&att[(size_t)(row0 + row) * DH + cb]     = u0;
        *(uint4*)&att[(size_t)(row0 + row) * DH + cb + 8] = u1;
    }
}

// =====================================================================
// K2a: fc_x in full fp32 (f32x2 FFMA) — output half is norm-dominant,
// so it must stay fp32-accurate. C = x @ Wfx + bfx -> out[:, 0:256].
// =====================================================================
__global__ __launch_bounds__(256)
void k_gemm_f32(const float* __restrict__ A, const float* __restrict__ W,
                const float* __restrict__ b, float* __restrict__ Cout) {
    __shared__ float As[32][68];
    __shared__ float Ws[32][256];
    const int tid  = threadIdx.x;
    const int row0 = blockIdx.x * 64;
    const int ty = tid / 32, tx = tid % 32;
    unsigned long long acc[8][4];
    #pragma unroll
    for (int r = 0; r < 8; r++)
        #pragma unroll
        for (int c = 0; c < 4; c++) acc[r][c] = 0ULL;

    for (int k0 = 0; k0 < DIN; k0 += 32) {
        #pragma unroll
        for (int p = 0; p < 2; p++) {
            int r  = p * 32 + tid / 8;
            int kq = (tid % 8) * 4;
            float4 v = *(const float4*)&A[(size_t)(row0 + r) * DIN + k0 + kq];
            As[kq + 0][r] = v.x; As[kq + 1][r] = v.y;
            As[kq + 2][r] = v.z; As[kq + 3][r] = v.w;
        }
        #pragma unroll
        for (int p = 0; p < 8; p++) {
            int i = p * 256 + tid;
            int k = i / 64, c4 = (i % 64) * 4;
            *(float4*)&Ws[k][c4] = *(const float4*)&W[(size_t)(k0 + k) * DOUT + c4];
        }
        __syncthreads();
        #pragma unroll 8
        for (int k = 0; k < 32; k++) {
            float4 a0 = *(const float4*)&As[k][ty * 8];
            float4 a1 = *(const float4*)&As[k][ty * 8 + 4];
            ulonglong2 vA = *(const ulonglong2*)&Ws[k][tx * 8];
            ulonglong2 vB = *(const ulonglong2*)&Ws[k][tx * 8 + 4];
            float av[8] = {a0.x, a0.y, a0.z, a0.w, a1.x, a1.y, a1.z, a1.w};
            unsigned long long vv[4] = {vA.x, vA.y, vB.x, vB.y};
            #pragma unroll
            for (int r = 0; r < 8; r++) {
                unsigned long long ar = pack2(av[r], av[r]);
                #pragma unroll
                for (int c = 0; c < 4; c++) fma2(acc[r][c], ar, vv[c]);
            }
        }
        __syncthreads();
    }
    #pragma unroll
    for (int r = 0; r < 8; r++) {
        int row = row0 + ty * 8 + r;
        float o[8];
        #pragma unroll
        for (int c4 = 0; c4 < 4; c4++) {
            float2 u = unpack2(acc[r][c4]);
            o[2 * c4]     = u.x + b[tx * 8 + 2 * c4];
            o[2 * c4 + 1] = u.y + b[tx * 8 + 2 * c4 + 1];
        }
        float4 s0 = {o[0], o[1], o[2], o[3]};
        float4 s1 = {o[4], o[5], o[6], o[7]};
        size_t off = (size_t)row * (2 * DOUT) + tx * 8;
        *(float4*)&Cout[off]     = s0;
        *(float4*)&Cout[off + 4] = s1;
    }
}

// =====================================================================
// K2b: value GEMM on HMMA, computed transposed (m-dim = d) so frags land
// in g_valueT[d][n] bf16. Agg side -> bf16 precision is fine (÷64 weight).
// =====================================================================
__device__ __forceinline__ void gemm_ldg(const float* __restrict__ X,
                                         const float* __restrict__ W,
                                         int row0, int d0, int kc, int tid,
                                         float4 xv[4], float wv[16]) {
    #pragma unroll
    for (int p = 0; p < 4; p++)
        xv[p] = *(const float4*)&X[(size_t)(row0 + p * 32 + (tid >> 3)) * DIN
                                   + kc * 32 + (tid & 7) * 4];
    const int wd = tid & 127, wkh = tid >> 7;
    #pragma unroll
    for (int k2 = 0; k2 < 16; k2++)
        wv[k2] = W[(size_t)(kc * 32 + wkh * 16 + k2) * DOUT + d0 + wd];
}
__device__ __forceinline__ void gemm_sts(char* sA, char* sB, int tid,
                                         const float4 xv[4], const float wv[16]) {
    #pragma unroll
    for (int p = 0; p < 4; p++) {
        __nv_bfloat162 b0 = __floats2bfloat162_rn(xv[p].x, xv[p].y);
        __nv_bfloat162 b1 = __floats2bfloat162_rn(xv[p].z, xv[p].w);
        uint2 u;
        u.x = reinterpret_cast<const uint32_t&>(b0);
        u.y = reinterpret_cast<const uint32_t&>(b1);
        *(uint2*)&sA[(p * 32 + (tid >> 3)) * 80 + (tid & 7) * 8] = u;
    }
    const int wd = tid & 127, wkh = tid >> 7;
    #pragma unroll
    for (int j = 0; j < 8; j++) {
        __nv_bfloat162 bb = __floats2bfloat162_rn(wv[2 * j], wv[2 * j + 1]);
        *(uint32_t*)&sB[wd * 80 + wkh * 32 + j * 4] = reinterpret_cast<const uint32_t&>(bb);
    }
}

__global__ __launch_bounds__(256)
void k_value_mma(const float* __restrict__ X, const float* __restrict__ W,
                 const float* __restrict__ bias) {
    __shared__ __align__(16) char sA[2][128 * 80];
    __shared__ __align__(16) char sB[2][128 * 80];
    const int tid = threadIdx.x, wid = tid >> 5, l = tid & 31;
    const int row0 = (int)(blockIdx.x >> 1) * 128;   // n block
    const int d0   = (int)(blockIdx.x & 1) * 128;    // d block
    const int wm = (wid >> 1) * 32, wn = (wid & 1) * 64;

    float acc[2][8][4];
    #pragma unroll
    for (int t = 0; t < 2; t++)
        #pragma unroll
        for (int u = 0; u < 8; u++)
            #pragma unroll
            for (int c = 0; c < 4; c++) acc[t][u][c] = 0.f;

    float4 xv[4]; float wv[16];
    gemm_ldg(X, W, row0, d0, 0, tid, xv, wv);
    gemm_sts(sA[0], sB[0], tid, xv, wv);
    gemm_ldg(X, W, row0, d0, 1, tid, xv, wv);

    const int lm16 = l & 15, lhi = (l >> 4) * 16;
    const int bn = (l & 7) + ((l >> 4) << 3), bk16 = ((l >> 3) & 1) * 16;

    for (int i = 0; i < 16; i++) {
        __syncthreads();
        if (i + 1 < 16) gemm_sts(sA[(i + 1) & 1], sB[(i + 1) & 1], tid, xv, wv);
        if (i + 2 < 16) gemm_ldg(X, W, row0, d0, i + 2, tid, xv, wv);

        const int b = i & 1;
        // transposed orientation: A-operand = W tile, B-operand = X tile
        const uint32_t Ab = smem_u32(sB[b]);
        const uint32_t Bb = smem_u32(sA[b]);
        #pragma unroll
        for (int kk = 0; kk < 2; kk++) {
            uint32_t a[2][4];
            #pragma unroll
            for (int t = 0; t < 2; t++) {
                uint32_t off = (uint32_t)((wm + t * 16 + lm16) * 80 + kk * 32 + lhi);
                LDMX4(a[t][0], a[t][1], a[t][2], a[t][3], Ab + off);
            }
            #pragma unroll
            for (int u2 = 0; u2 < 4; u2++) {
                uint32_t off = (uint32_t)((wn + u2 * 16 + bn) * 80 + kk * 32 + bk16);
                uint32_t r0_, r1_, r2_, r3_;
                LDMX4(r0_, r1_, r2_, r3_, Bb + off);
                uint32_t b0[2] = {r0_, r1_}, b1[2] = {r2_, r3_};
                #pragma unroll
                for (int t = 0; t < 2; t++) {
                    MMA16816(acc[t][2 * u2],     a[t], b0);
                    MMA16816(acc[t][2 * u2 + 1], a[t], b1);
                }
            }
        }
    }

    #pragma unroll
    for (int t = 0; t < 2; t++) {
        int dr = d0 + wm + t * 16 + (l >> 2);
        float bA = bias[dr], bB = bias[dr + 8];
        #pragma unroll
        for (int u = 0; u < 8; u++) {
            int nc = row0 + wn + u * 8 + (l & 3) * 2;
            __nv_bfloat162 pA = __floats2bfloat162_rn(acc[t][u][0] + bA, acc[t][u][1] + bA);
            __nv_bfloat162 pB = __floats2bfloat162_rn(acc[t][u][2] + bB, acc[t][u][3] + bB);
            *(__nv_bfloat162*)&g_valueT[(size_t)dr * NN + nc]       = pA;
            *(__nv_bfloat162*)&g_valueT[(size_t)(dr + 8) * NN + nc] = pB;
        }
    }
}

// =====================================================================
// K3: HMMA score kernel (unchanged from R4 — verified within 1/64 budget)
// =====================================================================
__device__ __forceinline__ void score_loadn(uint32_t nbase, int tid, int c) {
    #pragma unroll
    for (int q = 0; q < 2; q++) {
        int u  = tid * 2 + q;
        int rr = u >> 2, seg = u & 3;
        uint32_t dst = nbase + (uint32_t)(c % 3) * 10240u + (uint32_t)(rr * 80 + seg * 16);
        const char* src = (const char*)g_nattb + ((size_t)c * 128 + rr) * 64 + seg * 16;
        CP16(dst, src);
    }
}

__global__ __launch_bounds__(256)
void k_score_mma(const int* __restrict__ adj) {
    __shared__ __align__(16) char sN[3 * 128 * 80];
    __shared__ float s_rsum[2][64];
    const int tid = threadIdx.x, wid = tid >> 5, l = tid & 31;
    const int row0 = blockIdx.x * 64;
    const int wm = (wid >> 1) * 16;
    const int h  = wid & 1;
    const int wn = h * 64;
    const uint32_t nb = smem_u32(sN);

    uint32_t a[2][4];
    {
        const int r  = row0 + wm + (l >> 2);
        const int kq = (l & 3) * 2;
        const uint32_t* X = (const uint32_t*)g_xattb;
        #pragma unroll
        for (int kk = 0; kk < 2; kk++) {
            a[kk][0] = X[(size_t)r * 16       + (kk * 16 + kq) / 2];
            a[kk][1] = X[(size_t)(r + 8) * 16 + (kk * 16 + kq) / 2];
            a[kk][2] = X[(size_t)r * 16       + (kk * 16 + kq + 8) / 2];
            a[kk][3] = X[(size_t)(r + 8) * 16 + (kk * 16 + kq + 8) / 2];
        }
    }

    float rs0 = 0.f, rs1 = 0.f;
    const int bn = (l & 7) + ((l >> 4) << 3), bk16 = ((l >> 3) & 1) * 16;
    const int r0g = row0 + wm + (l >> 2);

    score_loadn(nb, tid, 0); CP_COMMIT();
    score_loadn(nb, tid, 1); CP_COMMIT();

    for (int i = 0; i < 64; i++) {
        CP_WAIT1();
        __syncthreads();
        if (i + 2 < 64) score_loadn(nb, tid, i + 2);
        CP_COMMIT();

        int2 adv[8][2];
        #pragma unroll
        for (int u = 0; u < 8; u++) {
            int cb = i * 128 + wn + u * 8 + (l & 3) * 2;
            adv[u][0] = *(const int2*)&adj[(size_t)r0g * NN + cb];
            adv[u][1] = *(const int2*)&adj[(size_t)(r0g + 8) * NN + cb];
        }

        float acc[8][4];
        #pragma unroll
        for (int u = 0; u < 8; u++)
            #pragma unroll
            for (int c = 0; c < 4; c++) acc[u][c] = 0.f;

        const uint32_t buf = nb + (uint32_t)(i % 3) * 10240u;
        #pragma unroll
        for (int kk = 0; kk < 2; kk++) {
            #pragma unroll
            for (int u2 = 0; u2 < 4; u2++) {
                uint32_t off = (uint32_t)((wn + u2 * 16 + bn) * 80 + kk * 32 + bk16);
                uint32_t r0_, r1_, r2_, r3_;
                LDMX4(r0_, r1_, r2_, r3_, buf + off);
                uint32_t b0[2] = {r0_, r1_}, b1[2] = {r2_, r3_};
                MMA16816(acc[2 * u2],     a[kk], b0);
                MMA16816(acc[2 * u2 + 1], a[kk], b1);
            }
        }

        #pragma unroll
        for (int u = 0; u < 8; u++) {
            int cb = i * 128 + wn + u * 8 + (l & 3) * 2;
            {
                float s0 = acc[u][0], s1 = acc[u][1];
                float w0 = s0 > 0.f ? s0 : 0.01f * s0;
                float w1 = s1 > 0.f ? s1 : 0.01f * s1;
                float e0 = adv[u][0].x > 0 ? __expf(w0) : 0.f;
                float e1 = adv[u][0].y > 0 ? __expf(w1) : 0.f;
                __nv_bfloat162 p = __floats2bfloat162_rn(e0, e1);
                rs0 += __low2float(p) + __high2float(p);
                *(__nv_bfloat162*)&g_E[(size_t)r0g * NN + cb] = p;
            }
            {
                float s0 = acc[u][2], s1 = acc[u][3];
                float w0 = s0 > 0.f ? s0 : 0.01f * s0;
                float w1 = s1 > 0.f ? s1 : 0.01f * s1;
                float e0 = adv[u][1].x > 0 ? __expf(w0) : 0.f;
                float e1 = adv[u][1].y > 0 ? __expf(w1) : 0.f;
                __nv_bfloat162 p = __floats2bfloat162_rn(e0, e1);
                rs1 += __low2float(p) + __high2float(p);
                *(__nv_bfloat162*)&g_E[(size_t)(r0g + 8) * NN + cb] = p;
            }
        }
    }

    rs0 += __shfl_xor_sync(0xffffffff, rs0, 1);
    rs0 += __shfl_xor_sync(0xffffffff, rs0, 2);
    rs1 += __shfl_xor_sync(0xffffffff, rs1, 1);
    rs1 += __shfl_xor_sync(0xffffffff, rs1, 2);
    if ((l & 3) == 0) {
        s_rsum[h][wm + (l >> 2)]     = rs0;
        s_rsum[h][wm + (l >> 2) + 8] = rs1;
    }
    __syncthreads();
    if (tid < 64) g_rowsum[row0 + tid] = s_rsum[0][tid] + s_rsum[1][tid];
}

// =====================================================================
// K4: HMMA PV GEMM: agg = softmax_norm(E @ V)
// =====================================================================
#define PV_BK     64
#define PV_NCH    (NN / PV_BK)
#define PV_STAGEB 32768
#define PV_SMEM   (4 * PV_STAGEB + 1024)

__device__ __forceinline__ void pv_load(uint32_t tile, int tid, int row0, int n0, int c) {
    const size_t kb = (size_t)c * (PV_BK * 2);
    const uint32_t eb = tile + (uint32_t)(c & 3) * PV_STAGEB;
    const uint32_t vb = eb + 16384u;
    #pragma unroll
    for (int p = 0; p < 4; p++) {
        int u = p * 256 + tid;
        int row = u >> 3, j = u & 7;
        uint32_t soff = SW128((uint32_t)(row * 128 + j * 16));
        const char* gE = (const char*)g_E +
            ((size_t)(row0 + row) * NN) * 2 + kb + (size_t)(j * 16);
        CP16(eb + soff, gE);
        const char* gV = (const char*)g_valueT +
            ((size_t)(n0 + row) * NN) * 2 + kb + (size_t)(j * 16);
        CP16(vb + soff, gV);
    }
}

__global__ __launch_bounds__(256)
void k_pv_mma(float* __restrict__ out) {
    extern __shared__ __align__(16) char dynsmem[];
    const int tid = threadIdx.x;
    const int wid = tid >> 5;
    const int l   = tid & 31;
    const int row0 = (int)(blockIdx.x >> 1) * 128;
    const int n0   = (int)(blockIdx.x & 1) * 128;
    const int wm0  = (wid >> 1) * 32;
    const int wn0  = (wid & 1) * 64;

    const uint32_t dynb = smem_u32(dynsmem);
    const uint32_t tile = (dynb + 1023u) & ~1023u;

    float acc[2][8][4];
    #pragma unroll
    for (int t = 0; t < 2; t++)
        #pragma unroll
        for (int u = 0; u < 8; u++)
            #pragma unroll
            for (int c = 0; c < 4; c++) acc[t][u][c] = 0.f;

    pv_load(tile, tid, row0, n0, 0); CP_COMMIT();
    pv_load(tile, tid, row0, n0, 1); CP_COMMIT();
    pv_load(tile, tid, row0, n0, 2); CP_COMMIT();

    const int lm16 = l & 15;
    const int lhi  = (l >> 4) * 16;
    const int bn   = (l & 7) + ((l >> 4) << 3);
    const int bk16 = ((l >> 3) & 1) * 16;

    for (int i = 0; i < PV_NCH; i++) {
        CP_WAIT2();
        __syncthreads();
        const uint32_t eb = tile + (uint32_t)(i & 3) * PV_STAGEB;
        const uint32_t vb = eb + 16384u;
        #pragma unroll
        for (int kk = 0; kk < 4; kk++) {
            uint32_t a[2][4];
            #pragma unroll
            for (int t = 0; t < 2; t++) {
                uint32_t off = (uint32_t)((wm0 + t * 16 + lm16) * 128 + kk * 32 + lhi);
                LDMX4(a[t][0], a[t][1], a[t][2], a[t][3], eb + SW128(off));
            }
            uint32_t b[8][2];
            #pragma unroll
            for (int u2 = 0; u2 < 4; u2++) {
                uint32_t off = (uint32_t)((wn0 + u2 * 16 + bn) * 128 + kk * 32 + bk16);
                uint32_t r0, r1, r2, r3;
                LDMX4(r0, r1, r2, r3, vb + SW128(off));
                b[2 * u2][0] = r0;     b[2 * u2][1] = r1;
                b[2 * u2 + 1][0] = r2; b[2 * u2 + 1][1] = r3;
            }
            #pragma unroll
            for (int t = 0; t < 2; t++)
                #pragma unroll
                for (int u = 0; u < 8; u++)
                    MMA16816(acc[t][u], a[t], b[u]);
        }
        const int j = i + 3;
        if (j < PV_NCH) pv_load(tile, tid, row0, n0, j);
        CP_COMMIT();
    }

    #pragma unroll
    for (int t = 0; t < 2; t++) {
        int ra = row0 + wm0 + t * 16 + (l >> 2);
        int rb = ra + 8;
        float inva = 1.0f / g_rowsum[ra];
        float invb = 1.0f / g_rowsum[rb];
        #pragma unroll
        for (int u = 0; u < 8; u++) {
            int col = DOUT + n0 + wn0 + u * 8 + (l & 3) * 2;
            float2 v0 = {acc[t][u][0] * inva, acc[t][u][1] * inva};
            float2 v1 = {acc[t][u][2] * invb, acc[t][u][3] * invb};
            *(float2*)&out[(size_t)ra * (2 * DOUT) + col] = v0;
            *(float2*)&out[(size_t)rb * (2 * DOUT) + col] = v1;
        }
    }
}

// =====================================================================
// launch
// =====================================================================
extern "C" void kernel_launch(void* const* d_in, const int* in_sizes, int n_in,
                              void* d_out, int out_size) {
    const float* x    = (const float*)d_in[0];
    const float* neigh= (const float*)d_in[1];
    const int*   adj  = (const int*)  d_in[2];
    const float* Wx1  = (const float*)d_in[3];
    const float* bx1  = (const float*)d_in[4];
    const float* Wx2  = (const float*)d_in[5];
    const float* bx2  = (const float*)d_in[6];
    const float* Wn1  = (const float*)d_in[7];
    const float* bn1  = (const float*)d_in[8];
    const float* Wn2  = (const float*)d_in[9];
    const float* bn2  = (const float*)d_in[10];
    const float* Wv   = (const float*)d_in[11];
    const float* bv   = (const float*)d_in[12];
    const float* Wfx  = (const float*)d_in[13];
    const float* bfx  = (const float*)d_in[14];
    float* out = (float*)d_out;

    __nv_bfloat16* xattb;
    __nv_bfloat16* nattb;
    cudaGetSymbolAddress((void**)&xattb, g_xattb);
    cudaGetSymbolAddress((void**)&nattb, g_nattb);

    cudaFuncSetAttribute(k_pv_mma, cudaFuncAttributeMaxDynamicSharedMemorySize, PV_SMEM);

    // fused attention MLPs -> bf16 att
    k_mlp<<<NX / 128, 256>>>(neigh, Wn1, bn1, Wn2, bn2, nattb);
    k_mlp<<<NX / 128, 256>>>(x, Wx1, bx1, Wx2, bx2, xattb);
    // value (HMMA, transposed -> g_valueT); fc_x in full fp32 (norm-dominant half)
    k_value_mma<<<128, 256>>>(neigh, Wv, bv);
    k_gemm_f32<<<NX / 64, 256>>>(x, Wfx, bfx, out);
    // HMMA scores + masked exp + rowsums
    k_score_mma<<<NX / 64, 256>>>(adj);
    // HMMA PV with softmax normalization
    k_pv_mma<<<(NX / 128) * 2, 256, PV_SMEM>>>(out);
}

// round 6
// speedup vs baseline: 3.9036x; 1.2997x over previous
#include <cuda_runtime.h>
#include <cuda_bf16.h>
#include <cstdint>

#define NX   8192
#define NN   8192
#define DIN  512
#define DH   32
#define DOUT 256

// ---------------- scratch (static __device__: allocation-free) ----------------
__device__ __nv_bfloat16 g_xattb[NX * DH];              // bf16 att (x)
__device__ __nv_bfloat16 g_nattb[NN * DH];              // bf16 att (neigh)
__device__ __nv_bfloat16 g_valueT[(size_t)DOUT * NN];   // 4 MB, [d][n] bf16
__device__ __nv_bfloat16 g_E[(size_t)NX * NN];          // 128 MB masked exp'd scores
__device__ float g_rowsum[NX];

// ---------------- f32x2 packed helpers ----------------
__device__ __forceinline__ unsigned long long pack2(float a, float b) {
    unsigned long long r;
    asm("mov.b64 %0, {%1, %2};" : "=l"(r) : "f"(a), "f"(b));
    return r;
}
__device__ __forceinline__ void fma2(unsigned long long &d, unsigned long long a,
                                     unsigned long long b) {
    asm("fma.rn.f32x2 %0, %1, %2, %0;" : "+l"(d) : "l"(a), "l"(b));
}
__device__ __forceinline__ float2 unpack2(unsigned long long v) {
    float2 r;
    asm("mov.b64 {%0, %1}, %2;" : "=f"(r.x), "=f"(r.y) : "l"(v));
    return r;
}

// ---------------- portable helpers ----------------
__device__ __forceinline__ uint32_t smem_u32(const void* p) {
    uint32_t a;
    asm("{ .reg .u64 t; cvta.to.shared.u64 t, %1; cvt.u32.u64 %0, t; }" : "=r"(a) : "l"(p));
    return a;
}
#define CP16(dst, src) \
    asm volatile("cp.async.cg.shared.global [%0], [%1], 16;" :: "r"(dst), "l"(src))
#define CP_COMMIT() asm volatile("cp.async.commit_group;" ::: "memory")
#define CP_WAIT1()  asm volatile("cp.async.wait_group 1;" ::: "memory")
#define CP_WAIT2()  asm volatile("cp.async.wait_group 2;" ::: "memory")

#define SW128(off) ((off) ^ (((off) >> 3) & 0x70))

#define LDMX4(r0, r1, r2, r3, addr) \
    asm volatile("ldmatrix.sync.aligned.m8n8.x4.shared.b16 {%0,%1,%2,%3}, [%4];" \
                 : "=r"(r0), "=r"(r1), "=r"(r2), "=r"(r3) : "r"(addr))

#define MMA16816(c, a, b) \
    asm volatile("mma.sync.aligned.m16n8k16.row.col.f32.bf16.bf16.f32 " \
                 "{%0,%1,%2,%3}, {%4,%5,%6,%7}, {%8,%9}, {%0,%1,%2,%3};" \
                 : "+f"((c)[0]), "+f"((c)[1]), "+f"((c)[2]), "+f"((c)[3]) \
                 : "r"((a)[0]), "r"((a)[1]), "r"((a)[2]), "r"((a)[3]), \
                   "r"((b)[0]), "r"((b)[1]))

// =====================================================================
// K1: fused MLP: att = tanh(A @ W1 + b1) @ W2 + b2 -> bf16
// =====================================================================
__global__ __launch_bounds__(256)
void k_mlp(const float* __restrict__ A, const float* __restrict__ W1,
           const float* __restrict__ b1, const float* __restrict__ W2,
           const float* __restrict__ b2, __nv_bfloat16* __restrict__ att) {
    __shared__ float As[32][132];
    __shared__ float Ws[32][32];
    __shared__ float W2s[32][33];
    __shared__ float Hs[128][36];
    const int tid  = threadIdx.x;
    const int row0 = blockIdx.x * 128;
    const int ty = tid / 8, tx = tid % 8;
    float acc[4][4] = {};

    #pragma unroll
    for (int p = 0; p < 4; p++) {
        int i = p * 256 + tid;
        W2s[i >> 5][i & 31] = W2[i];
    }

    for (int k0 = 0; k0 < DIN; k0 += 32) {
        #pragma unroll
        for (int p = 0; p < 4; p++) {
            int r  = p * 32 + tid / 8;
            int kq = (tid % 8) * 4;
            float4 v = *(const float4*)&A[(size_t)(row0 + r) * DIN + k0 + kq];
            As[kq + 0][r] = v.x; As[kq + 1][r] = v.y;
            As[kq + 2][r] = v.z; As[kq + 3][r] = v.w;
        }
        {
            int k = tid / 8, c4 = (tid % 8) * 4;
            *(float4*)&Ws[k][c4] = *(const float4*)&W1[(size_t)(k0 + k) * DH + c4];
        }
        __syncthreads();
        #pragma unroll
        for (int k = 0; k < 32; k++) {
            float4 a = *(const float4*)&As[k][ty * 4];
            float4 w = *(const float4*)&Ws[k][tx * 4];
            float av[4] = {a.x, a.y, a.z, a.w};
            float wv[4] = {w.x, w.y, w.z, w.w};
            #pragma unroll
            for (int r = 0; r < 4; r++)
                #pragma unroll
                for (int c = 0; c < 4; c++)
                    acc[r][c] += av[r] * wv[c];
        }
        __syncthreads();
    }
    #pragma unroll
    for (int r = 0; r < 4; r++)
        #pragma unroll
        for (int c = 0; c < 4; c++)
            Hs[ty * 4 + r][tx * 4 + c] = tanhf(acc[r][c] + b1[tx * 4 + c]);
    __syncthreads();

    {
        const int row = tid >> 1;
        const int cb  = (tid & 1) * 16;
        float s[16];
        #pragma unroll
        for (int j = 0; j < 16; j++) s[j] = b2[cb + j];
        #pragma unroll
        for (int k = 0; k < 32; k++) {
            float hv = Hs[row][k];
            #pragma unroll
            for (int j = 0; j < 16; j++) s[j] += hv * W2s[k][cb + j];
        }
        uint32_t ob[8];
        #pragma unroll
        for (int j2 = 0; j2 < 8; j2++) {
            __nv_bfloat162 p = __floats2bfloat162_rn(s[2 * j2], s[2 * j2 + 1]);
            ob[j2] = reinterpret_cast<uint32_t&>(p);
        }
        uint4 u0 = {ob[0], ob[1], ob[2], ob[3]};
        uint4 u1 = {ob[4], ob[5], ob[6], ob[7]};
        *(uint4*)&att[(size_t)(row0 + row) * DH + cb]     = u0;
        *(uint4*)&att[(size_t)(row0 + row) * DH + cb + 8] = u1;
    }
}

// =====================================================================
// K2a: fc_x in full fp32 (f32x2), 512 threads, thread tile 4x8.
// =====================================================================
__global__ __launch_bounds__(512)
void k_gemm_f32(const float* __restrict__ A, const float* __restrict__ W,
                const float* __restrict__ b, float* __restrict__ Cout) {
    __shared__ float As[32][68];
    __shared__ float Ws[32][256];
    const int tid  = threadIdx.x;
    const int row0 = blockIdx.x * 64;
    const int ty = tid >> 5;          // 0..15 -> rows ty*4
    const int tx = tid & 31;          // cols tx*8
    unsigned long long acc[4][4];
    #pragma unroll
    for (int r = 0; r < 4; r++)
        #pragma unroll
        for (int c = 0; c < 4; c++) acc[r][c] = 0ULL;

    for (int k0 = 0; k0 < DIN; k0 += 32) {
        {
            int r  = tid >> 3;              // 0..63
            int kq = (tid & 7) * 4;
            float4 v = *(const float4*)&A[(size_t)(row0 + r) * DIN + k0 + kq];
            As[kq + 0][r] = v.x; As[kq + 1][r] = v.y;
            As[kq + 2][r] = v.z; As[kq + 3][r] = v.w;
        }
        #pragma unroll
        for (int p = 0; p < 4; p++) {
            int i = p * 512 + tid;
            int k = i / 64, c4 = (i % 64) * 4;
            *(float4*)&Ws[k][c4] = *(const float4*)&W[(size_t)(k0 + k) * DOUT + c4];
        }
        __syncthreads();
        #pragma unroll 8
        for (int k = 0; k < 32; k++) {
            float4 a0 = *(const float4*)&As[k][ty * 4];
            ulonglong2 vA = *(const ulonglong2*)&Ws[k][tx * 8];
            ulonglong2 vB = *(const ulonglong2*)&Ws[k][tx * 8 + 4];
            float av[4] = {a0.x, a0.y, a0.z, a0.w};
            unsigned long long vv[4] = {vA.x, vA.y, vB.x, vB.y};
            #pragma unroll
            for (int r = 0; r < 4; r++) {
                unsigned long long ar = pack2(av[r], av[r]);
                #pragma unroll
                for (int c = 0; c < 4; c++) fma2(acc[r][c], ar, vv[c]);
            }
        }
        __syncthreads();
    }
    #pragma unroll
    for (int r = 0; r < 4; r++) {
        int row = row0 + ty * 4 + r;
        float o[8];
        #pragma unroll
        for (int c4 = 0; c4 < 4; c4++) {
            float2 u = unpack2(acc[r][c4]);
            o[2 * c4]     = u.x + b[tx * 8 + 2 * c4];
            o[2 * c4 + 1] = u.y + b[tx * 8 + 2 * c4 + 1];
        }
        float4 s0 = {o[0], o[1], o[2], o[3]};
        float4 s1 = {o[4], o[5], o[6], o[7]};
        size_t off = (size_t)row * (2 * DOUT) + tx * 8;
        *(float4*)&Cout[off]     = s0;
        *(float4*)&Cout[off + 4] = s1;
    }
}

// =====================================================================
// K2b: value GEMM on HMMA, transposed output into g_valueT[d][n] bf16.
// =====================================================================
__device__ __forceinline__ void gemm_ldg(const float* __restrict__ X,
                                         const float* __restrict__ W,
                                         int row0, int d0, int kc, int tid,
                                         float4 xv[4], float wv[16]) {
    #pragma unroll
    for (int p = 0; p < 4; p++)
        xv[p] = *(const float4*)&X[(size_t)(row0 + p * 32 + (tid >> 3)) * DIN
                                   + kc * 32 + (tid & 7) * 4];
    const int wd = tid & 127, wkh = tid >> 7;
    #pragma unroll
    for (int k2 = 0; k2 < 16; k2++)
        wv[k2] = W[(size_t)(kc * 32 + wkh * 16 + k2) * DOUT + d0 + wd];
}
__device__ __forceinline__ void gemm_sts(char* sA, char* sB, int tid,
                                         const float4 xv[4], const float wv[16]) {
    #pragma unroll
    for (int p = 0; p < 4; p++) {
        __nv_bfloat162 b0 = __floats2bfloat162_rn(xv[p].x, xv[p].y);
        __nv_bfloat162 b1 = __floats2bfloat162_rn(xv[p].z, xv[p].w);
        uint2 u;
        u.x = reinterpret_cast<const uint32_t&>(b0);
        u.y = reinterpret_cast<const uint32_t&>(b1);
        *(uint2*)&sA[(p * 32 + (tid >> 3)) * 80 + (tid & 7) * 8] = u;
    }
    const int wd = tid & 127, wkh = tid >> 7;
    #pragma unroll
    for (int j = 0; j < 8; j++) {
        __nv_bfloat162 bb = __floats2bfloat162_rn(wv[2 * j], wv[2 * j + 1]);
        *(uint32_t*)&sB[wd * 80 + wkh * 32 + j * 4] = reinterpret_cast<const uint32_t&>(bb);
    }
}

__global__ __launch_bounds__(256)
void k_value_mma(const float* __restrict__ X, const float* __restrict__ W,
                 const float* __restrict__ bias) {
    __shared__ __align__(16) char sA[2][128 * 80];
    __shared__ __align__(16) char sB[2][128 * 80];
    const int tid = threadIdx.x, wid = tid >> 5, l = tid & 31;
    const int row0 = (int)(blockIdx.x >> 1) * 128;
    const int d0   = (int)(blockIdx.x & 1) * 128;
    const int wm = (wid >> 1) * 32, wn = (wid & 1) * 64;

    float acc[2][8][4];
    #pragma unroll
    for (int t = 0; t < 2; t++)
        #pragma unroll
        for (int u = 0; u < 8; u++)
            #pragma unroll
            for (int c = 0; c < 4; c++) acc[t][u][c] = 0.f;

    float4 xv[4]; float wv[16];
    gemm_ldg(X, W, row0, d0, 0, tid, xv, wv);
    gemm_sts(sA[0], sB[0], tid, xv, wv);
    gemm_ldg(X, W, row0, d0, 1, tid, xv, wv);

    const int lm16 = l & 15, lhi = (l >> 4) * 16;
    const int bn = (l & 7) + ((l >> 4) << 3), bk16 = ((l >> 3) & 1) * 16;

    for (int i = 0; i < 16; i++) {
        __syncthreads();
        if (i + 1 < 16) gemm_sts(sA[(i + 1) & 1], sB[(i + 1) & 1], tid, xv, wv);
        if (i + 2 < 16) gemm_ldg(X, W, row0, d0, i + 2, tid, xv, wv);

        const int b = i & 1;
        const uint32_t Ab = smem_u32(sB[b]);   // transposed: A = W tile
        const uint32_t Bb = smem_u32(sA[b]);
        #pragma unroll
        for (int kk = 0; kk < 2; kk++) {
            uint32_t a[2][4];
            #pragma unroll
            for (int t = 0; t < 2; t++) {
                uint32_t off = (uint32_t)((wm + t * 16 + lm16) * 80 + kk * 32 + lhi);
                LDMX4(a[t][0], a[t][1], a[t][2], a[t][3], Ab + off);
            }
            #pragma unroll
            for (int u2 = 0; u2 < 4; u2++) {
                uint32_t off = (uint32_t)((wn + u2 * 16 + bn) * 80 + kk * 32 + bk16);
                uint32_t r0_, r1_, r2_, r3_;
                LDMX4(r0_, r1_, r2_, r3_, Bb + off);
                uint32_t b0[2] = {r0_, r1_}, b1[2] = {r2_, r3_};
                #pragma unroll
                for (int t = 0; t < 2; t++) {
                    MMA16816(acc[t][2 * u2],     a[t], b0);
                    MMA16816(acc[t][2 * u2 + 1], a[t], b1);
                }
            }
        }
    }

    #pragma unroll
    for (int t = 0; t < 2; t++) {
        int dr = d0 + wm + t * 16 + (l >> 2);
        float bA = bias[dr], bB = bias[dr + 8];
        #pragma unroll
        for (int u = 0; u < 8; u++) {
            int nc = row0 + wn + u * 8 + (l & 3) * 2;
            __nv_bfloat162 pA = __floats2bfloat162_rn(acc[t][u][0] + bA, acc[t][u][1] + bA);
            __nv_bfloat162 pB = __floats2bfloat162_rn(acc[t][u][2] + bB, acc[t][u][3] + bB);
            *(__nv_bfloat162*)&g_valueT[(size_t)dr * NN + nc]       = pA;
            *(__nv_bfloat162*)&g_valueT[(size_t)(dr + 8) * NN + nc] = pB;
        }
    }
}

// =====================================================================
// K3: HMMA score kernel — 512 threads, warps 4(m)x4(n) on 64x128 chunks.
// =====================================================================
__device__ __forceinline__ void score_loadn(uint32_t nbase, int tid, int c) {
    int rr = tid >> 2, seg = tid & 3;         // 512 threads = 128 rows x 4 segs
    uint32_t dst = nbase + (uint32_t)(c % 3) * 10240u + (uint32_t)(rr * 80 + seg * 16);
    const char* src = (const char*)g_nattb + ((size_t)c * 128 + rr) * 64 + seg * 16;
    CP16(dst, src);
}

__global__ __launch_bounds__(512)
void k_score_mma(const int* __restrict__ adj) {
    __shared__ __align__(16) char sN[3 * 128 * 80];
    __shared__ float s_rsum[4][64];
    const int tid = threadIdx.x, wid = tid >> 5, l = tid & 31;
    const int row0 = blockIdx.x * 64;
    const int wm = (wid >> 2) * 16;           // 4 m-groups
    const int h  = wid & 3;                   // 4 n-groups
    const int wn = h * 32;
    const uint32_t nb = smem_u32(sN);

    uint32_t a[2][4];
    {
        const int r  = row0 + wm + (l >> 2);
        const int kq = (l & 3) * 2;
        const uint32_t* X = (const uint32_t*)g_xattb;
        #pragma unroll
        for (int kk = 0; kk < 2; kk++) {
            a[kk][0] = X[(size_t)r * 16       + (kk * 16 + kq) / 2];
            a[kk][1] = X[(size_t)(r + 8) * 16 + (kk * 16 + kq) / 2];
            a[kk][2] = X[(size_t)r * 16       + (kk * 16 + kq + 8) / 2];
            a[kk][3] = X[(size_t)(r + 8) * 16 + (kk * 16 + kq + 8) / 2];
        }
    }

    float rs0 = 0.f, rs1 = 0.f;
    const int bn = (l & 7) + ((l >> 4) << 3), bk16 = ((l >> 3) & 1) * 16;
    const int r0g = row0 + wm + (l >> 2);

    score_loadn(nb, tid, 0); CP_COMMIT();
    score_loadn(nb, tid, 1); CP_COMMIT();

    for (int i = 0; i < 64; i++) {
        CP_WAIT1();
        __syncthreads();
        if (i + 2 < 64) score_loadn(nb, tid, i + 2);
        CP_COMMIT();

        int2 adv[4][2];
        #pragma unroll
        for (int u = 0; u < 4; u++) {
            int cb = i * 128 + wn + u * 8 + (l & 3) * 2;
            adv[u][0] = *(const int2*)&adj[(size_t)r0g * NN + cb];
            adv[u][1] = *(const int2*)&adj[(size_t)(r0g + 8) * NN + cb];
        }

        float acc[4][4];
        #pragma unroll
        for (int u = 0; u < 4; u++)
            #pragma unroll
            for (int c = 0; c < 4; c++) acc[u][c] = 0.f;

        const uint32_t buf = nb + (uint32_t)(i % 3) * 10240u;
        #pragma unroll
        for (int kk = 0; kk < 2; kk++) {
            #pragma unroll
            for (int u2 = 0; u2 < 2; u2++) {
                uint32_t off = (uint32_t)((wn + u2 * 16 + bn) * 80 + kk * 32 + bk16);
                uint32_t r0_, r1_, r2_, r3_;
                LDMX4(r0_, r1_, r2_, r3_, buf + off);
                uint32_t b0[2] = {r0_, r1_}, b1[2] = {r2_, r3_};
                MMA16816(acc[2 * u2],     a[kk], b0);
                MMA16816(acc[2 * u2 + 1], a[kk], b1);
            }
        }

        #pragma unroll
        for (int u = 0; u < 4; u++) {
            int cb = i * 128 + wn + u * 8 + (l & 3) * 2;
            {
                float s0 = acc[u][0], s1 = acc[u][1];
                float w0 = s0 > 0.f ? s0 : 0.01f * s0;
                float w1 = s1 > 0.f ? s1 : 0.01f * s1;
                float e0 = adv[u][0].x > 0 ? __expf(w0) : 0.f;
                float e1 = adv[u][0].y > 0 ? __expf(w1) : 0.f;
                __nv_bfloat162 p = __floats2bfloat162_rn(e0, e1);
                rs0 += e0 + e1;
                *(__nv_bfloat162*)&g_E[(size_t)r0g * NN + cb] = p;
            }
            {
                float s0 = acc[u][2], s1 = acc[u][3];
                float w0 = s0 > 0.f ? s0 : 0.01f * s0;
                float w1 = s1 > 0.f ? s1 : 0.01f * s1;
                float e0 = adv[u][1].x > 0 ? __expf(w0) : 0.f;
                float e1 = adv[u][1].y > 0 ? __expf(w1) : 0.f;
                __nv_bfloat162 p = __floats2bfloat162_rn(e0, e1);
                rs1 += e0 + e1;
                *(__nv_bfloat162*)&g_E[(size_t)(r0g + 8) * NN + cb] = p;
            }
        }
    }

    rs0 += __shfl_xor_sync(0xffffffff, rs0, 1);
    rs0 += __shfl_xor_sync(0xffffffff, rs0, 2);
    rs1 += __shfl_xor_sync(0xffffffff, rs1, 1);
    rs1 += __shfl_xor_sync(0xffffffff, rs1, 2);
    if ((l & 3) == 0) {
        s_rsum[h][wm + (l >> 2)]     = rs0;
        s_rsum[h][wm + (l >> 2) + 8] = rs1;
    }
    __syncthreads();
    if (tid < 64)
        g_rowsum[row0 + tid] = (s_rsum[0][tid] + s_rsum[1][tid]) +
                               (s_rsum[2][tid] + s_rsum[3][tid]);
}

// =====================================================================
// K4: HMMA PV GEMM — 512 threads, warps 4x4, warp tile 32x32.
// =====================================================================
#define PV_BK     64
#define PV_NCH    (NN / PV_BK)
#define PV_STAGEB 32768
#define PV_SMEM   (4 * PV_STAGEB + 1024)

__device__ __forceinline__ void pv_load(uint32_t tile, int tid, int row0, int n0, int c) {
    const size_t kb = (size_t)c * (PV_BK * 2);
    const uint32_t eb = tile + (uint32_t)(c & 3) * PV_STAGEB;
    const uint32_t vb = eb + 16384u;
    #pragma unroll
    for (int p = 0; p < 2; p++) {
        int u = p * 512 + tid;           // 0..1023
        int row = u >> 3, j = u & 7;
        uint32_t soff = SW128((uint32_t)(row * 128 + j * 16));
        const char* gE = (const char*)g_E +
            ((size_t)(row0 + row) * NN) * 2 + kb + (size_t)(j * 16);
        CP16(eb + soff, gE);
        const char* gV = (const char*)g_valueT +
            ((size_t)(n0 + row) * NN) * 2 + kb + (size_t)(j * 16);
        CP16(vb + soff, gV);
    }
}

__global__ __launch_bounds__(512)
void k_pv_mma(float* __restrict__ out) {
    extern __shared__ __align__(16) char dynsmem[];
    const int tid = threadIdx.x;
    const int wid = tid >> 5;
    const int l   = tid & 31;
    const int row0 = (int)(blockIdx.x >> 1) * 128;
    const int n0   = (int)(blockIdx.x & 1) * 128;
    const int wm0  = (wid >> 2) * 32;    // 4 m-groups
    const int wn0  = (wid & 3) * 32;     // 4 n-groups

    const uint32_t dynb = smem_u32(dynsmem);
    const uint32_t tile = (dynb + 1023u) & ~1023u;

    float acc[2][4][4];
    #pragma unroll
    for (int t = 0; t < 2; t++)
        #pragma unroll
        for (int u = 0; u < 4; u++)
            #pragma unroll
            for (int c = 0; c < 4; c++) acc[t][u][c] = 0.f;

    pv_load(tile, tid, row0, n0, 0); CP_COMMIT();
    pv_load(tile, tid, row0, n0, 1); CP_COMMIT();
    pv_load(tile, tid, row0, n0, 2); CP_COMMIT();

    const int lm16 = l & 15;
    const int lhi  = (l >> 4) * 16;
    const int bn   = (l & 7) + ((l >> 4) << 3);
    const int bk16 = ((l >> 3) & 1) * 16;

    for (int i = 0; i < PV_NCH; i++) {
        CP_WAIT2();
        __syncthreads();
        const uint32_t eb = tile + (uint32_t)(i & 3) * PV_STAGEB;
        const uint32_t vb = eb + 16384u;
        #pragma unroll
        for (int kk = 0; kk < 4; kk++) {
            uint32_t a[2][4];
            #pragma unroll
            for (int t = 0; t < 2; t++) {
                uint32_t off = (uint32_t)((wm0 + t * 16 + lm16) * 128 + kk * 32 + lhi);
                LDMX4(a[t][0], a[t][1], a[t][2], a[t][3], eb + SW128(off));
            }
            uint32_t b[4][2];
            #pragma unroll
            for (int u2 = 0; u2 < 2; u2++) {
                uint32_t off = (uint32_t)((wn0 + u2 * 16 + bn) * 128 + kk * 32 + bk16);
                uint32_t r0, r1, r2, r3;
                LDMX4(r0, r1, r2, r3, vb + SW128(off));
                b[2 * u2][0] = r0;     b[2 * u2][1] = r1;
                b[2 * u2 + 1][0] = r2; b[2 * u2 + 1][1] = r3;
            }
            #pragma unroll
            for (int t = 0; t < 2; t++)
                #pragma unroll
                for (int u = 0; u < 4; u++)
                    MMA16816(acc[t][u], a[t], b[u]);
        }
        const int j = i + 3;
        if (j < PV_NCH) pv_load(tile, tid, row0, n0, j);
        CP_COMMIT();
    }

    #pragma unroll
    for (int t = 0; t < 2; t++) {
        int ra = row0 + wm0 + t * 16 + (l >> 2);
        int rb = ra + 8;
        float inva = 1.0f / g_rowsum[ra];
        float invb = 1.0f / g_rowsum[rb];
        #pragma unroll
        for (int u = 0; u < 4; u++) {
            int col = DOUT + n0 + wn0 + u * 8 + (l & 3) * 2;
            float2 v0 = {acc[t][u][0] * inva, acc[t][u][1] * inva};
            float2 v1 = {acc[t][u][2] * invb, acc[t][u][3] * invb};
            *(float2*)&out[(size_t)ra * (2 * DOUT) + col] = v0;
            *(float2*)&out[(size_t)rb * (2 * DOUT) + col] = v1;
        }
    }
}

// =====================================================================
// launch
// =====================================================================
extern "C" void kernel_launch(void* const* d_in, const int* in_sizes, int n_in,
                              void* d_out, int out_size) {
    const float* x    = (const float*)d_in[0];
    const float* neigh= (const float*)d_in[1];
    const int*   adj  = (const int*)  d_in[2];
    const float* Wx1  = (const float*)d_in[3];
    const float* bx1  = (const float*)d_in[4];
    const float* Wx2  = (const float*)d_in[5];
    const float* bx2  = (const float*)d_in[6];
    const float* Wn1  = (const float*)d_in[7];
    const float* bn1  = (const float*)d_in[8];
    const float* Wn2  = (const float*)d_in[9];
    const float* bn2  = (const float*)d_in[10];
    const float* Wv   = (const float*)d_in[11];
    const float* bv   = (const float*)d_in[12];
    const float* Wfx  = (const float*)d_in[13];
    const float* bfx  = (const float*)d_in[14];
    float* out = (float*)d_out;

    __nv_bfloat16* xattb;
    __nv_bfloat16* nattb;
    cudaGetSymbolAddress((void**)&xattb, g_xattb);
    cudaGetSymbolAddress((void**)&nattb, g_nattb);

    cudaFuncSetAttribute(k_pv_mma, cudaFuncAttributeMaxDynamicSharedMemorySize, PV_SMEM);

    // fused attention MLPs -> bf16 att
    k_mlp<<<NX / 128, 256>>>(neigh, Wn1, bn1, Wn2, bn2, nattb);
    k_mlp<<<NX / 128, 256>>>(x, Wx1, bx1, Wx2, bx2, xattb);
    // value (HMMA, transposed -> g_valueT); fc_x in full fp32
    k_value_mma<<<128, 256>>>(neigh, Wv, bv);
    k_gemm_f32<<<NX / 64, 512>>>(x, Wfx, bfx, out);
    // HMMA scores + masked exp + rowsums
    k_score_mma<<<NX / 64, 512>>>(adj);
    // HMMA PV with softmax normalization
    k_pv_mma<<<(NX / 128) * 2, 512, PV_SMEM>>>(out);
}

// round 7
// speedup vs baseline: 4.8648x; 1.2463x over previous
#include <cuda_runtime.h>
#include <cuda_bf16.h>
#include <cstdint>

#define NX   8192
#define NN   8192
#define DIN  512
#define DH   32
#define DOUT 256

// ---------------- scratch (static __device__: allocation-free) ----------------
__device__ __nv_bfloat16 g_xattb[NX * DH];              // bf16 att (x)
__device__ __nv_bfloat16 g_nattb[NN * DH];              // bf16 att (neigh)
__device__ __nv_bfloat16 g_valueT[(size_t)DOUT * NN];   // 4 MB, [d][n] bf16
__device__ __nv_bfloat16 g_E[(size_t)NX * NN];          // 128 MB masked exp'd scores
__device__ float g_rowsum[NX];

// ---------------- portable helpers ----------------
__device__ __forceinline__ uint32_t smem_u32(const void* p) {
    uint32_t a;
    asm("{ .reg .u64 t; cvta.to.shared.u64 t, %1; cvt.u32.u64 %0, t; }" : "=r"(a) : "l"(p));
    return a;
}
#define CP16(dst, src) \
    asm volatile("cp.async.cg.shared.global [%0], [%1], 16;" :: "r"(dst), "l"(src))
#define CP_COMMIT() asm volatile("cp.async.commit_group;" ::: "memory")
#define CP_WAIT1()  asm volatile("cp.async.wait_group 1;" ::: "memory")
#define CP_WAIT2()  asm volatile("cp.async.wait_group 2;" ::: "memory")

#define SW128(off) ((off) ^ (((off) >> 3) & 0x70))

#define LDMX4(r0, r1, r2, r3, addr) \
    asm volatile("ldmatrix.sync.aligned.m8n8.x4.shared.b16 {%0,%1,%2,%3}, [%4];" \
                 : "=r"(r0), "=r"(r1), "=r"(r2), "=r"(r3) : "r"(addr))
#define LDMX2(r0, r1, addr) \
    asm volatile("ldmatrix.sync.aligned.m8n8.x2.shared.b16 {%0,%1}, [%2];" \
                 : "=r"(r0), "=r"(r1) : "r"(addr))

#define MMA16816(c, a, b) \
    asm volatile("mma.sync.aligned.m16n8k16.row.col.f32.bf16.bf16.f32 " \
                 "{%0,%1,%2,%3}, {%4,%5,%6,%7}, {%8,%9}, {%0,%1,%2,%3};" \
                 : "+f"((c)[0]), "+f"((c)[1]), "+f"((c)[2]), "+f"((c)[3]) \
                 : "r"((a)[0]), "r"((a)[1]), "r"((a)[2]), "r"((a)[3]), \
                   "r"((b)[0]), "r"((b)[1]))

__device__ __forceinline__ uint32_t bf2_hi(float a, float b) {
    __nv_bfloat162 p = __floats2bfloat162_rn(a, b);
    return reinterpret_cast<uint32_t&>(p);
}
__device__ __forceinline__ void split2(float a, float b, uint32_t &hi, uint32_t &lo) {
    __nv_bfloat16 ah = __float2bfloat16_rn(a);
    __nv_bfloat16 bh = __float2bfloat16_rn(b);
    __nv_bfloat162 h; h.x = ah; h.y = bh;
    __nv_bfloat162 l = __floats2bfloat162_rn(a - __bfloat162float(ah),
                                             b - __bfloat162float(bh));
    hi = reinterpret_cast<uint32_t&>(h);
    lo = reinterpret_cast<uint32_t&>(l);
}

// =====================================================================
// K1: fused MLP: att = tanh(A @ W1 + b1) @ W2 + b2 -> bf16
// grid 128: blocks 0..63 -> A0/att0 (neigh), 64..127 -> A1/att1 (x)
// =====================================================================
__global__ __launch_bounds__(256)
void k_mlp(const float* __restrict__ A0, const float* __restrict__ W10,
           const float* __restrict__ b10, const float* __restrict__ W20,
           const float* __restrict__ b20, __nv_bfloat16* __restrict__ att0,
           const float* __restrict__ A1, const float* __restrict__ W11,
           const float* __restrict__ b11, const float* __restrict__ W21,
           const float* __restrict__ b21, __nv_bfloat16* __restrict__ att1) {
    __shared__ float As[32][132];
    __shared__ float Ws[32][32];
    __shared__ float W2s[32][33];
    __shared__ float Hs[128][36];
    const int tid  = threadIdx.x;
    const int which = (int)(blockIdx.x >> 6);
    const int row0 = (int)(blockIdx.x & 63) * 128;
    const float* A  = which ? A1  : A0;
    const float* W1 = which ? W11 : W10;
    const float* b1 = which ? b11 : b10;
    const float* W2 = which ? W21 : W20;
    const float* b2 = which ? b21 : b20;
    __nv_bfloat16* att = which ? att1 : att0;

    const int ty = tid / 8, tx = tid % 8;
    float acc[4][4] = {};

    #pragma unroll
    for (int p = 0; p < 4; p++) {
        int i = p * 256 + tid;
        W2s[i >> 5][i & 31] = W2[i];
    }

    for (int k0 = 0; k0 < DIN; k0 += 32) {
        #pragma unroll
        for (int p = 0; p < 4; p++) {
            int r  = p * 32 + tid / 8;
            int kq = (tid % 8) * 4;
            float4 v = *(const float4*)&A[(size_t)(row0 + r) * DIN + k0 + kq];
            As[kq + 0][r] = v.x; As[kq + 1][r] = v.y;
            As[kq + 2][r] = v.z; As[kq + 3][r] = v.w;
        }
        {
            int k = tid / 8, c4 = (tid % 8) * 4;
            *(float4*)&Ws[k][c4] = *(const float4*)&W1[(size_t)(k0 + k) * DH + c4];
        }
        __syncthreads();
        #pragma unroll
        for (int k = 0; k < 32; k++) {
            float4 a = *(const float4*)&As[k][ty * 4];
            float4 w = *(const float4*)&Ws[k][tx * 4];
            float av[4] = {a.x, a.y, a.z, a.w};
            float wv[4] = {w.x, w.y, w.z, w.w};
            #pragma unroll
            for (int r = 0; r < 4; r++)
                #pragma unroll
                for (int c = 0; c < 4; c++)
                    acc[r][c] += av[r] * wv[c];
        }
        __syncthreads();
    }
    #pragma unroll
    for (int r = 0; r < 4; r++)
        #pragma unroll
        for (int c = 0; c < 4; c++)
            Hs[ty * 4 + r][tx * 4 + c] = tanhf(acc[r][c] + b1[tx * 4 + c]);
    __syncthreads();

    {
        const int row = tid >> 1;
        const int cb  = (tid & 1) * 16;
        float s[16];
        #pragma unroll
        for (int j = 0; j < 16; j++) s[j] = b2[cb + j];
        #pragma unroll
        for (int k = 0; k < 32; k++) {
            float hv = Hs[row][k];
            #pragma unroll
            for (int j = 0; j < 16; j++) s[j] += hv * W2s[k][cb + j];
        }
        uint32_t ob[8];
        #pragma unroll
        for (int j2 = 0; j2 < 8; j2++) ob[j2] = bf2_hi(s[2 * j2], s[2 * j2 + 1]);
        uint4 u0 = {ob[0], ob[1], ob[2], ob[3]};
        uint4 u1 = {ob[4], ob[5], ob[6], ob[7]};
        *(uint4*)&att[(size_t)(row0 + row) * DH + cb]     = u0;
        *(uint4*)&att[(size_t)(row0 + row) * DH + cb + 8] = u1;
    }
}

// =====================================================================
// K2a: fc_x via split-bf16 HMMA (3-term: xh*wh + xh*wl + xl*wh).
// ~17-bit effective mantissa => fp32-class accuracy on the norm-dominant
// output half, on the tensor pipe. 512 threads, warps 4x4, tile 128x128.
// Dynamic SMEM: 2 stages x 4 regions (Ah,Al,Bh,Bl) x (128 rows x 80 B).
// =====================================================================
#define FC_REG   10240
#define FC_STAGE (4 * FC_REG)
#define FC_SMEM  (2 * FC_STAGE)

__device__ __forceinline__ void fcx_ldg(const float* __restrict__ X,
                                        const float* __restrict__ W,
                                        int row0, int d0, int kc, int tid,
                                        float xv[8], float wv[8]) {
    // x: 128 rows x 32 k. thread -> row tid>>2, k seg (tid&3)*8
    const int r = tid >> 2, seg = tid & 3;
    const float* xs = &X[(size_t)(row0 + r) * DIN + kc * 32 + seg * 8];
    *(float4*)&xv[0] = *(const float4*)&xs[0];
    *(float4*)&xv[4] = *(const float4*)&xs[4];
    // W: 128 d x 32 k. thread -> d tid&127, k group (tid>>7)*8
    const int wd = tid & 127, wk = (tid >> 7) * 8;
    #pragma unroll
    for (int j = 0; j < 8; j++)
        wv[j] = W[(size_t)(kc * 32 + wk + j) * DOUT + d0 + wd];
}
__device__ __forceinline__ void fcx_sts(char* base, int tid,
                                        const float xv[8], const float wv[8]) {
    char* sAh = base;
    char* sAl = base + FC_REG;
    char* sBh = base + 2 * FC_REG;
    char* sBl = base + 3 * FC_REG;
    const int r = tid >> 2, seg = tid & 3;
    uint32_t h[4], lo[4];
    #pragma unroll
    for (int j = 0; j < 4; j++) split2(xv[2 * j], xv[2 * j + 1], h[j], lo[j]);
    *(uint4*)&sAh[r * 80 + seg * 16] = make_uint4(h[0], h[1], h[2], h[3]);
    *(uint4*)&sAl[r * 80 + seg * 16] = make_uint4(lo[0], lo[1], lo[2], lo[3]);
    const int wd = tid & 127, wk = (tid >> 7) * 8;
    #pragma unroll
    for (int j = 0; j < 4; j++) split2(wv[2 * j], wv[2 * j + 1], h[j], lo[j]);
    *(uint4*)&sBh[wd * 80 + wk * 2] = make_uint4(h[0], h[1], h[2], h[3]);
    *(uint4*)&sBl[wd * 80 + wk * 2] = make_uint4(lo[0], lo[1], lo[2], lo[3]);
}

__global__ __launch_bounds__(512)
void k_fcx_mma(const float* __restrict__ X, const float* __restrict__ W,
               const float* __restrict__ bias, float* __restrict__ outp) {
    extern __shared__ __align__(16) char fcsm[];
    const int tid = threadIdx.x, wid = tid >> 5, l = tid & 31;
    const int row0 = (int)(blockIdx.x >> 1) * 128;
    const int d0   = (int)(blockIdx.x & 1) * 128;
    const int wm = (wid >> 2) * 32, wn = (wid & 3) * 32;

    float acc[2][4][4];
    #pragma unroll
    for (int t = 0; t < 2; t++)
        #pragma unroll
        for (int u = 0; u < 4; u++)
            #pragma unroll
            for (int c = 0; c < 4; c++) acc[t][u][c] = 0.f;

    float xv[8], wv[8];
    fcx_ldg(X, W, row0, d0, 0, tid, xv, wv);
    fcx_sts(fcsm, tid, xv, wv);
    fcx_ldg(X, W, row0, d0, 1, tid, xv, wv);

    const int lm16 = l & 15, lhi = (l >> 4) * 16;
    const int bn = (l & 7) + ((l >> 4) << 3), bk16 = ((l >> 3) & 1) * 16;

    for (int i = 0; i < 16; i++) {
        __syncthreads();
        if (i + 1 < 16) fcx_sts(fcsm + ((i + 1) & 1) * FC_STAGE, tid, xv, wv);
        if (i + 2 < 16) fcx_ldg(X, W, row0, d0, i + 2, tid, xv, wv);
        __syncthreads();

        char* base = fcsm + (i & 1) * FC_STAGE;
        const uint32_t Ah = smem_u32(base);
        const uint32_t Al = Ah + FC_REG;
        const uint32_t Bh = Ah + 2 * FC_REG;
        const uint32_t Bl = Ah + 3 * FC_REG;
        #pragma unroll
        for (int kk = 0; kk < 2; kk++) {
            uint32_t ah[2][4], al[2][4];
            #pragma unroll
            for (int t = 0; t < 2; t++) {
                uint32_t off = (uint32_t)((wm + t * 16 + lm16) * 80 + kk * 32 + lhi);
                LDMX4(ah[t][0], ah[t][1], ah[t][2], ah[t][3], Ah + off);
                LDMX4(al[t][0], al[t][1], al[t][2], al[t][3], Al + off);
            }
            #pragma unroll
            for (int u2 = 0; u2 < 2; u2++) {
                uint32_t off = (uint32_t)((wn + u2 * 16 + bn) * 80 + kk * 32 + bk16);
                uint32_t h0, h1, h2, h3, l0, l1, l2, l3;
                LDMX4(h0, h1, h2, h3, Bh + off);
                LDMX4(l0, l1, l2, l3, Bl + off);
                uint32_t bh0[2] = {h0, h1}, bh1[2] = {h2, h3};
                uint32_t bl0[2] = {l0, l1}, bl1[2] = {l2, l3};
                #pragma unroll
                for (int t = 0; t < 2; t++) {
                    MMA16816(acc[t][2 * u2],     ah[t], bh0);
                    MMA16816(acc[t][2 * u2],     ah[t], bl0);
                    MMA16816(acc[t][2 * u2],     al[t], bh0);
                    MMA16816(acc[t][2 * u2 + 1], ah[t], bh1);
                    MMA16816(acc[t][2 * u2 + 1], ah[t], bl1);
                    MMA16816(acc[t][2 * u2 + 1], al[t], bh1);
                }
            }
        }
    }

    #pragma unroll
    for (int t = 0; t < 2; t++) {
        int ra = row0 + wm + t * 16 + (l >> 2);
        int rb = ra + 8;
        #pragma unroll
        for (int u = 0; u < 4; u++) {
            int col = d0 + wn + u * 8 + (l & 3) * 2;
            float b0v = bias[col], b1v = bias[col + 1];
            float2 v0 = {acc[t][u][0] + b0v, acc[t][u][1] + b1v};
            float2 v1 = {acc[t][u][2] + b0v, acc[t][u][3] + b1v};
            *(float2*)&outp[(size_t)ra * (2 * DOUT) + col] = v0;
            *(float2*)&outp[(size_t)rb * (2 * DOUT) + col] = v1;
        }
    }
}

// =====================================================================
// K2b: value GEMM on HMMA, transposed output into g_valueT[d][n] bf16.
// =====================================================================
__device__ __forceinline__ void gemm_ldg(const float* __restrict__ X,
                                         const float* __restrict__ W,
                                         int row0, int d0, int kc, int tid,
                                         float4 xv[4], float wv[16]) {
    #pragma unroll
    for (int p = 0; p < 4; p++)
        xv[p] = *(const float4*)&X[(size_t)(row0 + p * 32 + (tid >> 3)) * DIN
                                   + kc * 32 + (tid & 7) * 4];
    const int wd = tid & 127, wkh = tid >> 7;
    #pragma unroll
    for (int k2 = 0; k2 < 16; k2++)
        wv[k2] = W[(size_t)(kc * 32 + wkh * 16 + k2) * DOUT + d0 + wd];
}
__device__ __forceinline__ void gemm_sts(char* sA, char* sB, int tid,
                                         const float4 xv[4], const float wv[16]) {
    #pragma unroll
    for (int p = 0; p < 4; p++) {
        uint2 u;
        u.x = bf2_hi(xv[p].x, xv[p].y);
        u.y = bf2_hi(xv[p].z, xv[p].w);
        *(uint2*)&sA[(p * 32 + (tid >> 3)) * 80 + (tid & 7) * 8] = u;
    }
    const int wd = tid & 127, wkh = tid >> 7;
    #pragma unroll
    for (int j = 0; j < 8; j++)
        *(uint32_t*)&sB[wd * 80 + wkh * 32 + j * 4] = bf2_hi(wv[2 * j], wv[2 * j + 1]);
}

__global__ __launch_bounds__(256)
void k_value_mma(const float* __restrict__ X, const float* __restrict__ W,
                 const float* __restrict__ bias) {
    __shared__ __align__(16) char sA[2][128 * 80];
    __shared__ __align__(16) char sB[2][128 * 80];
    const int tid = threadIdx.x, wid = tid >> 5, l = tid & 31;
    const int row0 = (int)(blockIdx.x >> 1) * 128;
    const int d0   = (int)(blockIdx.x & 1) * 128;
    const int wm = (wid >> 1) * 32, wn = (wid & 1) * 64;

    float acc[2][8][4];
    #pragma unroll
    for (int t = 0; t < 2; t++)
        #pragma unroll
        for (int u = 0; u < 8; u++)
            #pragma unroll
            for (int c = 0; c < 4; c++) acc[t][u][c] = 0.f;

    float4 xv[4]; float wv[16];
    gemm_ldg(X, W, row0, d0, 0, tid, xv, wv);
    gemm_sts(sA[0], sB[0], tid, xv, wv);
    gemm_ldg(X, W, row0, d0, 1, tid, xv, wv);

    const int lm16 = l & 15, lhi = (l >> 4) * 16;
    const int bn = (l & 7) + ((l >> 4) << 3), bk16 = ((l >> 3) & 1) * 16;

    for (int i = 0; i < 16; i++) {
        __syncthreads();
        if (i + 1 < 16) gemm_sts(sA[(i + 1) & 1], sB[(i + 1) & 1], tid, xv, wv);
        if (i + 2 < 16) gemm_ldg(X, W, row0, d0, i + 2, tid, xv, wv);

        const int b = i & 1;
        const uint32_t Ab = smem_u32(sB[b]);   // transposed: A = W tile
        const uint32_t Bb = smem_u32(sA[b]);
        #pragma unroll
        for (int kk = 0; kk < 2; kk++) {
            uint32_t a[2][4];
            #pragma unroll
            for (int t = 0; t < 2; t++) {
                uint32_t off = (uint32_t)((wm + t * 16 + lm16) * 80 + kk * 32 + lhi);
                LDMX4(a[t][0], a[t][1], a[t][2], a[t][3], Ab + off);
            }
            #pragma unroll
            for (int u2 = 0; u2 < 4; u2++) {
                uint32_t off = (uint32_t)((wn + u2 * 16 + bn) * 80 + kk * 32 + bk16);
                uint32_t r0_, r1_, r2_, r3_;
                LDMX4(r0_, r1_, r2_, r3_, Bb + off);
                uint32_t b0[2] = {r0_, r1_}, b1[2] = {r2_, r3_};
                #pragma unroll
                for (int t = 0; t < 2; t++) {
                    MMA16816(acc[t][2 * u2],     a[t], b0);
                    MMA16816(acc[t][2 * u2 + 1], a[t], b1);
                }
            }
        }
    }

    #pragma unroll
    for (int t = 0; t < 2; t++) {
        int dr = d0 + wm + t * 16 + (l >> 2);
        float bA = bias[dr], bB = bias[dr + 8];
        #pragma unroll
        for (int u = 0; u < 8; u++) {
            int nc = row0 + wn + u * 8 + (l & 3) * 2;
            uint32_t pA = bf2_hi(acc[t][u][0] + bA, acc[t][u][1] + bA);
            uint32_t pB = bf2_hi(acc[t][u][2] + bB, acc[t][u][3] + bB);
            *(uint32_t*)&g_valueT[(size_t)dr * NN + nc]       = pA;
            *(uint32_t*)&g_valueT[(size_t)(dr + 8) * NN + nc] = pB;
        }
    }
}

// =====================================================================
// K3: HMMA score kernel — 512 threads, warps 4(m)x4(n) on 64x128 chunks.
// =====================================================================
__device__ __forceinline__ void score_loadn(uint32_t nbase, int tid, int c) {
    int rr = tid >> 2, seg = tid & 3;
    uint32_t dst = nbase + (uint32_t)(c % 3) * 10240u + (uint32_t)(rr * 80 + seg * 16);
    const char* src = (const char*)g_nattb + ((size_t)c * 128 + rr) * 64 + seg * 16;
    CP16(dst, src);
}

__global__ __launch_bounds__(512)
void k_score_mma(const int* __restrict__ adj) {
    __shared__ __align__(16) char sN[3 * 128 * 80];
    __shared__ float s_rsum[4][64];
    const int tid = threadIdx.x, wid = tid >> 5, l = tid & 31;
    const int row0 = blockIdx.x * 64;
    const int wm = (wid >> 2) * 16;
    const int h  = wid & 3;
    const int wn = h * 32;
    const uint32_t nb = smem_u32(sN);

    uint32_t a[2][4];
    {
        const int r  = row0 + wm + (l >> 2);
        const int kq = (l & 3) * 2;
        const uint32_t* X = (const uint32_t*)g_xattb;
        #pragma unroll
        for (int kk = 0; kk < 2; kk++) {
            a[kk][0] = X[(size_t)r * 16       + (kk * 16 + kq) / 2];
            a[kk][1] = X[(size_t)(r + 8) * 16 + (kk * 16 + kq) / 2];
            a[kk][2] = X[(size_t)r * 16       + (kk * 16 + kq + 8) / 2];
            a[kk][3] = X[(size_t)(r + 8) * 16 + (kk * 16 + kq + 8) / 2];
        }
    }

    float rs0 = 0.f, rs1 = 0.f;
    const int bn = (l & 7) + ((l >> 4) << 3), bk16 = ((l >> 3) & 1) * 16;
    const int r0g = row0 + wm + (l >> 2);

    score_loadn(nb, tid, 0); CP_COMMIT();
    score_loadn(nb, tid, 1); CP_COMMIT();

    for (int i = 0; i < 64; i++) {
        CP_WAIT1();
        __syncthreads();
        if (i + 2 < 64) score_loadn(nb, tid, i + 2);
        CP_COMMIT();

        int2 adv[4][2];
        #pragma unroll
        for (int u = 0; u < 4; u++) {
            int cb = i * 128 + wn + u * 8 + (l & 3) * 2;
            adv[u][0] = *(const int2*)&adj[(size_t)r0g * NN + cb];
            adv[u][1] = *(const int2*)&adj[(size_t)(r0g + 8) * NN + cb];
        }

        float acc[4][4];
        #pragma unroll
        for (int u = 0; u < 4; u++)
            #pragma unroll
            for (int c = 0; c < 4; c++) acc[u][c] = 0.f;

        const uint32_t buf = nb + (uint32_t)(i % 3) * 10240u;
        #pragma unroll
        for (int kk = 0; kk < 2; kk++) {
            #pragma unroll
            for (int u2 = 0; u2 < 2; u2++) {
                uint32_t off = (uint32_t)((wn + u2 * 16 + bn) * 80 + kk * 32 + bk16);
                uint32_t r0_, r1_, r2_, r3_;
                LDMX4(r0_, r1_, r2_, r3_, buf + off);
                uint32_t b0[2] = {r0_, r1_}, b1[2] = {r2_, r3_};
                MMA16816(acc[2 * u2],     a[kk], b0);
                MMA16816(acc[2 * u2 + 1], a[kk], b1);
            }
        }

        #pragma unroll
        for (int u = 0; u < 4; u++) {
            int cb = i * 128 + wn + u * 8 + (l & 3) * 2;
            {
                float s0 = acc[u][0], s1 = acc[u][1];
                float w0 = s0 > 0.f ? s0 : 0.01f * s0;
                float w1 = s1 > 0.f ? s1 : 0.01f * s1;
                float e0 = adv[u][0].x > 0 ? __expf(w0) : 0.f;
                float e1 = adv[u][0].y > 0 ? __expf(w1) : 0.f;
                rs0 += e0 + e1;
                *(uint32_t*)&g_E[(size_t)r0g * NN + cb] = bf2_hi(e0, e1);
            }
            {
                float s0 = acc[u][2], s1 = acc[u][3];
                float w0 = s0 > 0.f ? s0 : 0.01f * s0;
                float w1 = s1 > 0.f ? s1 : 0.01f * s1;
                float e0 = adv[u][1].x > 0 ? __expf(w0) : 0.f;
                float e1 = adv[u][1].y > 0 ? __expf(w1) : 0.f;
                rs1 += e0 + e1;
                *(uint32_t*)&g_E[(size_t)(r0g + 8) * NN + cb] = bf2_hi(e0, e1);
            }
        }
    }

    rs0 += __shfl_xor_sync(0xffffffff, rs0, 1);
    rs0 += __shfl_xor_sync(0xffffffff, rs0, 2);
    rs1 += __shfl_xor_sync(0xffffffff, rs1, 1);
    rs1 += __shfl_xor_sync(0xffffffff, rs1, 2);
    if ((l & 3) == 0) {
        s_rsum[h][wm + (l >> 2)]     = rs0;
        s_rsum[h][wm + (l >> 2) + 8] = rs1;
    }
    __syncthreads();
    if (tid < 64)
        g_rowsum[row0 + tid] = (s_rsum[0][tid] + s_rsum[1][tid]) +
                               (s_rsum[2][tid] + s_rsum[3][tid]);
}

// =====================================================================
// K4: HMMA PV GEMM — 512 threads, warps 4x4, warp tile 32x32.
// =====================================================================
#define PV_BK     64
#define PV_NCH    (NN / PV_BK)
#define PV_STAGEB 32768
#define PV_SMEM   (4 * PV_STAGEB + 1024)

__device__ __forceinline__ void pv_load(uint32_t tile, int tid, int row0, int n0, int c) {
    const size_t kb = (size_t)c * (PV_BK * 2);
    const uint32_t eb = tile + (uint32_t)(c & 3) * PV_STAGEB;
    const uint32_t vb = eb + 16384u;
    #pragma unroll
    for (int p = 0; p < 2; p++) {
        int u = p * 512 + tid;
        int row = u >> 3, j = u & 7;
        uint32_t soff = SW128((uint32_t)(row * 128 + j * 16));
        const char* gE = (const char*)g_E +
            ((size_t)(row0 + row) * NN) * 2 + kb + (size_t)(j * 16);
        CP16(eb + soff, gE);
        const char* gV = (const char*)g_valueT +
            ((size_t)(n0 + row) * NN) * 2 + kb + (size_t)(j * 16);
        CP16(vb + soff, gV);
    }
}

__global__ __launch_bounds__(512)
void k_pv_mma(float* __restrict__ out) {
    extern __shared__ __align__(16) char dynsmem[];
    const int tid = threadIdx.x;
    const int wid = tid >> 5;
    const int l   = tid & 31;
    const int row0 = (int)(blockIdx.x >> 1) * 128;
    const int n0   = (int)(blockIdx.x & 1) * 128;
    const int wm0  = (wid >> 2) * 32;
    const int wn0  = (wid & 3) * 32;

    const uint32_t dynb = smem_u32(dynsmem);
    const uint32_t tile = (dynb + 1023u) & ~1023u;

    float acc[2][4][4];
    #pragma unroll
    for (int t = 0; t < 2; t++)
        #pragma unroll
        for (int u = 0; u < 4; u++)
            #pragma unroll
            for (int c = 0; c < 4; c++) acc[t][u][c] = 0.f;

    pv_load(tile, tid, row0, n0, 0); CP_COMMIT();
    pv_load(tile, tid, row0, n0, 1); CP_COMMIT();
    pv_load(tile, tid, row0, n0, 2); CP_COMMIT();

    const int lm16 = l & 15;
    const int lhi  = (l >> 4) * 16;
    const int bn   = (l & 7) + ((l >> 4) << 3);
    const int bk16 = ((l >> 3) & 1) * 16;

    for (int i = 0; i < PV_NCH; i++) {
        CP_WAIT2();
        __syncthreads();
        const uint32_t eb = tile + (uint32_t)(i & 3) * PV_STAGEB;
        const uint32_t vb = eb + 16384u;
        #pragma unroll
        for (int kk = 0; kk < 4; kk++) {
            uint32_t a[2][4];
            #pragma unroll
            for (int t = 0; t < 2; t++) {
                uint32_t off = (uint32_t)((wm0 + t * 16 + lm16) * 128 + kk * 32 + lhi);
                LDMX4(a[t][0], a[t][1], a[t][2], a[t][3], eb + SW128(off));
            }
            uint32_t b[4][2];
            #pragma unroll
            for (int u2 = 0; u2 < 2; u2++) {
                uint32_t off = (uint32_t)((wn0 + u2 * 16 + bn) * 128 + kk * 32 + bk16);
                uint32_t r0, r1, r2, r3;
                LDMX4(r0, r1, r2, r3, vb + SW128(off));
                b[2 * u2][0] = r0;     b[2 * u2][1] = r1;
                b[2 * u2 + 1][0] = r2; b[2 * u2 + 1][1] = r3;
            }
            #pragma unroll
            for (int t = 0; t < 2; t++)
                #pragma unroll
                for (int u = 0; u < 4; u++)
                    MMA16816(acc[t][u], a[t], b[u]);
        }
        const int j = i + 3;
        if (j < PV_NCH) pv_load(tile, tid, row0, n0, j);
        CP_COMMIT();
    }

    #pragma unroll
    for (int t = 0; t < 2; t++) {
        int ra = row0 + wm0 + t * 16 + (l >> 2);
        int rb = ra + 8;
        float inva = 1.0f / g_rowsum[ra];
        float invb = 1.0f / g_rowsum[rb];
        #pragma unroll
        for (int u = 0; u < 4; u++) {
            int col = DOUT + n0 + wn0 + u * 8 + (l & 3) * 2;
            float2 v0 = {acc[t][u][0] * inva, acc[t][u][1] * inva};
            float2 v1 = {acc[t][u][2] * invb, acc[t][u][3] * invb};
            *(float2*)&out[(size_t)ra * (2 * DOUT) + col] = v0;
            *(float2*)&out[(size_t)rb * (2 * DOUT) + col] = v1;
        }
    }
}

// =====================================================================
// launch
// =====================================================================
extern "C" void kernel_launch(void* const* d_in, const int* in_sizes, int n_in,
                              void* d_out, int out_size) {
    const float* x    = (const float*)d_in[0];
    const float* neigh= (const float*)d_in[1];
    const int*   adj  = (const int*)  d_in[2];
    const float* Wx1  = (const float*)d_in[3];
    const float* bx1  = (const float*)d_in[4];
    const float* Wx2  = (const float*)d_in[5];
    const float* bx2  = (const float*)d_in[6];
    const float* Wn1  = (const float*)d_in[7];
    const float* bn1  = (const float*)d_in[8];
    const float* Wn2  = (const float*)d_in[9];
    const float* bn2  = (const float*)d_in[10];
    const float* Wv   = (const float*)d_in[11];
    const float* bv   = (const float*)d_in[12];
    const float* Wfx  = (const float*)d_in[13];
    const float* bfx  = (const float*)d_in[14];
    float* out = (float*)d_out;

    __nv_bfloat16* xattb;
    __nv_bfloat16* nattb;
    cudaGetSymbolAddress((void**)&xattb, g_xattb);
    cudaGetSymbolAddress((void**)&nattb, g_nattb);

    cudaFuncSetAttribute(k_pv_mma, cudaFuncAttributeMaxDynamicSharedMemorySize, PV_SMEM);
    cudaFuncSetAttribute(k_fcx_mma, cudaFuncAttributeMaxDynamicSharedMemorySize, FC_SMEM);

    // fused attention MLPs (both branches in one grid) -> bf16 att
    k_mlp<<<2 * (NX / 128), 256>>>(neigh, Wn1, bn1, Wn2, bn2, nattb,
                                   x, Wx1, bx1, Wx2, bx2, xattb);
    // value (HMMA, transposed -> g_valueT); fc_x split-bf16 HMMA
    k_value_mma<<<128, 256>>>(neigh, Wv, bv);
    k_fcx_mma<<<128, 512, FC_SMEM>>>(x, Wfx, bfx, out);
    // HMMA scores + masked exp + rowsums
    k_score_mma<<<NX / 64, 512>>>(adj);
    // HMMA PV with softmax normalization
    k_pv_mma<<<(NX / 128) * 2, 512, PV_SMEM>>>(out);
}

// round 8
// speedup vs baseline: 5.3582x; 1.1014x over previous
#include <cuda_runtime.h>
#include <cuda_bf16.h>
#include <cstdint>

#define NX   8192
#define NN   8192
#define DIN  512
#define DH   32
#define DOUT 256

// ---------------- scratch (static __device__: allocation-free) ----------------
__device__ __nv_bfloat16 g_xattb[NX * DH];              // bf16 att (x)
__device__ __nv_bfloat16 g_nattb[NN * DH];              // bf16 att (neigh)
__device__ __nv_bfloat16 g_valueT[(size_t)DOUT * NN];   // 4 MB, [d][n] bf16
__device__ __nv_bfloat16 g_E[(size_t)NX * NN];          // 128 MB masked exp'd scores
__device__ float g_rowsum[NX];

// ---------------- portable helpers ----------------
__device__ __forceinline__ uint32_t smem_u32(const void* p) {
    uint32_t a;
    asm("{ .reg .u64 t; cvta.to.shared.u64 t, %1; cvt.u32.u64 %0, t; }" : "=r"(a) : "l"(p));
    return a;
}
#define CP16(dst, src) \
    asm volatile("cp.async.cg.shared.global [%0], [%1], 16;" :: "r"(dst), "l"(src))
#define CP_COMMIT() asm volatile("cp.async.commit_group;" ::: "memory")
#define CP_WAIT1()  asm volatile("cp.async.wait_group 1;" ::: "memory")
#define CP_WAIT2()  asm volatile("cp.async.wait_group 2;" ::: "memory")

#define SW128(off) ((off) ^ (((off) >> 3) & 0x70))

#define LDMX4(r0, r1, r2, r3, addr) \
    asm volatile("ldmatrix.sync.aligned.m8n8.x4.shared.b16 {%0,%1,%2,%3}, [%4];" \
                 : "=r"(r0), "=r"(r1), "=r"(r2), "=r"(r3) : "r"(addr))

#define MMA16816(c, a, b) \
    asm volatile("mma.sync.aligned.m16n8k16.row.col.f32.bf16.bf16.f32 " \
                 "{%0,%1,%2,%3}, {%4,%5,%6,%7}, {%8,%9}, {%0,%1,%2,%3};" \
                 : "+f"((c)[0]), "+f"((c)[1]), "+f"((c)[2]), "+f"((c)[3]) \
                 : "r"((a)[0]), "r"((a)[1]), "r"((a)[2]), "r"((a)[3]), \
                   "r"((b)[0]), "r"((b)[1]))

__device__ __forceinline__ uint32_t bf2_hi(float a, float b) {
    __nv_bfloat162 p = __floats2bfloat162_rn(a, b);
    return reinterpret_cast<uint32_t&>(p);
}
__device__ __forceinline__ void split2(float a, float b, uint32_t &hi, uint32_t &lo) {
    __nv_bfloat16 ah = __float2bfloat16_rn(a);
    __nv_bfloat16 bh = __float2bfloat16_rn(b);
    __nv_bfloat162 h; h.x = ah; h.y = bh;
    __nv_bfloat162 l = __floats2bfloat162_rn(a - __bfloat162float(ah),
                                             b - __bfloat162float(bh));
    hi = reinterpret_cast<uint32_t&>(h);
    lo = reinterpret_cast<uint32_t&>(l);
}

// Fast exp on the FMA/ALU pipes (no MUFU). rel err ~2e-6 on |w| <~ 20.
// E is stored as bf16 (0.4% grid), so this is 100x more accurate than needed.
__device__ __forceinline__ float fast_exp(float w) {
    const float L2E = 1.4426950408889634f;
    float t  = fmaf(w, L2E, 12582912.0f);       // magic round-to-nearest (1.5*2^23)
    int   n  = __float_as_int(t) - 0x4B400000;  // integer part
    float nf = t - 12582912.0f;
    float f  = fmaf(w, L2E, -nf);               // f in [-0.5, 0.5]
    float p  = fmaf(f, 0.0013333558f, 0.0096181291f);
    p = fmaf(f, p, 0.0555041087f);
    p = fmaf(f, p, 0.2402265069f);
    p = fmaf(f, p, 0.6931471806f);
    p = fmaf(f, p, 1.0f);
    return __int_as_float(__float_as_int(p) + (n << 23));
}

// =====================================================================
// K1: fused MLP: att = tanh(A @ W1 + b1) @ W2 + b2 -> bf16
// grid 128: blocks 0..63 -> A0/att0 (neigh), 64..127 -> A1/att1 (x)
// =====================================================================
__global__ __launch_bounds__(256)
void k_mlp(const float* __restrict__ A0, const float* __restrict__ W10,
           const float* __restrict__ b10, const float* __restrict__ W20,
           const float* __restrict__ b20, __nv_bfloat16* __restrict__ att0,
           const float* __restrict__ A1, const float* __restrict__ W11,
           const float* __restrict__ b11, const float* __restrict__ W21,
           const float* __restrict__ b21, __nv_bfloat16* __restrict__ att1) {
    __shared__ float As[32][132];
    __shared__ float Ws[32][32];
    __shared__ float W2s[32][33];
    __shared__ float Hs[128][36];
    const int tid  = threadIdx.x;
    const int which = (int)(blockIdx.x >> 6);
    const int row0 = (int)(blockIdx.x & 63) * 128;
    const float* A  = which ? A1  : A0;
    const float* W1 = which ? W11 : W10;
    const float* b1 = which ? b11 : b10;
    const float* W2 = which ? W21 : W20;
    const float* b2 = which ? b21 : b20;
    __nv_bfloat16* att = which ? att1 : att0;

    const int ty = tid / 8, tx = tid % 8;
    float acc[4][4] = {};

    #pragma unroll
    for (int p = 0; p < 4; p++) {
        int i = p * 256 + tid;
        W2s[i >> 5][i & 31] = W2[i];
    }

    for (int k0 = 0; k0 < DIN; k0 += 32) {
        #pragma unroll
        for (int p = 0; p < 4; p++) {
            int r  = p * 32 + tid / 8;
            int kq = (tid % 8) * 4;
            float4 v = *(const float4*)&A[(size_t)(row0 + r) * DIN + k0 + kq];
            As[kq + 0][r] = v.x; As[kq + 1][r] = v.y;
            As[kq + 2][r] = v.z; As[kq + 3][r] = v.w;
        }
        {
            int k = tid / 8, c4 = (tid % 8) * 4;
            *(float4*)&Ws[k][c4] = *(const float4*)&W1[(size_t)(k0 + k) * DH + c4];
        }
        __syncthreads();
        #pragma unroll
        for (int k = 0; k < 32; k++) {
            float4 a = *(const float4*)&As[k][ty * 4];
            float4 w = *(const float4*)&Ws[k][tx * 4];
            float av[4] = {a.x, a.y, a.z, a.w};
            float wv[4] = {w.x, w.y, w.z, w.w};
            #pragma unroll
            for (int r = 0; r < 4; r++)
                #pragma unroll
                for (int c = 0; c < 4; c++)
                    acc[r][c] += av[r] * wv[c];
        }
        __syncthreads();
    }
    #pragma unroll
    for (int r = 0; r < 4; r++)
        #pragma unroll
        for (int c = 0; c < 4; c++)
            Hs[ty * 4 + r][tx * 4 + c] = tanhf(acc[r][c] + b1[tx * 4 + c]);
    __syncthreads();

    {
        const int row = tid >> 1;
        const int cb  = (tid & 1) * 16;
        float s[16];
        #pragma unroll
        for (int j = 0; j < 16; j++) s[j] = b2[cb + j];
        #pragma unroll
        for (int k = 0; k < 32; k++) {
            float hv = Hs[row][k];
            #pragma unroll
            for (int j = 0; j < 16; j++) s[j] += hv * W2s[k][cb + j];
        }
        uint32_t ob[8];
        #pragma unroll
        for (int j2 = 0; j2 < 8; j2++) ob[j2] = bf2_hi(s[2 * j2], s[2 * j2 + 1]);
        uint4 u0 = {ob[0], ob[1], ob[2], ob[3]};
        uint4 u1 = {ob[4], ob[5], ob[6], ob[7]};
        *(uint4*)&att[(size_t)(row0 + row) * DH + cb]     = u0;
        *(uint4*)&att[(size_t)(row0 + row) * DH + cb + 8] = u1;
    }
}

// =====================================================================
// K2a: fc_x via split-bf16 HMMA (3-term: xh*wh + xh*wl + xl*wh).
// =====================================================================
#define FC_REG   10240
#define FC_STAGE (4 * FC_REG)
#define FC_SMEM  (2 * FC_STAGE)

__device__ __forceinline__ void fcx_ldg(const float* __restrict__ X,
                                        const float* __restrict__ W,
                                        int row0, int d0, int kc, int tid,
                                        float xv[8], float wv[8]) {
    const int r = tid >> 2, seg = tid & 3;
    const float* xs = &X[(size_t)(row0 + r) * DIN + kc * 32 + seg * 8];
    *(float4*)&xv[0] = *(const float4*)&xs[0];
    *(float4*)&xv[4] = *(const float4*)&xs[4];
    const int wd = tid & 127, wk = (tid >> 7) * 8;
    #pragma unroll
    for (int j = 0; j < 8; j++)
        wv[j] = W[(size_t)(kc * 32 + wk + j) * DOUT + d0 + wd];
}
__device__ __forceinline__ void fcx_sts(char* base, int tid,
                                        const float xv[8], const float wv[8]) {
    char* sAh = base;
    char* sAl = base + FC_REG;
    char* sBh = base + 2 * FC_REG;
    char* sBl = base + 3 * FC_REG;
    const int r = tid >> 2, seg = tid & 3;
    uint32_t h[4], lo[4];
    #pragma unroll
    for (int j = 0; j < 4; j++) split2(xv[2 * j], xv[2 * j + 1], h[j], lo[j]);
    *(uint4*)&sAh[r * 80 + seg * 16] = make_uint4(h[0], h[1], h[2], h[3]);
    *(uint4*)&sAl[r * 80 + seg * 16] = make_uint4(lo[0], lo[1], lo[2], lo[3]);
    const int wd = tid & 127, wk = (tid >> 7) * 8;
    #pragma unroll
    for (int j = 0; j < 4; j++) split2(wv[2 * j], wv[2 * j + 1], h[j], lo[j]);
    *(uint4*)&sBh[wd * 80 + wk * 2] = make_uint4(h[0], h[1], h[2], h[3]);
    *(uint4*)&sBl[wd * 80 + wk * 2] = make_uint4(lo[0], lo[1], lo[2], lo[3]);
}

__global__ __launch_bounds__(512)
void k_fcx_mma(const float* __restrict__ X, const float* __restrict__ W,
               const float* __restrict__ bias, float* __restrict__ outp) {
    extern __shared__ __align__(16) char fcsm[];
    const int tid = threadIdx.x, wid = tid >> 5, l = tid & 31;
    const int row0 = (int)(blockIdx.x >> 1) * 128;
    const int d0   = (int)(blockIdx.x & 1) * 128;
    const int wm = (wid >> 2) * 32, wn = (wid & 3) * 32;

    float acc[2][4][4];
    #pragma unroll
    for (int t = 0; t < 2; t++)
        #pragma unroll
        for (int u = 0; u < 4; u++)
            #pragma unroll
            for (int c = 0; c < 4; c++) acc[t][u][c] = 0.f;

    float xv[8], wv[8];
    fcx_ldg(X, W, row0, d0, 0, tid, xv, wv);
    fcx_sts(fcsm, tid, xv, wv);
    fcx_ldg(X, W, row0, d0, 1, tid, xv, wv);

    const int lm16 = l & 15, lhi = (l >> 4) * 16;
    const int bn = (l & 7) + ((l >> 4) << 3), bk16 = ((l >> 3) & 1) * 16;

    for (int i = 0; i < 16; i++) {
        __syncthreads();
        if (i + 1 < 16) fcx_sts(fcsm + ((i + 1) & 1) * FC_STAGE, tid, xv, wv);
        if (i + 2 < 16) fcx_ldg(X, W, row0, d0, i + 2, tid, xv, wv);
        __syncthreads();

        char* base = fcsm + (i & 1) * FC_STAGE;
        const uint32_t Ah = smem_u32(base);
        const uint32_t Al = Ah + FC_REG;
        const uint32_t Bh = Ah + 2 * FC_REG;
        const uint32_t Bl = Ah + 3 * FC_REG;
        #pragma unroll
        for (int kk = 0; kk < 2; kk++) {
            uint32_t ah[2][4], al[2][4];
            #pragma unroll
            for (int t = 0; t < 2; t++) {
                uint32_t off = (uint32_t)((wm + t * 16 + lm16) * 80 + kk * 32 + lhi);
                LDMX4(ah[t][0], ah[t][1], ah[t][2], ah[t][3], Ah + off);
                LDMX4(al[t][0], al[t][1], al[t][2], al[t][3], Al + off);
            }
            #pragma unroll
            for (int u2 = 0; u2 < 2; u2++) {
                uint32_t off = (uint32_t)((wn + u2 * 16 + bn) * 80 + kk * 32 + bk16);
                uint32_t h0, h1, h2, h3, l0, l1, l2, l3;
                LDMX4(h0, h1, h2, h3, Bh + off);
                LDMX4(l0, l1, l2, l3, Bl + off);
                uint32_t bh0[2] = {h0, h1}, bh1[2] = {h2, h3};
                uint32_t bl0[2] = {l0, l1}, bl1[2] = {l2, l3};
                #pragma unroll
                for (int t = 0; t < 2; t++) {
                    MMA16816(acc[t][2 * u2],     ah[t], bh0);
                    MMA16816(acc[t][2 * u2],     ah[t], bl0);
                    MMA16816(acc[t][2 * u2],     al[t], bh0);
                    MMA16816(acc[t][2 * u2 + 1], ah[t], bh1);
                    MMA16816(acc[t][2 * u2 + 1], ah[t], bl1);
                    MMA16816(acc[t][2 * u2 + 1], al[t], bh1);
                }
            }
        }
    }

    #pragma unroll
    for (int t = 0; t < 2; t++) {
        int ra = row0 + wm + t * 16 + (l >> 2);
        int rb = ra + 8;
        #pragma unroll
        for (int u = 0; u < 4; u++) {
            int col = d0 + wn + u * 8 + (l & 3) * 2;
            float b0v = bias[col], b1v = bias[col + 1];
            float2 v0 = {acc[t][u][0] + b0v, acc[t][u][1] + b1v};
            float2 v1 = {acc[t][u][2] + b0v, acc[t][u][3] + b1v};
            *(float2*)&outp[(size_t)ra * (2 * DOUT) + col] = v0;
            *(float2*)&outp[(size_t)rb * (2 * DOUT) + col] = v1;
        }
    }
}

// =====================================================================
// K2b: value GEMM on HMMA, transposed output into g_valueT[d][n] bf16.
// =====================================================================
__device__ __forceinline__ void gemm_ldg(const float* __restrict__ X,
                                         const float* __restrict__ W,
                                         int row0, int d0, int kc, int tid,
                                         float4 xv[4], float wv[16]) {
    #pragma unroll
    for (int p = 0; p < 4; p++)
        xv[p] = *(const float4*)&X[(size_t)(row0 + p * 32 + (tid >> 3)) * DIN
                                   + kc * 32 + (tid & 7) * 4];
    const int wd = tid & 127, wkh = tid >> 7;
    #pragma unroll
    for (int k2 = 0; k2 < 16; k2++)
        wv[k2] = W[(size_t)(kc * 32 + wkh * 16 + k2) * DOUT + d0 + wd];
}
__device__ __forceinline__ void gemm_sts(char* sA, char* sB, int tid,
                                         const float4 xv[4], const float wv[16]) {
    #pragma unroll
    for (int p = 0; p < 4; p++) {
        uint2 u;
        u.x = bf2_hi(xv[p].x, xv[p].y);
        u.y = bf2_hi(xv[p].z, xv[p].w);
        *(uint2*)&sA[(p * 32 + (tid >> 3)) * 80 + (tid & 7) * 8] = u;
    }
    const int wd = tid & 127, wkh = tid >> 7;
    #pragma unroll
    for (int j = 0; j < 8; j++)
        *(uint32_t*)&sB[wd * 80 + wkh * 32 + j * 4] = bf2_hi(wv[2 * j], wv[2 * j + 1]);
}

__global__ __launch_bounds__(256)
void k_value_mma(const float* __restrict__ X, const float* __restrict__ W,
                 const float* __restrict__ bias) {
    __shared__ __align__(16) char sA[2][128 * 80];
    __shared__ __align__(16) char sB[2][128 * 80];
    const int tid = threadIdx.x, wid = tid >> 5, l = tid & 31;
    const int row0 = (int)(blockIdx.x >> 1) * 128;
    const int d0   = (int)(blockIdx.x & 1) * 128;
    const int wm = (wid >> 1) * 32, wn = (wid & 1) * 64;

    float acc[2][8][4];
    #pragma unroll
    for (int t = 0; t < 2; t++)
        #pragma unroll
        for (int u = 0; u < 8; u++)
            #pragma unroll
            for (int c = 0; c < 4; c++) acc[t][u][c] = 0.f;

    float4 xv[4]; float wv[16];
    gemm_ldg(X, W, row0, d0, 0, tid, xv, wv);
    gemm_sts(sA[0], sB[0], tid, xv, wv);
    gemm_ldg(X, W, row0, d0, 1, tid, xv, wv);

    const int lm16 = l & 15, lhi = (l >> 4) * 16;
    const int bn = (l & 7) + ((l >> 4) << 3), bk16 = ((l >> 3) & 1) * 16;

    for (int i = 0; i < 16; i++) {
        __syncthreads();
        if (i + 1 < 16) gemm_sts(sA[(i + 1) & 1], sB[(i + 1) & 1], tid, xv, wv);
        if (i + 2 < 16) gemm_ldg(X, W, row0, d0, i + 2, tid, xv, wv);

        const int b = i & 1;
        const uint32_t Ab = smem_u32(sB[b]);   // transposed: A = W tile
        const uint32_t Bb = smem_u32(sA[b]);
        #pragma unroll
        for (int kk = 0; kk < 2; kk++) {
            uint32_t a[2][4];
            #pragma unroll
            for (int t = 0; t < 2; t++) {
                uint32_t off = (uint32_t)((wm + t * 16 + lm16) * 80 + kk * 32 + lhi);
                LDMX4(a[t][0], a[t][1], a[t][2], a[t][3], Ab + off);
            }
            #pragma unroll
            for (int u2 = 0; u2 < 4; u2++) {
                uint32_t off = (uint32_t)((wn + u2 * 16 + bn) * 80 + kk * 32 + bk16);
                uint32_t r0_, r1_, r2_, r3_;
                LDMX4(r0_, r1_, r2_, r3_, Bb + off);
                uint32_t b0[2] = {r0_, r1_}, b1[2] = {r2_, r3_};
                #pragma unroll
                for (int t = 0; t < 2; t++) {
                    MMA16816(acc[t][2 * u2],     a[t], b0);
                    MMA16816(acc[t][2 * u2 + 1], a[t], b1);
                }
            }
        }
    }

    #pragma unroll
    for (int t = 0; t < 2; t++) {
        int dr = d0 + wm + t * 16 + (l >> 2);
        float bA = bias[dr], bB = bias[dr + 8];
        #pragma unroll
        for (int u = 0; u < 8; u++) {
            int nc = row0 + wn + u * 8 + (l & 3) * 2;
            uint32_t pA = bf2_hi(acc[t][u][0] + bA, acc[t][u][1] + bA);
            uint32_t pB = bf2_hi(acc[t][u][2] + bB, acc[t][u][3] + bB);
            *(uint32_t*)&g_valueT[(size_t)dr * NN + nc]       = pA;
            *(uint32_t*)&g_valueT[(size_t)(dr + 8) * NN + nc] = pB;
        }
    }
}

// =====================================================================
// K3: HMMA score kernel — fast_exp (no MUFU), 32 rows/CTA, 256 CTAs,
// 256 threads (8 warps: 2m x 4n over 32x128 chunks).
// =====================================================================
__device__ __forceinline__ void score_loadn(uint32_t nbase, int tid, int c) {
    #pragma unroll
    for (int q = 0; q < 2; q++) {
        int u  = tid * 2 + q;            // 0..511 -> 128 rows x 4 segs
        int rr = u >> 2, seg = u & 3;
        uint32_t dst = nbase + (uint32_t)(c % 3) * 10240u + (uint32_t)(rr * 80 + seg * 16);
        const char* src = (const char*)g_nattb + ((size_t)c * 128 + rr) * 64 + seg * 16;
        CP16(dst, src);
    }
}

__global__ __launch_bounds__(256)
void k_score_mma(const int* __restrict__ adj) {
    __shared__ __align__(16) char sN[3 * 128 * 80];
    __shared__ float s_rsum[4][32];
    const int tid = threadIdx.x, wid = tid >> 5, l = tid & 31;
    const int row0 = blockIdx.x * 32;
    const int wm = (wid >> 2) * 16;           // 2 m-groups
    const int h  = wid & 3;                   // 4 n-groups
    const int wn = h * 32;
    const uint32_t nb = smem_u32(sN);

    uint32_t a[2][4];
    {
        const int r  = row0 + wm + (l >> 2);
        const int kq = (l & 3) * 2;
        const uint32_t* X = (const uint32_t*)g_xattb;
        #pragma unroll
        for (int kk = 0; kk < 2; kk++) {
            a[kk][0] = X[(size_t)r * 16       + (kk * 16 + kq) / 2];
            a[kk][1] = X[(size_t)(r + 8) * 16 + (kk * 16 + kq) / 2];
            a[kk][2] = X[(size_t)r * 16       + (kk * 16 + kq + 8) / 2];
            a[kk][3] = X[(size_t)(r + 8) * 16 + (kk * 16 + kq + 8) / 2];
        }
    }

    float rs0 = 0.f, rs1 = 0.f;
    const int bn = (l & 7) + ((l >> 4) << 3), bk16 = ((l >> 3) & 1) * 16;
    const int r0g = row0 + wm + (l >> 2);

    score_loadn(nb, tid, 0); CP_COMMIT();
    score_loadn(nb, tid, 1); CP_COMMIT();

    for (int i = 0; i < 64; i++) {
        CP_WAIT1();
        __syncthreads();
        if (i + 2 < 64) score_loadn(nb, tid, i + 2);
        CP_COMMIT();

        int2 adv[4][2];
        #pragma unroll
        for (int u = 0; u < 4; u++) {
            int cb = i * 128 + wn + u * 8 + (l & 3) * 2;
            adv[u][0] = *(const int2*)&adj[(size_t)r0g * NN + cb];
            adv[u][1] = *(const int2*)&adj[(size_t)(r0g + 8) * NN + cb];
        }

        float acc[4][4];
        #pragma unroll
        for (int u = 0; u < 4; u++)
            #pragma unroll
            for (int c = 0; c < 4; c++) acc[u][c] = 0.f;

        const uint32_t buf = nb + (uint32_t)(i % 3) * 10240u;
        #pragma unroll
        for (int kk = 0; kk < 2; kk++) {
            #pragma unroll
            for (int u2 = 0; u2 < 2; u2++) {
                uint32_t off = (uint32_t)((wn + u2 * 16 + bn) * 80 + kk * 32 + bk16);
                uint32_t r0_, r1_, r2_, r3_;
                LDMX4(r0_, r1_, r2_, r3_, buf + off);
                uint32_t b0[2] = {r0_, r1_}, b1[2] = {r2_, r3_};
                MMA16816(acc[2 * u2],     a[kk], b0);
                MMA16816(acc[2 * u2 + 1], a[kk], b1);
            }
        }

        #pragma unroll
        for (int u = 0; u < 4; u++) {
            int cb = i * 128 + wn + u * 8 + (l & 3) * 2;
            {
                float s0 = acc[u][0], s1 = acc[u][1];
                float w0 = s0 > 0.f ? s0 : 0.01f * s0;
                float w1 = s1 > 0.f ? s1 : 0.01f * s1;
                float e0 = adv[u][0].x > 0 ? fast_exp(w0) : 0.f;
                float e1 = adv[u][0].y > 0 ? fast_exp(w1) : 0.f;
                rs0 += e0 + e1;
                *(uint32_t*)&g_E[(size_t)r0g * NN + cb] = bf2_hi(e0, e1);
            }
            {
                float s0 = acc[u][2], s1 = acc[u][3];
                float w0 = s0 > 0.f ? s0 : 0.01f * s0;
                float w1 = s1 > 0.f ? s1 : 0.01f * s1;
                float e0 = adv[u][1].x > 0 ? fast_exp(w0) : 0.f;
                float e1 = adv[u][1].y > 0 ? fast_exp(w1) : 0.f;
                rs1 += e0 + e1;
                *(uint32_t*)&g_E[(size_t)(r0g + 8) * NN + cb] = bf2_hi(e0, e1);
            }
        }
    }

    rs0 += __shfl_xor_sync(0xffffffff, rs0, 1);
    rs0 += __shfl_xor_sync(0xffffffff, rs0, 2);
    rs1 += __shfl_xor_sync(0xffffffff, rs1, 1);
    rs1 += __shfl_xor_sync(0xffffffff, rs1, 2);
    if ((l & 3) == 0) {
        s_rsum[h][wm + (l >> 2)]     = rs0;
        s_rsum[h][wm + (l >> 2) + 8] = rs1;
    }
    __syncthreads();
    if (tid < 32)
        g_rowsum[row0 + tid] = (s_rsum[0][tid] + s_rsum[1][tid]) +
                               (s_rsum[2][tid] + s_rsum[3][tid]);
}

// =====================================================================
// K4: HMMA PV GEMM — 512 threads, warps 4x4, warp tile 32x32.
// =====================================================================
#define PV_BK     64
#define PV_NCH    (NN / PV_BK)
#define PV_STAGEB 32768
#define PV_SMEM   (4 * PV_STAGEB + 1024)

__device__ __forceinline__ void pv_load(uint32_t tile, int tid, int row0, int n0, int c) {
    const size_t kb = (size_t)c * (PV_BK * 2);
    const uint32_t eb = tile + (uint32_t)(c & 3) * PV_STAGEB;
    const uint32_t vb = eb + 16384u;
    #pragma unroll
    for (int p = 0; p < 2; p++) {
        int u = p * 512 + tid;
        int row = u >> 3, j = u & 7;
        uint32_t soff = SW128((uint32_t)(row * 128 + j * 16));
        const char* gE = (const char*)g_E +
            ((size_t)(row0 + row) * NN) * 2 + kb + (size_t)(j * 16);
        CP16(eb + soff, gE);
        const char* gV = (const char*)g_valueT +
            ((size_t)(n0 + row) * NN) * 2 + kb + (size_t)(j * 16);
        CP16(vb + soff, gV);
    }
}

__global__ __launch_bounds__(512)
void k_pv_mma(float* __restrict__ out) {
    extern __shared__ __align__(16) char dynsmem[];
    const int tid = threadIdx.x;
    const int wid = tid >> 5;
    const int l   = tid & 31;
    const int row0 = (int)(blockIdx.x >> 1) * 128;
    const int n0   = (int)(blockIdx.x & 1) * 128;
    const int wm0  = (wid >> 2) * 32;
    const int wn0  = (wid & 3) * 32;

    const uint32_t dynb = smem_u32(dynsmem);
    const uint32_t tile = (dynb + 1023u) & ~1023u;

    float acc[2][4][4];
    #pragma unroll
    for (int t = 0; t < 2; t++)
        #pragma unroll
        for (int u = 0; u < 4; u++)
            #pragma unroll
            for (int c = 0; c < 4; c++) acc[t][u][c] = 0.f;

    pv_load(tile, tid, row0, n0, 0); CP_COMMIT();
    pv_load(tile, tid, row0, n0, 1); CP_COMMIT();
    pv_load(tile, tid, row0, n0, 2); CP_COMMIT();

    const int lm16 = l & 15;
    const int lhi  = (l >> 4) * 16;
    const int bn   = (l & 7) + ((l >> 4) << 3);
    const int bk16 = ((l >> 3) & 1) * 16;

    for (int i = 0; i < PV_NCH; i++) {
        CP_WAIT2();
        __syncthreads();
        const uint32_t eb = tile + (uint32_t)(i & 3) * PV_STAGEB;
        const uint32_t vb = eb + 16384u;
        #pragma unroll
        for (int kk = 0; kk < 4; kk++) {
            uint32_t a[2][4];
            #pragma unroll
            for (int t = 0; t < 2; t++) {
                uint32_t off = (uint32_t)((wm0 + t * 16 + lm16) * 128 + kk * 32 + lhi);
                LDMX4(a[t][0], a[t][1], a[t][2], a[t][3], eb + SW128(off));
            }
            uint32_t b[4][2];
            #pragma unroll
            for (int u2 = 0; u2 < 2; u2++) {
                uint32_t off = (uint32_t)((wn0 + u2 * 16 + bn) * 128 + kk * 32 + bk16);
                uint32_t r0, r1, r2, r3;
                LDMX4(r0, r1, r2, r3, vb + SW128(off));
                b[2 * u2][0] = r0;     b[2 * u2][1] = r1;
                b[2 * u2 + 1][0] = r2; b[2 * u2 + 1][1] = r3;
            }
            #pragma unroll
            for (int t = 0; t < 2; t++)
                #pragma unroll
                for (int u = 0; u < 4; u++)
                    MMA16816(acc[t][u], a[t], b[u]);
        }
        const int j = i + 3;
        if (j < PV_NCH) pv_load(tile, tid, row0, n0, j);
        CP_COMMIT();
    }

    #pragma unroll
    for (int t = 0; t < 2; t++) {
        int ra = row0 + wm0 + t * 16 + (l >> 2);
        int rb = ra + 8;
        float inva = 1.0f / g_rowsum[ra];
        float invb = 1.0f / g_rowsum[rb];
        #pragma unroll
        for (int u = 0; u < 4; u++) {
            int col = DOUT + n0 + wn0 + u * 8 + (l & 3) * 2;
            float2 v0 = {acc[t][u][0] * inva, acc[t][u][1] * inva};
            float2 v1 = {acc[t][u][2] * invb, acc[t][u][3] * invb};
            *(float2*)&out[(size_t)ra * (2 * DOUT) + col] = v0;
            *(float2*)&out[(size_t)rb * (2 * DOUT) + col] = v1;
        }
    }
}

// =====================================================================
// launch
// =====================================================================
extern "C" void kernel_launch(void* const* d_in, const int* in_sizes, int n_in,
                              void* d_out, int out_size) {
    const float* x    = (const float*)d_in[0];
    const float* neigh= (const float*)d_in[1];
    const int*   adj  = (const int*)  d_in[2];
    const float* Wx1  = (const float*)d_in[3];
    const float* bx1  = (const float*)d_in[4];
    const float* Wx2  = (const float*)d_in[5];
    const float* bx2  = (const float*)d_in[6];
    const float* Wn1  = (const float*)d_in[7];
    const float* bn1  = (const float*)d_in[8];
    const float* Wn2  = (const float*)d_in[9];
    const float* bn2  = (const float*)d_in[10];
    const float* Wv   = (const float*)d_in[11];
    const float* bv   = (const float*)d_in[12];
    const float* Wfx  = (const float*)d_in[13];
    const float* bfx  = (const float*)d_in[14];
    float* out = (float*)d_out;

    __nv_bfloat16* xattb;
    __nv_bfloat16* nattb;
    cudaGetSymbolAddress((void**)&xattb, g_xattb);
    cudaGetSymbolAddress((void**)&nattb, g_nattb);

    cudaFuncSetAttribute(k_pv_mma, cudaFuncAttributeMaxDynamicSharedMemorySize, PV_SMEM);
    cudaFuncSetAttribute(k_fcx_mma, cudaFuncAttributeMaxDynamicSharedMemorySize, FC_SMEM);

    // fused attention MLPs (both branches in one grid) -> bf16 att
    k_mlp<<<2 * (NX / 128), 256>>>(neigh, Wn1, bn1, Wn2, bn2, nattb,
                                   x, Wx1, bx1, Wx2, bx2, xattb);
    // value (HMMA, transposed -> g_valueT); fc_x split-bf16 HMMA
    k_value_mma<<<128, 256>>>(neigh, Wv, bv);
    k_fcx_mma<<<128, 512, FC_SMEM>>>(x, Wfx, bfx, out);
    // HMMA scores + masked fast_exp + rowsums (FMA-pipe exp, no MUFU)
    k_score_mma<<<NX / 32, 256>>>(adj);
    // HMMA PV with softmax normalization
    k_pv_mma<<<(NX / 128) * 2, 512, PV_SMEM>>>(out);
}

// round 9
// speedup vs baseline: 6.0260x; 1.1246x over previous
#include <cuda_runtime.h>
#include <cuda_bf16.h>
#include <cstdint>

#define NX   8192
#define NN   8192
#define DIN  512
#define DH   32
#define DOUT 256
#define NSPLIT 4

// ---------------- scratch (static __device__: allocation-free) ----------------
__device__ __nv_bfloat16 g_xattb[NX * DH];              // bf16 att (x)
__device__ __nv_bfloat16 g_nattb[NN * DH];              // bf16 att (neigh)
__device__ __nv_bfloat16 g_valueT[(size_t)DOUT * NN];   // 4 MB, [d][n] bf16
__device__ __nv_bfloat16 g_E[(size_t)NX * NN];          // 128 MB masked exp'd scores
__device__ float g_rowsum4[NSPLIT * NX];                // per-column-split partials

// ---------------- portable helpers ----------------
__device__ __forceinline__ uint32_t smem_u32(const void* p) {
    uint32_t a;
    asm("{ .reg .u64 t; cvta.to.shared.u64 t, %1; cvt.u32.u64 %0, t; }" : "=r"(a) : "l"(p));
    return a;
}
#define CP16(dst, src) \
    asm volatile("cp.async.cg.shared.global [%0], [%1], 16;" :: "r"(dst), "l"(src))
#define CP_COMMIT() asm volatile("cp.async.commit_group;" ::: "memory")
#define CP_WAIT1()  asm volatile("cp.async.wait_group 1;" ::: "memory")
#define CP_WAIT2()  asm volatile("cp.async.wait_group 2;" ::: "memory")

#define SW128(off) ((off) ^ (((off) >> 3) & 0x70))

#define LDMX4(r0, r1, r2, r3, addr) \
    asm volatile("ldmatrix.sync.aligned.m8n8.x4.shared.b16 {%0,%1,%2,%3}, [%4];" \
                 : "=r"(r0), "=r"(r1), "=r"(r2), "=r"(r3) : "r"(addr))

#define MMA16816(c, a, b) \
    asm volatile("mma.sync.aligned.m16n8k16.row.col.f32.bf16.bf16.f32 " \
                 "{%0,%1,%2,%3}, {%4,%5,%6,%7}, {%8,%9}, {%0,%1,%2,%3};" \
                 : "+f"((c)[0]), "+f"((c)[1]), "+f"((c)[2]), "+f"((c)[3]) \
                 : "r"((a)[0]), "r"((a)[1]), "r"((a)[2]), "r"((a)[3]), \
                   "r"((b)[0]), "r"((b)[1]))

__device__ __forceinline__ uint32_t bf2_hi(float a, float b) {
    __nv_bfloat162 p = __floats2bfloat162_rn(a, b);
    return reinterpret_cast<uint32_t&>(p);
}
__device__ __forceinline__ void split2(float a, float b, uint32_t &hi, uint32_t &lo) {
    __nv_bfloat16 ah = __float2bfloat16_rn(a);
    __nv_bfloat16 bh = __float2bfloat16_rn(b);
    __nv_bfloat162 h; h.x = ah; h.y = bh;
    __nv_bfloat162 l = __floats2bfloat162_rn(a - __bfloat162float(ah),
                                             b - __bfloat162float(bh));
    hi = reinterpret_cast<uint32_t&>(h);
    lo = reinterpret_cast<uint32_t&>(l);
}

// Fast exp on the FMA/ALU pipes (no MUFU). rel err ~2e-6 on |w| <~ 20.
__device__ __forceinline__ float fast_exp(float w) {
    const float L2E = 1.4426950408889634f;
    float t  = fmaf(w, L2E, 12582912.0f);
    int   n  = __float_as_int(t) - 0x4B400000;
    float nf = t - 12582912.0f;
    float f  = fmaf(w, L2E, -nf);
    float p  = fmaf(f, 0.0013333558f, 0.0096181291f);
    p = fmaf(f, p, 0.0555041087f);
    p = fmaf(f, p, 0.2402265069f);
    p = fmaf(f, p, 0.6931471806f);
    p = fmaf(f, p, 1.0f);
    return __int_as_float(__float_as_int(p) + (n << 23));
}

// =====================================================================
// K1: fused MLP: att = tanh(A @ W1 + b1) @ W2 + b2 -> bf16
// =====================================================================
__global__ __launch_bounds__(256)
void k_mlp(const float* __restrict__ A0, const float* __restrict__ W10,
           const float* __restrict__ b10, const float* __restrict__ W20,
           const float* __restrict__ b20, __nv_bfloat16* __restrict__ att0,
           const float* __restrict__ A1, const float* __restrict__ W11,
           const float* __restrict__ b11, const float* __restrict__ W21,
           const float* __restrict__ b21, __nv_bfloat16* __restrict__ att1) {
    __shared__ float As[32][132];
    __shared__ float Ws[32][32];
    __shared__ float W2s[32][33];
    __shared__ float Hs[128][36];
    const int tid  = threadIdx.x;
    const int which = (int)(blockIdx.x >> 6);
    const int row0 = (int)(blockIdx.x & 63) * 128;
    const float* A  = which ? A1  : A0;
    const float* W1 = which ? W11 : W10;
    const float* b1 = which ? b11 : b10;
    const float* W2 = which ? W21 : W20;
    const float* b2 = which ? b21 : b20;
    __nv_bfloat16* att = which ? att1 : att0;

    const int ty = tid / 8, tx = tid % 8;
    float acc[4][4] = {};

    #pragma unroll
    for (int p = 0; p < 4; p++) {
        int i = p * 256 + tid;
        W2s[i >> 5][i & 31] = W2[i];
    }

    for (int k0 = 0; k0 < DIN; k0 += 32) {
        #pragma unroll
        for (int p = 0; p < 4; p++) {
            int r  = p * 32 + tid / 8;
            int kq = (tid % 8) * 4;
            float4 v = *(const float4*)&A[(size_t)(row0 + r) * DIN + k0 + kq];
            As[kq + 0][r] = v.x; As[kq + 1][r] = v.y;
            As[kq + 2][r] = v.z; As[kq + 3][r] = v.w;
        }
        {
            int k = tid / 8, c4 = (tid % 8) * 4;
            *(float4*)&Ws[k][c4] = *(const float4*)&W1[(size_t)(k0 + k) * DH + c4];
        }
        __syncthreads();
        #pragma unroll
        for (int k = 0; k < 32; k++) {
            float4 a = *(const float4*)&As[k][ty * 4];
            float4 w = *(const float4*)&Ws[k][tx * 4];
            float av[4] = {a.x, a.y, a.z, a.w};
            float wv[4] = {w.x, w.y, w.z, w.w};
            #pragma unroll
            for (int r = 0; r < 4; r++)
                #pragma unroll
                for (int c = 0; c < 4; c++)
                    acc[r][c] += av[r] * wv[c];
        }
        __syncthreads();
    }
    #pragma unroll
    for (int r = 0; r < 4; r++)
        #pragma unroll
        for (int c = 0; c < 4; c++)
            Hs[ty * 4 + r][tx * 4 + c] = tanhf(acc[r][c] + b1[tx * 4 + c]);
    __syncthreads();

    {
        const int row = tid >> 1;
        const int cb  = (tid & 1) * 16;
        float s[16];
        #pragma unroll
        for (int j = 0; j < 16; j++) s[j] = b2[cb + j];
        #pragma unroll
        for (int k = 0; k < 32; k++) {
            float hv = Hs[row][k];
            #pragma unroll
            for (int j = 0; j < 16; j++) s[j] += hv * W2s[k][cb + j];
        }
        uint32_t ob[8];
        #pragma unroll
        for (int j2 = 0; j2 < 8; j2++) ob[j2] = bf2_hi(s[2 * j2], s[2 * j2 + 1]);
        uint4 u0 = {ob[0], ob[1], ob[2], ob[3]};
        uint4 u1 = {ob[4], ob[5], ob[6], ob[7]};
        *(uint4*)&att[(size_t)(row0 + row) * DH + cb]     = u0;
        *(uint4*)&att[(size_t)(row0 + row) * DH + cb + 8] = u1;
    }
}

// =====================================================================
// K2a: fc_x via split-bf16 HMMA (3-term: xh*wh + xh*wl + xl*wh).
// =====================================================================
#define FC_REG   10240
#define FC_STAGE (4 * FC_REG)
#define FC_SMEM  (2 * FC_STAGE)

__device__ __forceinline__ void fcx_ldg(const float* __restrict__ X,
                                        const float* __restrict__ W,
                                        int row0, int d0, int kc, int tid,
                                        float xv[8], float wv[8]) {
    const int r = tid >> 2, seg = tid & 3;
    const float* xs = &X[(size_t)(row0 + r) * DIN + kc * 32 + seg * 8];
    *(float4*)&xv[0] = *(const float4*)&xs[0];
    *(float4*)&xv[4] = *(const float4*)&xs[4];
    const int wd = tid & 127, wk = (tid >> 7) * 8;
    #pragma unroll
    for (int j = 0; j < 8; j++)
        wv[j] = W[(size_t)(kc * 32 + wk + j) * DOUT + d0 + wd];
}
__device__ __forceinline__ void fcx_sts(char* base, int tid,
                                        const float xv[8], const float wv[8]) {
    char* sAh = base;
    char* sAl = base + FC_REG;
    char* sBh = base + 2 * FC_REG;
    char* sBl = base + 3 * FC_REG;
    const int r = tid >> 2, seg = tid & 3;
    uint32_t h[4], lo[4];
    #pragma unroll
    for (int j = 0; j < 4; j++) split2(xv[2 * j], xv[2 * j + 1], h[j], lo[j]);
    *(uint4*)&sAh[r * 80 + seg * 16] = make_uint4(h[0], h[1], h[2], h[3]);
    *(uint4*)&sAl[r * 80 + seg * 16] = make_uint4(lo[0], lo[1], lo[2], lo[3]);
    const int wd = tid & 127, wk = (tid >> 7) * 8;
    #pragma unroll
    for (int j = 0; j < 4; j++) split2(wv[2 * j], wv[2 * j + 1], h[j], lo[j]);
    *(uint4*)&sBh[wd * 80 + wk * 2] = make_uint4(h[0], h[1], h[2], h[3]);
    *(uint4*)&sBl[wd * 80 + wk * 2] = make_uint4(lo[0], lo[1], lo[2], lo[3]);
}

__global__ __launch_bounds__(512)
void k_fcx_mma(const float* __restrict__ X, const float* __restrict__ W,
               const float* __restrict__ bias, float* __restrict__ outp) {
    extern __shared__ __align__(16) char fcsm[];
    const int tid = threadIdx.x, wid = tid >> 5, l = tid & 31;
    const int row0 = (int)(blockIdx.x >> 1) * 128;
    const int d0   = (int)(blockIdx.x & 1) * 128;
    const int wm = (wid >> 2) * 32, wn = (wid & 3) * 32;

    float acc[2][4][4];
    #pragma unroll
    for (int t = 0; t < 2; t++)
        #pragma unroll
        for (int u = 0; u < 4; u++)
            #pragma unroll
            for (int c = 0; c < 4; c++) acc[t][u][c] = 0.f;

    float xv[8], wv[8];
    fcx_ldg(X, W, row0, d0, 0, tid, xv, wv);
    fcx_sts(fcsm, tid, xv, wv);
    fcx_ldg(X, W, row0, d0, 1, tid, xv, wv);

    const int lm16 = l & 15, lhi = (l >> 4) * 16;
    const int bn = (l & 7) + ((l >> 4) << 3), bk16 = ((l >> 3) & 1) * 16;

    for (int i = 0; i < 16; i++) {
        __syncthreads();
        if (i + 1 < 16) fcx_sts(fcsm + ((i + 1) & 1) * FC_STAGE, tid, xv, wv);
        if (i + 2 < 16) fcx_ldg(X, W, row0, d0, i + 2, tid, xv, wv);
        __syncthreads();

        char* base = fcsm + (i & 1) * FC_STAGE;
        const uint32_t Ah = smem_u32(base);
        const uint32_t Al = Ah + FC_REG;
        const uint32_t Bh = Ah + 2 * FC_REG;
        const uint32_t Bl = Ah + 3 * FC_REG;
        #pragma unroll
        for (int kk = 0; kk < 2; kk++) {
            uint32_t ah[2][4], al[2][4];
            #pragma unroll
            for (int t = 0; t < 2; t++) {
                uint32_t off = (uint32_t)((wm + t * 16 + lm16) * 80 + kk * 32 + lhi);
                LDMX4(ah[t][0], ah[t][1], ah[t][2], ah[t][3], Ah + off);
                LDMX4(al[t][0], al[t][1], al[t][2], al[t][3], Al + off);
            }
            #pragma unroll
            for (int u2 = 0; u2 < 2; u2++) {
                uint32_t off = (uint32_t)((wn + u2 * 16 + bn) * 80 + kk * 32 + bk16);
                uint32_t h0, h1, h2, h3, l0, l1, l2, l3;
                LDMX4(h0, h1, h2, h3, Bh + off);
                LDMX4(l0, l1, l2, l3, Bl + off);
                uint32_t bh0[2] = {h0, h1}, bh1[2] = {h2, h3};
                uint32_t bl0[2] = {l0, l1}, bl1[2] = {l2, l3};
                #pragma unroll
                for (int t = 0; t < 2; t++) {
                    MMA16816(acc[t][2 * u2],     ah[t], bh0);
                    MMA16816(acc[t][2 * u2],     ah[t], bl0);
                    MMA16816(acc[t][2 * u2],     al[t], bh0);
                    MMA16816(acc[t][2 * u2 + 1], ah[t], bh1);
                    MMA16816(acc[t][2 * u2 + 1], ah[t], bl1);
                    MMA16816(acc[t][2 * u2 + 1], al[t], bh1);
                }
            }
        }
    }

    #pragma unroll
    for (int t = 0; t < 2; t++) {
        int ra = row0 + wm + t * 16 + (l >> 2);
        int rb = ra + 8;
        #pragma unroll
        for (int u = 0; u < 4; u++) {
            int col = d0 + wn + u * 8 + (l & 3) * 2;
            float b0v = bias[col], b1v = bias[col + 1];
            float2 v0 = {acc[t][u][0] + b0v, acc[t][u][1] + b1v};
            float2 v1 = {acc[t][u][2] + b0v, acc[t][u][3] + b1v};
            *(float2*)&outp[(size_t)ra * (2 * DOUT) + col] = v0;
            *(float2*)&outp[(size_t)rb * (2 * DOUT) + col] = v1;
        }
    }
}

// =====================================================================
// K2b: value GEMM on HMMA, transposed output into g_valueT[d][n] bf16.
// =====================================================================
__device__ __forceinline__ void gemm_ldg(const float* __restrict__ X,
                                         const float* __restrict__ W,
                                         int row0, int d0, int kc, int tid,
                                         float4 xv[4], float wv[16]) {
    #pragma unroll
    for (int p = 0; p < 4; p++)
        xv[p] = *(const float4*)&X[(size_t)(row0 + p * 32 + (tid >> 3)) * DIN
                                   + kc * 32 + (tid & 7) * 4];
    const int wd = tid & 127, wkh = tid >> 7;
    #pragma unroll
    for (int k2 = 0; k2 < 16; k2++)
        wv[k2] = W[(size_t)(kc * 32 + wkh * 16 + k2) * DOUT + d0 + wd];
}
__device__ __forceinline__ void gemm_sts(char* sA, char* sB, int tid,
                                         const float4 xv[4], const float wv[16]) {
    #pragma unroll
    for (int p = 0; p < 4; p++) {
        uint2 u;
        u.x = bf2_hi(xv[p].x, xv[p].y);
        u.y = bf2_hi(xv[p].z, xv[p].w);
        *(uint2*)&sA[(p * 32 + (tid >> 3)) * 80 + (tid & 7) * 8] = u;
    }
    const int wd = tid & 127, wkh = tid >> 7;
    #pragma unroll
    for (int j = 0; j < 8; j++)
        *(uint32_t*)&sB[wd * 80 + wkh * 32 + j * 4] = bf2_hi(wv[2 * j], wv[2 * j + 1]);
}

__global__ __launch_bounds__(256)
void k_value_mma(const float* __restrict__ X, const float* __restrict__ W,
                 const float* __restrict__ bias) {
    __shared__ __align__(16) char sA[2][128 * 80];
    __shared__ __align__(16) char sB[2][128 * 80];
    const int tid = threadIdx.x, wid = tid >> 5, l = tid & 31;
    const int row0 = (int)(blockIdx.x >> 1) * 128;
    const int d0   = (int)(blockIdx.x & 1) * 128;
    const int wm = (wid >> 1) * 32, wn = (wid & 1) * 64;

    float acc[2][8][4];
    #pragma unroll
    for (int t = 0; t < 2; t++)
        #pragma unroll
        for (int u = 0; u < 8; u++)
            #pragma unroll
            for (int c = 0; c < 4; c++) acc[t][u][c] = 0.f;

    float4 xv[4]; float wv[16];
    gemm_ldg(X, W, row0, d0, 0, tid, xv, wv);
    gemm_sts(sA[0], sB[0], tid, xv, wv);
    gemm_ldg(X, W, row0, d0, 1, tid, xv, wv);

    const int lm16 = l & 15, lhi = (l >> 4) * 16;
    const int bn = (l & 7) + ((l >> 4) << 3), bk16 = ((l >> 3) & 1) * 16;

    for (int i = 0; i < 16; i++) {
        __syncthreads();
        if (i + 1 < 16) gemm_sts(sA[(i + 1) & 1], sB[(i + 1) & 1], tid, xv, wv);
        if (i + 2 < 16) gemm_ldg(X, W, row0, d0, i + 2, tid, xv, wv);

        const int b = i & 1;
        const uint32_t Ab = smem_u32(sB[b]);   // transposed: A = W tile
        const uint32_t Bb = smem_u32(sA[b]);
        #pragma unroll
        for (int kk = 0; kk < 2; kk++) {
            uint32_t a[2][4];
            #pragma unroll
            for (int t = 0; t < 2; t++) {
                uint32_t off = (uint32_t)((wm + t * 16 + lm16) * 80 + kk * 32 + lhi);
                LDMX4(a[t][0], a[t][1], a[t][2], a[t][3], Ab + off);
            }
            #pragma unroll
            for (int u2 = 0; u2 < 4; u2++) {
                uint32_t off = (uint32_t)((wn + u2 * 16 + bn) * 80 + kk * 32 + bk16);
                uint32_t r0_, r1_, r2_, r3_;
                LDMX4(r0_, r1_, r2_, r3_, Bb + off);
                uint32_t b0[2] = {r0_, r1_}, b1[2] = {r2_, r3_};
                #pragma unroll
                for (int t = 0; t < 2; t++) {
                    MMA16816(acc[t][2 * u2],     a[t], b0);
                    MMA16816(acc[t][2 * u2 + 1], a[t], b1);
                }
            }
        }
    }

    #pragma unroll
    for (int t = 0; t < 2; t++) {
        int dr = d0 + wm + t * 16 + (l >> 2);
        float bA = bias[dr], bB = bias[dr + 8];
        #pragma unroll
        for (int u = 0; u < 8; u++) {
            int nc = row0 + wn + u * 8 + (l & 3) * 2;
            uint32_t pA = bf2_hi(acc[t][u][0] + bA, acc[t][u][1] + bA);
            uint32_t pB = bf2_hi(acc[t][u][2] + bB, acc[t][u][3] + bB);
            *(uint32_t*)&g_valueT[(size_t)dr * NN + nc]       = pA;
            *(uint32_t*)&g_valueT[(size_t)(dr + 8) * NN + nc] = pB;
        }
    }
}

// =====================================================================
// K3: HMMA score kernel — column-split x4 for occupancy.
// grid = (NX/32) * NSPLIT CTAs; CTA: 32 rows x 2048 cols (16 chunks).
// Partial rowsums -> g_rowsum4[sp][row]; summed in PV epilogue.
// =====================================================================
__device__ __forceinline__ void score_loadn(uint32_t nbase, int tid, int c, int buf) {
    #pragma unroll
    for (int q = 0; q < 2; q++) {
        int u  = tid * 2 + q;            // 0..511 -> 128 rows x 4 segs
        int rr = u >> 2, seg = u & 3;
        uint32_t dst = nbase + (uint32_t)buf * 10240u + (uint32_t)(rr * 80 + seg * 16);
        const char* src = (const char*)g_nattb + ((size_t)c * 128 + rr) * 64 + seg * 16;
        CP16(dst, src);
    }
}

__global__ __launch_bounds__(256, 4)
void k_score_mma(const int* __restrict__ adj) {
    __shared__ __align__(16) char sN[3 * 128 * 80];
    __shared__ float s_rsum[4][32];
    const int tid = threadIdx.x, wid = tid >> 5, l = tid & 31;
    const int row0 = (int)(blockIdx.x >> 2) * 32;
    const int sp   = (int)(blockIdx.x & 3);
    const int c0   = sp * 16;                 // first global chunk
    const int wm = (wid >> 2) * 16;           // 2 m-groups
    const int h  = wid & 3;                   // 4 n-groups
    const int wn = h * 32;
    const uint32_t nb = smem_u32(sN);

    uint32_t a[2][4];
    {
        const int r  = row0 + wm + (l >> 2);
        const int kq = (l & 3) * 2;
        const uint32_t* X = (const uint32_t*)g_xattb;
        #pragma unroll
        for (int kk = 0; kk < 2; kk++) {
            a[kk][0] = X[(size_t)r * 16       + (kk * 16 + kq) / 2];
            a[kk][1] = X[(size_t)(r + 8) * 16 + (kk * 16 + kq) / 2];
            a[kk][2] = X[(size_t)r * 16       + (kk * 16 + kq + 8) / 2];
            a[kk][3] = X[(size_t)(r + 8) * 16 + (kk * 16 + kq + 8) / 2];
        }
    }

    float rs0 = 0.f, rs1 = 0.f;
    const int bn = (l & 7) + ((l >> 4) << 3), bk16 = ((l >> 3) & 1) * 16;
    const int r0g = row0 + wm + (l >> 2);

    score_loadn(nb, tid, c0 + 0, 0); CP_COMMIT();
    score_loadn(nb, tid, c0 + 1, 1); CP_COMMIT();

    for (int i = 0; i < 16; i++) {
        CP_WAIT1();
        __syncthreads();
        if (i + 2 < 16) score_loadn(nb, tid, c0 + i + 2, (i + 2) % 3);
        CP_COMMIT();

        int2 adv[4][2];
        #pragma unroll
        for (int u = 0; u < 4; u++) {
            int cb = (c0 + i) * 128 + wn + u * 8 + (l & 3) * 2;
            adv[u][0] = *(const int2*)&adj[(size_t)r0g * NN + cb];
            adv[u][1] = *(const int2*)&adj[(size_t)(r0g + 8) * NN + cb];
        }

        float acc[4][4];
        #pragma unroll
        for (int u = 0; u < 4; u++)
            #pragma unroll
            for (int c = 0; c < 4; c++) acc[u][c] = 0.f;

        const uint32_t buf = nb + (uint32_t)(i % 3) * 10240u;
        #pragma unroll
        for (int kk = 0; kk < 2; kk++) {
            #pragma unroll
            for (int u2 = 0; u2 < 2; u2++) {
                uint32_t off = (uint32_t)((wn + u2 * 16 + bn) * 80 + kk * 32 + bk16);
                uint32_t r0_, r1_, r2_, r3_;
                LDMX4(r0_, r1_, r2_, r3_, buf + off);
                uint32_t b0[2] = {r0_, r1_}, b1[2] = {r2_, r3_};
                MMA16816(acc[2 * u2],     a[kk], b0);
                MMA16816(acc[2 * u2 + 1], a[kk], b1);
            }
        }

        #pragma unroll
        for (int u = 0; u < 4; u++) {
            int cb = (c0 + i) * 128 + wn + u * 8 + (l & 3) * 2;
            {
                float s0 = acc[u][0], s1 = acc[u][1];
                float w0 = s0 > 0.f ? s0 : 0.01f * s0;
                float w1 = s1 > 0.f ? s1 : 0.01f * s1;
                float e0 = adv[u][0].x > 0 ? fast_exp(w0) : 0.f;
                float e1 = adv[u][0].y > 0 ? fast_exp(w1) : 0.f;
                rs0 += e0 + e1;
                *(uint32_t*)&g_E[(size_t)r0g * NN + cb] = bf2_hi(e0, e1);
            }
            {
                float s0 = acc[u][2], s1 = acc[u][3];
                float w0 = s0 > 0.f ? s0 : 0.01f * s0;
                float w1 = s1 > 0.f ? s1 : 0.01f * s1;
                float e0 = adv[u][1].x > 0 ? fast_exp(w0) : 0.f;
                float e1 = adv[u][1].y > 0 ? fast_exp(w1) : 0.f;
                rs1 += e0 + e1;
                *(uint32_t*)&g_E[(size_t)(r0g + 8) * NN + cb] = bf2_hi(e0, e1);
            }
        }
    }

    rs0 += __shfl_xor_sync(0xffffffff, rs0, 1);
    rs0 += __shfl_xor_sync(0xffffffff, rs0, 2);
    rs1 += __shfl_xor_sync(0xffffffff, rs1, 1);
    rs1 += __shfl_xor_sync(0xffffffff, rs1, 2);
    if ((l & 3) == 0) {
        s_rsum[h][wm + (l >> 2)]     = rs0;
        s_rsum[h][wm + (l >> 2) + 8] = rs1;
    }
    __syncthreads();
    if (tid < 32)
        g_rowsum4[sp * NX + row0 + tid] =
            (s_rsum[0][tid] + s_rsum[1][tid]) + (s_rsum[2][tid] + s_rsum[3][tid]);
}

// =====================================================================
// K4: HMMA PV GEMM — 512 threads, warps 4x4, warp tile 32x32.
// =====================================================================
#define PV_BK     64
#define PV_NCH    (NN / PV_BK)
#define PV_STAGEB 32768
#define PV_SMEM   (4 * PV_STAGEB + 1024)

__device__ __forceinline__ void pv_load(uint32_t tile, int tid, int row0, int n0, int c) {
    const size_t kb = (size_t)c * (PV_BK * 2);
    const uint32_t eb = tile + (uint32_t)(c & 3) * PV_STAGEB;
    const uint32_t vb = eb + 16384u;
    #pragma unroll
    for (int p = 0; p < 2; p++) {
        int u = p * 512 + tid;
        int row = u >> 3, j = u & 7;
        uint32_t soff = SW128((uint32_t)(row * 128 + j * 16));
        const char* gE = (const char*)g_E +
            ((size_t)(row0 + row) * NN) * 2 + kb + (size_t)(j * 16);
        CP16(eb + soff, gE);
        const char* gV = (const char*)g_valueT +
            ((size_t)(n0 + row) * NN) * 2 + kb + (size_t)(j * 16);
        CP16(vb + soff, gV);
    }
}

__global__ __launch_bounds__(512)
void k_pv_mma(float* __restrict__ out) {
    extern __shared__ __align__(16) char dynsmem[];
    const int tid = threadIdx.x;
    const int wid = tid >> 5;
    const int l   = tid & 31;
    const int row0 = (int)(blockIdx.x >> 1) * 128;
    const int n0   = (int)(blockIdx.x & 1) * 128;
    const int wm0  = (wid >> 2) * 32;
    const int wn0  = (wid & 3) * 32;

    const uint32_t dynb = smem_u32(dynsmem);
    const uint32_t tile = (dynb + 1023u) & ~1023u;

    float acc[2][4][4];
    #pragma unroll
    for (int t = 0; t < 2; t++)
        #pragma unroll
        for (int u = 0; u < 4; u++)
            #pragma unroll
            for (int c = 0; c < 4; c++) acc[t][u][c] = 0.f;

    pv_load(tile, tid, row0, n0, 0); CP_COMMIT();
    pv_load(tile, tid, row0, n0, 1); CP_COMMIT();
    pv_load(tile, tid, row0, n0, 2); CP_COMMIT();

    const int lm16 = l & 15;
    const int lhi  = (l >> 4) * 16;
    const int bn   = (l & 7) + ((l >> 4) << 3);
    const int bk16 = ((l >> 3) & 1) * 16;

    for (int i = 0; i < PV_NCH; i++) {
        CP_WAIT2();
        __syncthreads();
        const uint32_t eb = tile + (uint32_t)(i & 3) * PV_STAGEB;
        const uint32_t vb = eb + 16384u;
        #pragma unroll
        for (int kk = 0; kk < 4; kk++) {
            uint32_t a[2][4];
            #pragma unroll
            for (int t = 0; t < 2; t++) {
                uint32_t off = (uint32_t)((wm0 + t * 16 + lm16) * 128 + kk * 32 + lhi);
                LDMX4(a[t][0], a[t][1], a[t][2], a[t][3], eb + SW128(off));
            }
            uint32_t b[4][2];
            #pragma unroll
            for (int u2 = 0; u2 < 2; u2++) {
                uint32_t off = (uint32_t)((wn0 + u2 * 16 + bn) * 128 + kk * 32 + bk16);
                uint32_t r0, r1, r2, r3;
                LDMX4(r0, r1, r2, r3, vb + SW128(off));
                b[2 * u2][0] = r0;     b[2 * u2][1] = r1;
                b[2 * u2 + 1][0] = r2; b[2 * u2 + 1][1] = r3;
            }
            #pragma unroll
            for (int t = 0; t < 2; t++)
                #pragma unroll
                for (int u = 0; u < 4; u++)
                    MMA16816(acc[t][u], a[t], b[u]);
        }
        const int j = i + 3;
        if (j < PV_NCH) pv_load(tile, tid, row0, n0, j);
        CP_COMMIT();
    }

    #pragma unroll
    for (int t = 0; t < 2; t++) {
        int ra = row0 + wm0 + t * 16 + (l >> 2);
        int rb = ra + 8;
        float sa = (g_rowsum4[ra] + g_rowsum4[NX + ra]) +
                   (g_rowsum4[2 * NX + ra] + g_rowsum4[3 * NX + ra]);
        float sb = (g_rowsum4[rb] + g_rowsum4[NX + rb]) +
                   (g_rowsum4[2 * NX + rb] + g_rowsum4[3 * NX + rb]);
        float inva = 1.0f / sa;
        float invb = 1.0f / sb;
        #pragma unroll
        for (int u = 0; u < 4; u++) {
            int col = DOUT + n0 + wn0 + u * 8 + (l & 3) * 2;
            float2 v0 = {acc[t][u][0] * inva, acc[t][u][1] * inva};
            float2 v1 = {acc[t][u][2] * invb, acc[t][u][3] * invb};
            *(float2*)&out[(size_t)ra * (2 * DOUT) + col] = v0;
            *(float2*)&out[(size_t)rb * (2 * DOUT) + col] = v1;
        }
    }
}

// =====================================================================
// launch
// =====================================================================
extern "C" void kernel_launch(void* const* d_in, const int* in_sizes, int n_in,
                              void* d_out, int out_size) {
    const float* x    = (const float*)d_in[0];
    const float* neigh= (const float*)d_in[1];
    const int*   adj  = (const int*)  d_in[2];
    const float* Wx1  = (const float*)d_in[3];
    const float* bx1  = (const float*)d_in[4];
    const float* Wx2  = (const float*)d_in[5];
    const float* bx2  = (const float*)d_in[6];
    const float* Wn1  = (const float*)d_in[7];
    const float* bn1  = (const float*)d_in[8];
    const float* Wn2  = (const float*)d_in[9];
    const float* bn2  = (const float*)d_in[10];
    const float* Wv   = (const float*)d_in[11];
    const float* bv   = (const float*)d_in[12];
    const float* Wfx  = (const float*)d_in[13];
    const float* bfx  = (const float*)d_in[14];
    float* out = (float*)d_out;

    __nv_bfloat16* xattb;
    __nv_bfloat16* nattb;
    cudaGetSymbolAddress((void**)&xattb, g_xattb);
    cudaGetSymbolAddress((void**)&nattb, g_nattb);

    cudaFuncSetAttribute(k_pv_mma, cudaFuncAttributeMaxDynamicSharedMemorySize, PV_SMEM);
    cudaFuncSetAttribute(k_fcx_mma, cudaFuncAttributeMaxDynamicSharedMemorySize, FC_SMEM);

    // fused attention MLPs (both branches in one grid) -> bf16 att
    k_mlp<<<2 * (NX / 128), 256>>>(neigh, Wn1, bn1, Wn2, bn2, nattb,
                                   x, Wx1, bx1, Wx2, bx2, xattb);
    // value (HMMA, transposed -> g_valueT); fc_x split-bf16 HMMA
    k_value_mma<<<128, 256>>>(neigh, Wv, bv);
    k_fcx_mma<<<128, 512, FC_SMEM>>>(x, Wfx, bfx, out);
    // HMMA scores + masked fast_exp + partial rowsums (column-split x4)
    k_score_mma<<<(NX / 32) * NSPLIT, 256>>>(adj);
    // HMMA PV with softmax normalization (sums 4 rowsum partials)
    k_pv_mma<<<(NX / 128) * 2, 512, PV_SMEM>>>(out);
}

// round 10
// speedup vs baseline: 6.4853x; 1.0762x over previous
#include <cuda_runtime.h>
#include <cuda_bf16.h>
#include <cstdint>

#define NX   8192
#define NN   8192
#define DIN  512
#define DH   32
#define DOUT 256
#define NSPLIT 4

// ---------------- scratch (static __device__: allocation-free) ----------------
__device__ __nv_bfloat16 g_xattb[NX * DH];              // bf16 att (x)
__device__ __nv_bfloat16 g_nattb[NN * DH];              // bf16 att (neigh)
__device__ __nv_bfloat16 g_valueT[(size_t)DOUT * NN];   // 4 MB, [d][n] bf16
__device__ __nv_bfloat16 g_E[(size_t)NX * NN];          // 128 MB masked exp'd scores
__device__ float g_rowsum4[NSPLIT * NX];                // per-column-split partials
__device__ float g_pvpart[2 * (size_t)NX * DOUT];       // 16 MB PV k-split partials

// ---------------- portable helpers ----------------
__device__ __forceinline__ uint32_t smem_u32(const void* p) {
    uint32_t a;
    asm("{ .reg .u64 t; cvta.to.shared.u64 t, %1; cvt.u32.u64 %0, t; }" : "=r"(a) : "l"(p));
    return a;
}
#define CP16(dst, src) \
    asm volatile("cp.async.cg.shared.global [%0], [%1], 16;" :: "r"(dst), "l"(src))
#define CP_COMMIT() asm volatile("cp.async.commit_group;" ::: "memory")
#define CP_WAIT1()  asm volatile("cp.async.wait_group 1;" ::: "memory")
#define CP_WAIT2()  asm volatile("cp.async.wait_group 2;" ::: "memory")

#define SW128(off) ((off) ^ (((off) >> 3) & 0x70))

#define LDMX4(r0, r1, r2, r3, addr) \
    asm volatile("ldmatrix.sync.aligned.m8n8.x4.shared.b16 {%0,%1,%2,%3}, [%4];" \
                 : "=r"(r0), "=r"(r1), "=r"(r2), "=r"(r3) : "r"(addr))

#define MMA16816(c, a, b) \
    asm volatile("mma.sync.aligned.m16n8k16.row.col.f32.bf16.bf16.f32 " \
                 "{%0,%1,%2,%3}, {%4,%5,%6,%7}, {%8,%9}, {%0,%1,%2,%3};" \
                 : "+f"((c)[0]), "+f"((c)[1]), "+f"((c)[2]), "+f"((c)[3]) \
                 : "r"((a)[0]), "r"((a)[1]), "r"((a)[2]), "r"((a)[3]), \
                   "r"((b)[0]), "r"((b)[1]))

__device__ __forceinline__ uint32_t bf2_hi(float a, float b) {
    __nv_bfloat162 p = __floats2bfloat162_rn(a, b);
    return reinterpret_cast<uint32_t&>(p);
}
__device__ __forceinline__ void split2(float a, float b, uint32_t &hi, uint32_t &lo) {
    __nv_bfloat16 ah = __float2bfloat16_rn(a);
    __nv_bfloat16 bh = __float2bfloat16_rn(b);
    __nv_bfloat162 h; h.x = ah; h.y = bh;
    __nv_bfloat162 l = __floats2bfloat162_rn(a - __bfloat162float(ah),
                                             b - __bfloat162float(bh));
    hi = reinterpret_cast<uint32_t&>(h);
    lo = reinterpret_cast<uint32_t&>(l);
}

// Fast exp on the FMA/ALU pipes (no MUFU). rel err ~2e-6 on |w| <~ 20.
__device__ __forceinline__ float fast_exp(float w) {
    const float L2E = 1.4426950408889634f;
    float t  = fmaf(w, L2E, 12582912.0f);
    int   n  = __float_as_int(t) - 0x4B400000;
    float nf = t - 12582912.0f;
    float f  = fmaf(w, L2E, -nf);
    float p  = fmaf(f, 0.0013333558f, 0.0096181291f);
    p = fmaf(f, p, 0.0555041087f);
    p = fmaf(f, p, 0.2402265069f);
    p = fmaf(f, p, 0.6931471806f);
    p = fmaf(f, p, 1.0f);
    return __int_as_float(__float_as_int(p) + (n << 23));
}

// =====================================================================
// K1: fused MLP: att = tanh(A @ W1 + b1) @ W2 + b2 -> bf16
// =====================================================================
__global__ __launch_bounds__(256)
void k_mlp(const float* __restrict__ A0, const float* __restrict__ W10,
           const float* __restrict__ b10, const float* __restrict__ W20,
           const float* __restrict__ b20, __nv_bfloat16* __restrict__ att0,
           const float* __restrict__ A1, const float* __restrict__ W11,
           const float* __restrict__ b11, const float* __restrict__ W21,
           const float* __restrict__ b21, __nv_bfloat16* __restrict__ att1) {
    __shared__ float As[32][132];
    __shared__ float Ws[32][32];
    __shared__ float W2s[32][33];
    __shared__ float Hs[128][36];
    const int tid  = threadIdx.x;
    const int which = (int)(blockIdx.x >> 6);
    const int row0 = (int)(blockIdx.x & 63) * 128;
    const float* A  = which ? A1  : A0;
    const float* W1 = which ? W11 : W10;
    const float* b1 = which ? b11 : b10;
    const float* W2 = which ? W21 : W20;
    const float* b2 = which ? b21 : b20;
    __nv_bfloat16* att = which ? att1 : att0;

    const int ty = tid / 8, tx = tid % 8;
    float acc[4][4] = {};

    #pragma unroll
    for (int p = 0; p < 4; p++) {
        int i = p * 256 + tid;
        W2s[i >> 5][i & 31] = W2[i];
    }

    for (int k0 = 0; k0 < DIN; k0 += 32) {
        #pragma unroll
        for (int p = 0; p < 4; p++) {
            int r  = p * 32 + tid / 8;
            int kq = (tid % 8) * 4;
            float4 v = *(const float4*)&A[(size_t)(row0 + r) * DIN + k0 + kq];
            As[kq + 0][r] = v.x; As[kq + 1][r] = v.y;
            As[kq + 2][r] = v.z; As[kq + 3][r] = v.w;
        }
        {
            int k = tid / 8, c4 = (tid % 8) * 4;
            *(float4*)&Ws[k][c4] = *(const float4*)&W1[(size_t)(k0 + k) * DH + c4];
        }
        __syncthreads();
        #pragma unroll
        for (int k = 0; k < 32; k++) {
            float4 a = *(const float4*)&As[k][ty * 4];
            float4 w = *(const float4*)&Ws[k][tx * 4];
            float av[4] = {a.x, a.y, a.z, a.w};
            float wv[4] = {w.x, w.y, w.z, w.w};
            #pragma unroll
            for (int r = 0; r < 4; r++)
                #pragma unroll
                for (int c = 0; c < 4; c++)
                    acc[r][c] += av[r] * wv[c];
        }
        __syncthreads();
    }
    #pragma unroll
    for (int r = 0; r < 4; r++)
        #pragma unroll
        for (int c = 0; c < 4; c++)
            Hs[ty * 4 + r][tx * 4 + c] = tanhf(acc[r][c] + b1[tx * 4 + c]);
    __syncthreads();

    {
        const int row = tid >> 1;
        const int cb  = (tid & 1) * 16;
        float s[16];
        #pragma unroll
        for (int j = 0; j < 16; j++) s[j] = b2[cb + j];
        #pragma unroll
        for (int k = 0; k < 32; k++) {
            float hv = Hs[row][k];
            #pragma unroll
            for (int j = 0; j < 16; j++) s[j] += hv * W2s[k][cb + j];
        }
        uint32_t ob[8];
        #pragma unroll
        for (int j2 = 0; j2 < 8; j2++) ob[j2] = bf2_hi(s[2 * j2], s[2 * j2 + 1]);
        uint4 u0 = {ob[0], ob[1], ob[2], ob[3]};
        uint4 u1 = {ob[4], ob[5], ob[6], ob[7]};
        *(uint4*)&att[(size_t)(row0 + row) * DH + cb]     = u0;
        *(uint4*)&att[(size_t)(row0 + row) * DH + cb + 8] = u1;
    }
}

// =====================================================================
// K2a: fc_x via split-bf16 HMMA (3-term: xh*wh + xh*wl + xl*wh).
// =====================================================================
#define FC_REG   10240
#define FC_STAGE (4 * FC_REG)
#define FC_SMEM  (2 * FC_STAGE)

__device__ __forceinline__ void fcx_ldg(const float* __restrict__ X,
                                        const float* __restrict__ W,
                                        int row0, int d0, int kc, int tid,
                                        float xv[8], float wv[8]) {
    const int r = tid >> 2, seg = tid & 3;
    const float* xs = &X[(size_t)(row0 + r) * DIN + kc * 32 + seg * 8];
    *(float4*)&xv[0] = *(const float4*)&xs[0];
    *(float4*)&xv[4] = *(const float4*)&xs[4];
    const int wd = tid & 127, wk = (tid >> 7) * 8;
    #pragma unroll
    for (int j = 0; j < 8; j++)
        wv[j] = W[(size_t)(kc * 32 + wk + j) * DOUT + d0 + wd];
}
__device__ __forceinline__ void fcx_sts(char* base, int tid,
                                        const float xv[8], const float wv[8]) {
    char* sAh = base;
    char* sAl = base + FC_REG;
    char* sBh = base + 2 * FC_REG;
    char* sBl = base + 3 * FC_REG;
    const int r = tid >> 2, seg = tid & 3;
    uint32_t h[4], lo[4];
    #pragma unroll
    for (int j = 0; j < 4; j++) split2(xv[2 * j], xv[2 * j + 1], h[j], lo[j]);
    *(uint4*)&sAh[r * 80 + seg * 16] = make_uint4(h[0], h[1], h[2], h[3]);
    *(uint4*)&sAl[r * 80 + seg * 16] = make_uint4(lo[0], lo[1], lo[2], lo[3]);
    const int wd = tid & 127, wk = (tid >> 7) * 8;
    #pragma unroll
    for (int j = 0; j < 4; j++) split2(wv[2 * j], wv[2 * j + 1], h[j], lo[j]);
    *(uint4*)&sBh[wd * 80 + wk * 2] = make_uint4(h[0], h[1], h[2], h[3]);
    *(uint4*)&sBl[wd * 80 + wk * 2] = make_uint4(lo[0], lo[1], lo[2], lo[3]);
}

__global__ __launch_bounds__(512)
void k_fcx_mma(const float* __restrict__ X, const float* __restrict__ W,
               const float* __restrict__ bias, float* __restrict__ outp) {
    extern __shared__ __align__(16) char fcsm[];
    const int tid = threadIdx.x, wid = tid >> 5, l = tid & 31;
    const int row0 = (int)(blockIdx.x >> 1) * 128;
    const int d0   = (int)(blockIdx.x & 1) * 128;
    const int wm = (wid >> 2) * 32, wn = (wid & 3) * 32;

    float acc[2][4][4];
    #pragma unroll
    for (int t = 0; t < 2; t++)
        #pragma unroll
        for (int u = 0; u < 4; u++)
            #pragma unroll
            for (int c = 0; c < 4; c++) acc[t][u][c] = 0.f;

    float xv[8], wv[8];
    fcx_ldg(X, W, row0, d0, 0, tid, xv, wv);
    fcx_sts(fcsm, tid, xv, wv);
    fcx_ldg(X, W, row0, d0, 1, tid, xv, wv);

    const int lm16 = l & 15, lhi = (l >> 4) * 16;
    const int bn = (l & 7) + ((l >> 4) << 3), bk16 = ((l >> 3) & 1) * 16;

    for (int i = 0; i < 16; i++) {
        __syncthreads();
        if (i + 1 < 16) fcx_sts(fcsm + ((i + 1) & 1) * FC_STAGE, tid, xv, wv);
        if (i + 2 < 16) fcx_ldg(X, W, row0, d0, i + 2, tid, xv, wv);
        __syncthreads();

        char* base = fcsm + (i & 1) * FC_STAGE;
        const uint32_t Ah = smem_u32(base);
        const uint32_t Al = Ah + FC_REG;
        const uint32_t Bh = Ah + 2 * FC_REG;
        const uint32_t Bl = Ah + 3 * FC_REG;
        #pragma unroll
        for (int kk = 0; kk < 2; kk++) {
            uint32_t ah[2][4], al[2][4];
            #pragma unroll
            for (int t = 0; t < 2; t++) {
                uint32_t off = (uint32_t)((wm + t * 16 + lm16) * 80 + kk * 32 + lhi);
                LDMX4(ah[t][0], ah[t][1], ah[t][2], ah[t][3], Ah + off);
                LDMX4(al[t][0], al[t][1], al[t][2], al[t][3], Al + off);
            }
            #pragma unroll
            for (int u2 = 0; u2 < 2; u2++) {
                uint32_t off = (uint32_t)((wn + u2 * 16 + bn) * 80 + kk * 32 + bk16);
                uint32_t h0, h1, h2, h3, l0, l1, l2, l3;
                LDMX4(h0, h1, h2, h3, Bh + off);
                LDMX4(l0, l1, l2, l3, Bl + off);
                uint32_t bh0[2] = {h0, h1}, bh1[2] = {h2, h3};
                uint32_t bl0[2] = {l0, l1}, bl1[2] = {l2, l3};
                #pragma unroll
                for (int t = 0; t < 2; t++) {
                    MMA16816(acc[t][2 * u2],     ah[t], bh0);
                    MMA16816(acc[t][2 * u2],     ah[t], bl0);
                    MMA16816(acc[t][2 * u2],     al[t], bh0);
                    MMA16816(acc[t][2 * u2 + 1], ah[t], bh1);
                    MMA16816(acc[t][2 * u2 + 1], ah[t], bl1);
                    MMA16816(acc[t][2 * u2 + 1], al[t], bh1);
                }
            }
        }
    }

    #pragma unroll
    for (int t = 0; t < 2; t++) {
        int ra = row0 + wm + t * 16 + (l >> 2);
        int rb = ra + 8;
        #pragma unroll
        for (int u = 0; u < 4; u++) {
            int col = d0 + wn + u * 8 + (l & 3) * 2;
            float b0v = bias[col], b1v = bias[col + 1];
            float2 v0 = {acc[t][u][0] + b0v, acc[t][u][1] + b1v};
            float2 v1 = {acc[t][u][2] + b0v, acc[t][u][3] + b1v};
            *(float2*)&outp[(size_t)ra * (2 * DOUT) + col] = v0;
            *(float2*)&outp[(size_t)rb * (2 * DOUT) + col] = v1;
        }
    }
}

// =====================================================================
// K2b: value GEMM on HMMA, transposed output into g_valueT[d][n] bf16.
// =====================================================================
__device__ __forceinline__ void gemm_ldg(const float* __restrict__ X,
                                         const float* __restrict__ W,
                                         int row0, int d0, int kc, int tid,
                                         float4 xv[4], float wv[16]) {
    #pragma unroll
    for (int p = 0; p < 4; p++)
        xv[p] = *(const float4*)&X[(size_t)(row0 + p * 32 + (tid >> 3)) * DIN
                                   + kc * 32 + (tid & 7) * 4];
    const int wd = tid & 127, wkh = tid >> 7;
    #pragma unroll
    for (int k2 = 0; k2 < 16; k2++)
        wv[k2] = W[(size_t)(kc * 32 + wkh * 16 + k2) * DOUT + d0 + wd];
}
__device__ __forceinline__ void gemm_sts(char* sA, char* sB, int tid,
                                         const float4 xv[4], const float wv[16]) {
    #pragma unroll
    for (int p = 0; p < 4; p++) {
        uint2 u;
        u.x = bf2_hi(xv[p].x, xv[p].y);
        u.y = bf2_hi(xv[p].z, xv[p].w);
        *(uint2*)&sA[(p * 32 + (tid >> 3)) * 80 + (tid & 7) * 8] = u;
    }
    const int wd = tid & 127, wkh = tid >> 7;
    #pragma unroll
    for (int j = 0; j < 8; j++)
        *(uint32_t*)&sB[wd * 80 + wkh * 32 + j * 4] = bf2_hi(wv[2 * j], wv[2 * j + 1]);
}

__global__ __launch_bounds__(256)
void k_value_mma(const float* __restrict__ X, const float* __restrict__ W,
                 const float* __restrict__ bias) {
    __shared__ __align__(16) char sA[2][128 * 80];
    __shared__ __align__(16) char sB[2][128 * 80];
    const int tid = threadIdx.x, wid = tid >> 5, l = tid & 31;
    const int row0 = (int)(blockIdx.x >> 1) * 128;
    const int d0   = (int)(blockIdx.x & 1) * 128;
    const int wm = (wid >> 1) * 32, wn = (wid & 1) * 64;

    float acc[2][8][4];
    #pragma unroll
    for (int t = 0; t < 2; t++)
        #pragma unroll
        for (int u = 0; u < 8; u++)
            #pragma unroll
            for (int c = 0; c < 4; c++) acc[t][u][c] = 0.f;

    float4 xv[4]; float wv[16];
    gemm_ldg(X, W, row0, d0, 0, tid, xv, wv);
    gemm_sts(sA[0], sB[0], tid, xv, wv);
    gemm_ldg(X, W, row0, d0, 1, tid, xv, wv);

    const int lm16 = l & 15, lhi = (l >> 4) * 16;
    const int bn = (l & 7) + ((l >> 4) << 3), bk16 = ((l >> 3) & 1) * 16;

    for (int i = 0; i < 16; i++) {
        __syncthreads();
        if (i + 1 < 16) gemm_sts(sA[(i + 1) & 1], sB[(i + 1) & 1], tid, xv, wv);
        if (i + 2 < 16) gemm_ldg(X, W, row0, d0, i + 2, tid, xv, wv);

        const int b = i & 1;
        const uint32_t Ab = smem_u32(sB[b]);   // transposed: A = W tile
        const uint32_t Bb = smem_u32(sA[b]);
        #pragma unroll
        for (int kk = 0; kk < 2; kk++) {
            uint32_t a[2][4];
            #pragma unroll
            for (int t = 0; t < 2; t++) {
                uint32_t off = (uint32_t)((wm + t * 16 + lm16) * 80 + kk * 32 + lhi);
                LDMX4(a[t][0], a[t][1], a[t][2], a[t][3], Ab + off);
            }
            #pragma unroll
            for (int u2 = 0; u2 < 4; u2++) {
                uint32_t off = (uint32_t)((wn + u2 * 16 + bn) * 80 + kk * 32 + bk16);
                uint32_t r0_, r1_, r2_, r3_;
                LDMX4(r0_, r1_, r2_, r3_, Bb + off);
                uint32_t b0[2] = {r0_, r1_}, b1[2] = {r2_, r3_};
                #pragma unroll
                for (int t = 0; t < 2; t++) {
                    MMA16816(acc[t][2 * u2],     a[t], b0);
                    MMA16816(acc[t][2 * u2 + 1], a[t], b1);
                }
            }
        }
    }

    #pragma unroll
    for (int t = 0; t < 2; t++) {
        int dr = d0 + wm + t * 16 + (l >> 2);
        float bA = bias[dr], bB = bias[dr + 8];
        #pragma unroll
        for (int u = 0; u < 8; u++) {
            int nc = row0 + wn + u * 8 + (l & 3) * 2;
            uint32_t pA = bf2_hi(acc[t][u][0] + bA, acc[t][u][1] + bA);
            uint32_t pB = bf2_hi(acc[t][u][2] + bB, acc[t][u][3] + bB);
            *(uint32_t*)&g_valueT[(size_t)dr * NN + nc]       = pA;
            *(uint32_t*)&g_valueT[(size_t)(dr + 8) * NN + nc] = pB;
        }
    }
}

// =====================================================================
// K3: HMMA score kernel — column-split x4; E stores staged through a
// XOR-swizzled SMEM tile (conflict-free STS) then coalesced STG.128.
// =====================================================================
__device__ __forceinline__ void score_loadn(uint32_t nbase, int tid, int c, int buf) {
    #pragma unroll
    for (int q = 0; q < 2; q++) {
        int u  = tid * 2 + q;
        int rr = u >> 2, seg = u & 3;
        uint32_t dst = nbase + (uint32_t)buf * 10240u + (uint32_t)(rr * 80 + seg * 16);
        const char* src = (const char*)g_nattb + ((size_t)c * 128 + rr) * 64 + seg * 16;
        CP16(dst, src);
    }
}

__global__ __launch_bounds__(256, 4)
void k_score_mma(const int* __restrict__ adj) {
    __shared__ __align__(16) char sN[3 * 128 * 80];
    __shared__ __align__(16) uint32_t sEw[2][2048];   // 2 x 32 rows x 64 words
    __shared__ float s_rsum[4][32];
    const int tid = threadIdx.x, wid = tid >> 5, l = tid & 31;
    const int row0 = (int)(blockIdx.x >> 2) * 32;
    const int sp   = (int)(blockIdx.x & 3);
    const int c0   = sp * 16;
    const int wm = (wid >> 2) * 16;
    const int h  = wid & 3;
    const int wn = h * 32;
    const uint32_t nb = smem_u32(sN);

    uint32_t a[2][4];
    {
        const int r  = row0 + wm + (l >> 2);
        const int kq = (l & 3) * 2;
        const uint32_t* X = (const uint32_t*)g_xattb;
        #pragma unroll
        for (int kk = 0; kk < 2; kk++) {
            a[kk][0] = X[(size_t)r * 16       + (kk * 16 + kq) / 2];
            a[kk][1] = X[(size_t)(r + 8) * 16 + (kk * 16 + kq) / 2];
            a[kk][2] = X[(size_t)r * 16       + (kk * 16 + kq + 8) / 2];
            a[kk][3] = X[(size_t)(r + 8) * 16 + (kk * 16 + kq + 8) / 2];
        }
    }

    float rs0 = 0.f, rs1 = 0.f;
    const int bn = (l & 7) + ((l >> 4) << 3), bk16 = ((l >> 3) & 1) * 16;
    const int r0g = row0 + wm + (l >> 2);
    const int rlo = wm + (l >> 2);           // local row 0..31
    const int swz = ((l >> 2) & 7) << 2;     // (row&7)<<2, same for rlo/rlo+8

    score_loadn(nb, tid, c0 + 0, 0); CP_COMMIT();
    score_loadn(nb, tid, c0 + 1, 1); CP_COMMIT();

    for (int i = 0; i < 16; i++) {
        CP_WAIT1();
        __syncthreads();                               // barrier A
        if (i + 2 < 16) score_loadn(nb, tid, c0 + i + 2, (i + 2) % 3);
        CP_COMMIT();

        int2 adv[4][2];
        #pragma unroll
        for (int u = 0; u < 4; u++) {
            int cb = (c0 + i) * 128 + wn + u * 8 + (l & 3) * 2;
            adv[u][0] = *(const int2*)&adj[(size_t)r0g * NN + cb];
            adv[u][1] = *(const int2*)&adj[(size_t)(r0g + 8) * NN + cb];
        }

        float acc[4][4];
        #pragma unroll
        for (int u = 0; u < 4; u++)
            #pragma unroll
            for (int c = 0; c < 4; c++) acc[u][c] = 0.f;

        const uint32_t buf = nb + (uint32_t)(i % 3) * 10240u;
        #pragma unroll
        for (int kk = 0; kk < 2; kk++) {
            #pragma unroll
            for (int u2 = 0; u2 < 2; u2++) {
                uint32_t off = (uint32_t)((wn + u2 * 16 + bn) * 80 + kk * 32 + bk16);
                uint32_t r0_, r1_, r2_, r3_;
                LDMX4(r0_, r1_, r2_, r3_, buf + off);
                uint32_t b0[2] = {r0_, r1_}, b1[2] = {r2_, r3_};
                MMA16816(acc[2 * u2],     a[kk], b0);
                MMA16816(acc[2 * u2 + 1], a[kk], b1);
            }
        }

        #pragma unroll
        for (int u = 0; u < 4; u++) {
            const int colw = (wn >> 1) + u * 4 + (l & 3);  // word index within row
            {
                float s0 = acc[u][0], s1 = acc[u][1];
                float w0 = s0 > 0.f ? s0 : 0.01f * s0;
                float w1 = s1 > 0.f ? s1 : 0.01f * s1;
                float e0 = adv[u][0].x > 0 ? fast_exp(w0) : 0.f;
                float e1 = adv[u][0].y > 0 ? fast_exp(w1) : 0.f;
                rs0 += e0 + e1;
                sEw[i & 1][rlo * 64 + (colw ^ swz)] = bf2_hi(e0, e1);
            }
            {
                float s0 = acc[u][2], s1 = acc[u][3];
                float w0 = s0 > 0.f ? s0 : 0.01f * s0;
                float w1 = s1 > 0.f ? s1 : 0.01f * s1;
                float e0 = adv[u][1].x > 0 ? fast_exp(w0) : 0.f;
                float e1 = adv[u][1].y > 0 ? fast_exp(w1) : 0.f;
                rs1 += e0 + e1;
                sEw[i & 1][(rlo + 8) * 64 + (colw ^ swz)] = bf2_hi(e0, e1);
            }
        }
        __syncthreads();                               // barrier B: STS done

        // coalesced copy: 32 rows x 128B
        {
            const int row = tid >> 3;
            const int jb  = tid & 7;
            const int rsw = (row & 7) << 2;
            size_t gbase = (size_t)(row0 + row) * NN + (size_t)(c0 + i) * 128;
            #pragma unroll
            for (int hh = 0; hh < 2; hh++) {
                int blk = jb + hh * 8;
                int pos = (blk * 4) ^ rsw;
                uint4 v = *(uint4*)&sEw[i & 1][row * 64 + pos];
                *(uint4*)&g_E[gbase + blk * 8] = v;
            }
        }
    }

    rs0 += __shfl_xor_sync(0xffffffff, rs0, 1);
    rs0 += __shfl_xor_sync(0xffffffff, rs0, 2);
    rs1 += __shfl_xor_sync(0xffffffff, rs1, 1);
    rs1 += __shfl_xor_sync(0xffffffff, rs1, 2);
    if ((l & 3) == 0) {
        s_rsum[h][wm + (l >> 2)]     = rs0;
        s_rsum[h][wm + (l >> 2) + 8] = rs1;
    }
    __syncthreads();
    if (tid < 32)
        g_rowsum4[sp * NX + row0 + tid] =
            (s_rsum[0][tid] + s_rsum[1][tid]) + (s_rsum[2][tid] + s_rsum[3][tid]);
}

// =====================================================================
// K4: HMMA PV GEMM — K-split x2. CTA: 128 rows x 256 dout x half-K.
// 512 threads, warps 4m x 4n, warp tile 32x64. Partials -> g_pvpart.
// =====================================================================
#define PV_BK     64
#define PV_NCHS   64                 // chunks per CTA (half of K)
#define PV_STAGEB 49152              // 16KB E + 32KB V
#define PV_SMEM   (4 * PV_STAGEB + 1024)

__device__ __forceinline__ void pv_load(uint32_t tile, int tid, int row0, int gc, int c) {
    const size_t kb = (size_t)gc * (PV_BK * 2);
    const uint32_t eb = tile + (uint32_t)(c & 3) * PV_STAGEB;
    const uint32_t vb = eb + 16384u;
    #pragma unroll
    for (int p = 0; p < 2; p++) {
        int u = p * 512 + tid;               // 0..1023 -> E: 128 rows x 8 segs
        int row = u >> 3, j = u & 7;
        CP16(eb + SW128((uint32_t)(row * 128 + j * 16)),
             (const char*)g_E + ((size_t)(row0 + row) * NN) * 2 + kb + (size_t)(j * 16));
    }
    #pragma unroll
    for (int p = 0; p < 4; p++) {
        int u = p * 512 + tid;               // 0..2047 -> V: 256 d-rows x 8 segs
        int row = u >> 3, j = u & 7;
        CP16(vb + SW128((uint32_t)(row * 128 + j * 16)),
             (const char*)g_valueT + ((size_t)row * NN) * 2 + kb + (size_t)(j * 16));
    }
}

__global__ __launch_bounds__(512, 1)
void k_pv_mma() {
    extern __shared__ __align__(16) char dynsmem[];
    const int tid = threadIdx.x;
    const int wid = tid >> 5;
    const int l   = tid & 31;
    const int row0 = (int)(blockIdx.x >> 1) * 128;
    const int ks   = (int)(blockIdx.x & 1);
    const int wm0  = (wid >> 2) * 32;
    const int wn0  = (wid & 3) * 64;

    const uint32_t dynb = smem_u32(dynsmem);
    const uint32_t tile = (dynb + 1023u) & ~1023u;

    float acc[2][8][4];
    #pragma unroll
    for (int t = 0; t < 2; t++)
        #pragma unroll
        for (int u = 0; u < 8; u++)
            #pragma unroll
            for (int c = 0; c < 4; c++) acc[t][u][c] = 0.f;

    const int gc0 = ks * PV_NCHS;
    pv_load(tile, tid, row0, gc0 + 0, 0); CP_COMMIT();
    pv_load(tile, tid, row0, gc0 + 1, 1); CP_COMMIT();
    pv_load(tile, tid, row0, gc0 + 2, 2); CP_COMMIT();

    const int lm16 = l & 15;
    const int lhi  = (l >> 4) * 16;
    const int bn   = (l & 7) + ((l >> 4) << 3);
    const int bk16 = ((l >> 3) & 1) * 16;

    for (int i = 0; i < PV_NCHS; i++) {
        CP_WAIT2();
        __syncthreads();
        const uint32_t eb = tile + (uint32_t)(i & 3) * PV_STAGEB;
        const uint32_t vb = eb + 16384u;
        #pragma unroll
        for (int kk = 0; kk < 4; kk++) {
            uint32_t a[2][4];
            #pragma unroll
            for (int t = 0; t < 2; t++) {
                uint32_t off = (uint32_t)((wm0 + t * 16 + lm16) * 128 + kk * 32 + lhi);
                LDMX4(a[t][0], a[t][1], a[t][2], a[t][3], eb + SW128(off));
            }
            #pragma unroll
            for (int u2 = 0; u2 < 4; u2++) {
                uint32_t off = (uint32_t)((wn0 + u2 * 16 + bn) * 128 + kk * 32 + bk16);
                uint32_t r0, r1, r2, r3;
                LDMX4(r0, r1, r2, r3, vb + SW128(off));
                uint32_t b0[2] = {r0, r1}, b1[2] = {r2, r3};
                #pragma unroll
                for (int t = 0; t < 2; t++) {
                    MMA16816(acc[t][2 * u2],     a[t], b0);
                    MMA16816(acc[t][2 * u2 + 1], a[t], b1);
                }
            }
        }
        const int j = i + 3;
        if (j < PV_NCHS) pv_load(tile, tid, row0, gc0 + j, j);
        CP_COMMIT();
    }

    float* part = &g_pvpart[(size_t)ks * NX * DOUT];
    #pragma unroll
    for (int t = 0; t < 2; t++) {
        int ra = row0 + wm0 + t * 16 + (l >> 2);
        int rb = ra + 8;
        #pragma unroll
        for (int u = 0; u < 8; u++) {
            int col = wn0 + u * 8 + (l & 3) * 2;
            float2 v0 = {acc[t][u][0], acc[t][u][1]};
            float2 v1 = {acc[t][u][2], acc[t][u][3]};
            *(float2*)&part[(size_t)ra * DOUT + col] = v0;
            *(float2*)&part[(size_t)rb * DOUT + col] = v1;
        }
    }
}

// =====================================================================
// K5: combine PV partials + softmax normalization -> out[:, 256:512]
// =====================================================================
__global__ __launch_bounds__(256)
void k_combine(float* __restrict__ out) {
    int idx = (int)blockIdx.x * 256 + (int)threadIdx.x;   // 0 .. NX*64-1
    int row = idx >> 6;
    int c4  = (idx & 63) << 2;
    float rs = (g_rowsum4[row] + g_rowsum4[NX + row]) +
               (g_rowsum4[2 * NX + row] + g_rowsum4[3 * NX + row]);
    float inv = 1.0f / rs;
    float4 a = *(float4*)&g_pvpart[(size_t)row * DOUT + c4];
    float4 b = *(float4*)&g_pvpart[(size_t)NX * DOUT + (size_t)row * DOUT + c4];
    float4 r = {(a.x + b.x) * inv, (a.y + b.y) * inv,
                (a.z + b.z) * inv, (a.w + b.w) * inv};
    *(float4*)&out[(size_t)row * (2 * DOUT) + DOUT + c4] = r;
}

// =====================================================================
// launch
// =====================================================================
extern "C" void kernel_launch(void* const* d_in, const int* in_sizes, int n_in,
                              void* d_out, int out_size) {
    const float* x    = (const float*)d_in[0];
    const float* neigh= (const float*)d_in[1];
    const int*   adj  = (const int*)  d_in[2];
    const float* Wx1  = (const float*)d_in[3];
    const float* bx1  = (const float*)d_in[4];
    const float* Wx2  = (const float*)d_in[5];
    const float* bx2  = (const float*)d_in[6];
    const float* Wn1  = (const float*)d_in[7];
    const float* bn1  = (const float*)d_in[8];
    const float* Wn2  = (const float*)d_in[9];
    const float* bn2  = (const float*)d_in[10];
    const float* Wv   = (const float*)d_in[11];
    const float* bv   = (const float*)d_in[12];
    const float* Wfx  = (const float*)d_in[13];
    const float* bfx  = (const float*)d_in[14];
    float* out = (float*)d_out;

    __nv_bfloat16* xattb;
    __nv_bfloat16* nattb;
    cudaGetSymbolAddress((void**)&xattb, g_xattb);
    cudaGetSymbolAddress((void**)&nattb, g_nattb);

    cudaFuncSetAttribute(k_pv_mma, cudaFuncAttributeMaxDynamicSharedMemorySize, PV_SMEM);
    cudaFuncSetAttribute(k_fcx_mma, cudaFuncAttributeMaxDynamicSharedMemorySize, FC_SMEM);

    // fused attention MLPs (both branches in one grid) -> bf16 att
    k_mlp<<<2 * (NX / 128), 256>>>(neigh, Wn1, bn1, Wn2, bn2, nattb,
                                   x, Wx1, bx1, Wx2, bx2, xattb);
    // value (HMMA, transposed -> g_valueT); fc_x split-bf16 HMMA
    k_value_mma<<<128, 256>>>(neigh, Wv, bv);
    k_fcx_mma<<<128, 512, FC_SMEM>>>(x, Wfx, bfx, out);
    // HMMA scores + masked fast_exp + partial rowsums (column-split x4)
    k_score_mma<<<(NX / 32) * NSPLIT, 256>>>(adj);
    // HMMA PV (K-split x2) -> partials
    k_pv_mma<<<(NX / 128) * 2, 512, PV_SMEM>>>();
    // combine partials + softmax normalization
    k_combine<<<NX * (DOUT / 4) / 256, 256>>>(out);
}